// round 4
// baseline (speedup 1.0000x reference)
#include <cuda_runtime.h>

// ---------------------------------------------------------------------------
// MultiHeadSelfAttention: B=2, S=2048, D=2048, H=16, Hd=128, fp32
//   Q = x Wq^T, K = x Wk^T, V = x Wv^T        (GEMM-NT, both K-major)
//   ctx = softmax(Q K^T / sqrt(Hd)) V         (flash-attention, fp32)
//   out = ctx Wo^T                            (GEMM-NT)
// ---------------------------------------------------------------------------

#define S_LEN   2048
#define D_MODEL 2048
#define BATCH   2
#define NHEADS  16
#define HDIM    128
#define MROWS   (BATCH * S_LEN)   // 4096

// Scratch (static __device__ globals: allocation-free per harness rules)
__device__ float g_Q[(size_t)MROWS * D_MODEL];
__device__ float g_K[(size_t)MROWS * D_MODEL];
__device__ float g_V[(size_t)MROWS * D_MODEL];
__device__ float g_ctx[(size_t)MROWS * D_MODEL];

// ---------------------------------------------------------------------------
// GEMM-NT: C[M,N] = A[M,K] * W[N,K]^T, M=4096, N=2048, K=2048 (all fp32)
// Block tile 128x128, BK=16, 256 threads, 8x8 register tile per thread.
// Global loads are prefetched into registers before the sync so the load
// latency overlaps the previous tile's compute.
// ---------------------------------------------------------------------------
__global__ __launch_bounds__(256) void gemm_nt_kernel(
    const float* __restrict__ A, const float* __restrict__ W, float* __restrict__ C)
{
    __shared__ __align__(16) float As[16][132];  // [k][m], padded
    __shared__ __align__(16) float Bs[16][132];  // [k][n], padded

    const int tid  = threadIdx.x;
    const int tx   = tid & 15;
    const int ty   = tid >> 4;
    const int row0 = blockIdx.y * 128;
    const int col0 = blockIdx.x * 128;
    const int lr   = tid >> 2;        // 0..63 (handles lr and lr+64)
    const int lc4  = (tid & 3) * 4;   // k-offset within the 16-wide tile

    float acc[8][8];
#pragma unroll
    for (int i = 0; i < 8; i++)
#pragma unroll
        for (int j = 0; j < 8; j++) acc[i][j] = 0.f;

    for (int kt = 0; kt < D_MODEL; kt += 16) {
        // prefetch (global) before the barrier
        float4 a0 = *(const float4*)(A + (size_t)(row0 + lr)      * D_MODEL + kt + lc4);
        float4 a1 = *(const float4*)(A + (size_t)(row0 + lr + 64) * D_MODEL + kt + lc4);
        float4 b0 = *(const float4*)(W + (size_t)(col0 + lr)      * D_MODEL + kt + lc4);
        float4 b1 = *(const float4*)(W + (size_t)(col0 + lr + 64) * D_MODEL + kt + lc4);
        __syncthreads();   // previous tile's compute done before overwrite
        As[lc4 + 0][lr]      = a0.x; As[lc4 + 1][lr]      = a0.y;
        As[lc4 + 2][lr]      = a0.z; As[lc4 + 3][lr]      = a0.w;
        As[lc4 + 0][lr + 64] = a1.x; As[lc4 + 1][lr + 64] = a1.y;
        As[lc4 + 2][lr + 64] = a1.z; As[lc4 + 3][lr + 64] = a1.w;
        Bs[lc4 + 0][lr]      = b0.x; Bs[lc4 + 1][lr]      = b0.y;
        Bs[lc4 + 2][lr]      = b0.z; Bs[lc4 + 3][lr]      = b0.w;
        Bs[lc4 + 0][lr + 64] = b1.x; Bs[lc4 + 1][lr + 64] = b1.y;
        Bs[lc4 + 2][lr + 64] = b1.z; Bs[lc4 + 3][lr + 64] = b1.w;
        __syncthreads();

#pragma unroll
        for (int k = 0; k < 16; k++) {
            float4 av0 = *(const float4*)&As[k][ty * 8];
            float4 av1 = *(const float4*)&As[k][ty * 8 + 4];
            float4 bv0 = *(const float4*)&Bs[k][tx * 8];
            float4 bv1 = *(const float4*)&Bs[k][tx * 8 + 4];
            float a[8] = {av0.x, av0.y, av0.z, av0.w, av1.x, av1.y, av1.z, av1.w};
            float b[8] = {bv0.x, bv0.y, bv0.z, bv0.w, bv1.x, bv1.y, bv1.z, bv1.w};
#pragma unroll
            for (int i = 0; i < 8; i++)
#pragma unroll
                for (int j = 0; j < 8; j++)
                    acc[i][j] = fmaf(a[i], b[j], acc[i][j]);
        }
    }

#pragma unroll
    for (int i = 0; i < 8; i++) {
        float* cp = C + (size_t)(row0 + ty * 8 + i) * D_MODEL + col0 + tx * 8;
        *(float4*)cp       = make_float4(acc[i][0], acc[i][1], acc[i][2], acc[i][3]);
        *(float4*)(cp + 4) = make_float4(acc[i][4], acc[i][5], acc[i][6], acc[i][7]);
    }
}

// ---------------------------------------------------------------------------
// Flash attention (fp32): per (b, h, q-block of 64 rows), stream K/V in
// 64-row tiles through shared memory with online softmax.
// Threads: 256 as 16x16. Scores tile 64x64 -> 4x4/thread.
// Output tile 64x128 -> 4x8/thread.
// ---------------------------------------------------------------------------
#define BQ     64
#define BKV    64
#define QS_STR 68                                   // 64 + 4 pad
#define ATTN_SMEM_FLOATS (128 * QS_STR * 2 + BKV * HDIM + BKV * QS_STR)

__global__ __launch_bounds__(256) void attn_kernel()
{
    extern __shared__ __align__(16) float sm[];
    float* Qs = sm;                       // [128][68]  (d-major, transposed)
    float* Ks = Qs + 128 * QS_STR;        // [128][68]  (d-major, transposed)
    float* Vs = Ks + 128 * QS_STR;        // [64][128]  (natural)
    float* Ps = Vs + BKV * HDIM;          // [64][68]   (kv-major, transposed)

    const int tid = threadIdx.x;
    const int tx  = tid & 15;
    const int ty  = tid >> 4;
    const int b   = blockIdx.z;
    const int h   = blockIdx.y;
    const int q0  = blockIdx.x * BQ;
    const float scale = 0.0883883476483184f;   // 1/sqrt(128)

    const float* Qg = g_Q + (size_t)(b * S_LEN + q0) * D_MODEL + h * HDIM;
    const float* Kg = g_K + (size_t)(b * S_LEN) * D_MODEL + h * HDIM;
    const float* Vg = g_V + (size_t)(b * S_LEN) * D_MODEL + h * HDIM;

    // Load Q tile transposed, pre-scaled (so scores come out scaled)
#pragma unroll
    for (int i = 0; i < 8; i++) {
        int idx = tid + i * 256;          // 0..2047
        int r = idx >> 5;                 // 0..63
        int c = (idx & 31) * 4;           // 0..124
        float4 v = *(const float4*)(Qg + (size_t)r * D_MODEL + c);
        Qs[(c + 0) * QS_STR + r] = v.x * scale;
        Qs[(c + 1) * QS_STR + r] = v.y * scale;
        Qs[(c + 2) * QS_STR + r] = v.z * scale;
        Qs[(c + 3) * QS_STR + r] = v.w * scale;
    }

    float m_i[4], l_i[4], acc[4][8];
#pragma unroll
    for (int i = 0; i < 4; i++) {
        m_i[i] = -1e30f;
        l_i[i] = 0.f;
#pragma unroll
        for (int j = 0; j < 8; j++) acc[i][j] = 0.f;
    }

    for (int t = 0; t < S_LEN / BKV; t++) {
        const float* Kt = Kg + (size_t)(t * BKV) * D_MODEL;
        const float* Vt = Vg + (size_t)(t * BKV) * D_MODEL;

        __syncthreads();   // previous iter's Ps/Vs reads done (also covers Qs on t=0)
#pragma unroll
        for (int i = 0; i < 8; i++) {
            int idx = tid + i * 256;
            int r = idx >> 5;
            int c = (idx & 31) * 4;
            float4 kv = *(const float4*)(Kt + (size_t)r * D_MODEL + c);
            Ks[(c + 0) * QS_STR + r] = kv.x;
            Ks[(c + 1) * QS_STR + r] = kv.y;
            Ks[(c + 2) * QS_STR + r] = kv.z;
            Ks[(c + 3) * QS_STR + r] = kv.w;
            float4 vv = *(const float4*)(Vt + (size_t)r * D_MODEL + c);
            *(float4*)(Vs + r * HDIM + c) = vv;
        }
        __syncthreads();

        // S = (Q * scale) K^T : 4x4 per thread
        float s[4][4];
#pragma unroll
        for (int i = 0; i < 4; i++)
#pragma unroll
            for (int j = 0; j < 4; j++) s[i][j] = 0.f;

#pragma unroll 8
        for (int d = 0; d < HDIM; d++) {
            float4 qv = *(const float4*)(Qs + d * QS_STR + ty * 4);
            float4 kv = *(const float4*)(Ks + d * QS_STR + tx * 4);
            float qa[4] = {qv.x, qv.y, qv.z, qv.w};
            float kb[4] = {kv.x, kv.y, kv.z, kv.w};
#pragma unroll
            for (int i = 0; i < 4; i++)
#pragma unroll
                for (int j = 0; j < 4; j++)
                    s[i][j] = fmaf(qa[i], kb[j], s[i][j]);
        }

        // online softmax (row = ty*4+i; 16 tx-lanes share a row, contiguous in warp)
#pragma unroll
        for (int i = 0; i < 4; i++) {
            float mx = fmaxf(fmaxf(s[i][0], s[i][1]), fmaxf(s[i][2], s[i][3]));
            mx = fmaxf(mx, __shfl_xor_sync(0xffffffffu, mx, 1));
            mx = fmaxf(mx, __shfl_xor_sync(0xffffffffu, mx, 2));
            mx = fmaxf(mx, __shfl_xor_sync(0xffffffffu, mx, 4));
            mx = fmaxf(mx, __shfl_xor_sync(0xffffffffu, mx, 8));
            float mnew  = fmaxf(m_i[i], mx);
            float alpha = __expf(m_i[i] - mnew);
            m_i[i] = mnew;
            float rs = 0.f;
#pragma unroll
            for (int j = 0; j < 4; j++) {
                float p = __expf(s[i][j] - mnew);
                s[i][j] = p;
                rs += p;
            }
            rs += __shfl_xor_sync(0xffffffffu, rs, 1);
            rs += __shfl_xor_sync(0xffffffffu, rs, 2);
            rs += __shfl_xor_sync(0xffffffffu, rs, 4);
            rs += __shfl_xor_sync(0xffffffffu, rs, 8);
            l_i[i] = l_i[i] * alpha + rs;
#pragma unroll
            for (int j = 0; j < 8; j++) acc[i][j] *= alpha;
        }

        // stage P transposed: Ps[kv][row]
#pragma unroll
        for (int j = 0; j < 4; j++) {
            *(float4*)(Ps + (tx * 4 + j) * QS_STR + ty * 4) =
                make_float4(s[0][j], s[1][j], s[2][j], s[3][j]);
        }
        __syncthreads();

        // acc += P V : 4x8 per thread
#pragma unroll 4
        for (int kk = 0; kk < BKV; kk++) {
            float4 pa = *(const float4*)(Ps + kk * QS_STR + ty * 4);
            float4 v0 = *(const float4*)(Vs + kk * HDIM + tx * 8);
            float4 v1 = *(const float4*)(Vs + kk * HDIM + tx * 8 + 4);
            float aa[4] = {pa.x, pa.y, pa.z, pa.w};
            float bb[8] = {v0.x, v0.y, v0.z, v0.w, v1.x, v1.y, v1.z, v1.w};
#pragma unroll
            for (int i = 0; i < 4; i++)
#pragma unroll
                for (int j = 0; j < 8; j++)
                    acc[i][j] = fmaf(aa[i], bb[j], acc[i][j]);
        }
    }

    float* Cg = g_ctx + (size_t)(b * S_LEN + q0) * D_MODEL + h * HDIM;
#pragma unroll
    for (int i = 0; i < 4; i++) {
        float inv = 1.0f / l_i[i];
        float* cp = Cg + (size_t)(ty * 4 + i) * D_MODEL + tx * 8;
        *(float4*)cp = make_float4(acc[i][0] * inv, acc[i][1] * inv,
                                   acc[i][2] * inv, acc[i][3] * inv);
        *(float4*)(cp + 4) = make_float4(acc[i][4] * inv, acc[i][5] * inv,
                                         acc[i][6] * inv, acc[i][7] * inv);
    }
}

// ---------------------------------------------------------------------------
extern "C" void kernel_launch(void* const* d_in, const int* in_sizes, int n_in,
                              void* d_out, int out_size)
{
    const float* x  = (const float*)d_in[0];
    const float* Wq = (const float*)d_in[1];
    const float* Wk = (const float*)d_in[2];
    const float* Wv = (const float*)d_in[3];
    const float* Wo = (const float*)d_in[4];
    float* out = (float*)d_out;

    float *Q, *K, *V, *ctx;
    cudaGetSymbolAddress((void**)&Q,   g_Q);
    cudaGetSymbolAddress((void**)&K,   g_K);
    cudaGetSymbolAddress((void**)&V,   g_V);
    cudaGetSymbolAddress((void**)&ctx, g_ctx);

    cudaFuncSetAttribute(attn_kernel, cudaFuncAttributeMaxDynamicSharedMemorySize,
                         ATTN_SMEM_FLOATS * (int)sizeof(float));

    dim3 ggrid(D_MODEL / 128, MROWS / 128);   // (16, 32)
    gemm_nt_kernel<<<ggrid, 256>>>(x, Wq, Q);
    gemm_nt_kernel<<<ggrid, 256>>>(x, Wk, K);
    gemm_nt_kernel<<<ggrid, 256>>>(x, Wv, V);
    attn_kernel<<<dim3(S_LEN / BQ, NHEADS, BATCH), 256,
                  ATTN_SMEM_FLOATS * (int)sizeof(float)>>>();
    gemm_nt_kernel<<<ggrid, 256>>>(ctx, Wo, out);
}

// round 9
// speedup vs baseline: 1.4969x; 1.4969x over previous
#include <cuda_runtime.h>
#include <cuda_bf16.h>
#include <cstdint>

// ---------------------------------------------------------------------------
// MultiHeadSelfAttention  B=2, S=2048, D=2048, H=16, Hd=128, fp32 in/out
//   Projections + output GEMM: mma.sync HMMA bf16 "x3" (hi/lo split)
//     (tcgen05 is unavailable: harness compiles at virtual arch compute_103,
//      family-generic -- sm_103a-only PTX is rejected by ptxas)
//   Attention: fp32 SIMT flash attention (known-correct from R4)
// ---------------------------------------------------------------------------

#define S_LEN   2048
#define D_MODEL 2048
#define BATCH   2
#define NHEADS  16
#define HDIM    128
#define MROWS   (BATCH * S_LEN)   // 4096

// ------------------------- scratch (static, allocation-free) ---------------
__device__ float g_Q  [(size_t)MROWS * D_MODEL];
__device__ float g_K  [(size_t)MROWS * D_MODEL];
__device__ float g_V  [(size_t)MROWS * D_MODEL];
__device__ float g_ctx[(size_t)MROWS * D_MODEL];
__device__ __nv_bfloat16 g_xh[(size_t)MROWS * D_MODEL];
__device__ __nv_bfloat16 g_xl[(size_t)MROWS * D_MODEL];
__device__ __nv_bfloat16 g_wh[(size_t)D_MODEL * D_MODEL];
__device__ __nv_bfloat16 g_wl[(size_t)D_MODEL * D_MODEL];

// ------------------------- helpers -----------------------------------------
__device__ __forceinline__ uint32_t smem_u32(const void* p) {
    uint32_t a;
    asm("{ .reg .u64 t; cvta.to.shared.u64 t, %1; cvt.u32.u64 %0, t; }"
        : "=r"(a) : "l"(p));
    return a;
}
#define SMEM_SWIZZLE_128B(off) ((off) ^ (((off) >> 3) & 0x70))

__device__ __forceinline__ void ldsm4(uint32_t* r, uint32_t addr) {
    asm volatile("ldmatrix.sync.aligned.m8n8.x4.shared.b16 {%0,%1,%2,%3}, [%4];"
                 : "=r"(r[0]), "=r"(r[1]), "=r"(r[2]), "=r"(r[3]) : "r"(addr));
}
__device__ __forceinline__ void mma16816(float* d, const uint32_t* a, const uint32_t* b) {
    asm volatile(
        "mma.sync.aligned.m16n8k16.row.col.f32.bf16.bf16.f32 "
        "{%0,%1,%2,%3}, {%4,%5,%6,%7}, {%8,%9}, {%0,%1,%2,%3};"
        : "+f"(d[0]), "+f"(d[1]), "+f"(d[2]), "+f"(d[3])
        : "r"(a[0]), "r"(a[1]), "r"(a[2]), "r"(a[3]), "r"(b[0]), "r"(b[1]));
}
__device__ __forceinline__ void cp_async16(uint32_t sdst, const void* gsrc) {
    asm volatile("cp.async.cg.shared.global [%0], [%1], 16;" :: "r"(sdst), "l"(gsrc));
}

// ---------------------------------------------------------------------------
// fp32 -> (bf16 hi, bf16 lo) split.  lo = bf16(x - float(hi)); subtraction exact.
// ---------------------------------------------------------------------------
__global__ __launch_bounds__(256) void cvt_hilo_kernel(
    const float* __restrict__ in, __nv_bfloat16* __restrict__ hi,
    __nv_bfloat16* __restrict__ lo, int n4)
{
    int i = blockIdx.x * blockDim.x + threadIdx.x;
    if (i >= n4) return;
    float4 v = ((const float4*)in)[i];
    float x[4] = {v.x, v.y, v.z, v.w};
    __nv_bfloat16 h[4], l[4];
#pragma unroll
    for (int j = 0; j < 4; j++) {
        h[j] = __float2bfloat16(x[j]);
        l[j] = __float2bfloat16(x[j] - __bfloat162float(h[j]));
    }
    __nv_bfloat162* hp = (__nv_bfloat162*)hi;
    __nv_bfloat162* lp = (__nv_bfloat162*)lo;
    hp[2 * i]     = __nv_bfloat162(h[0], h[1]);
    hp[2 * i + 1] = __nv_bfloat162(h[2], h[3]);
    lp[2 * i]     = __nv_bfloat162(l[0], l[1]);
    lp[2 * i + 1] = __nv_bfloat162(l[2], l[3]);
}

// ---------------------------------------------------------------------------
// mma.sync GEMM-NT, bf16x3:  C[M,N] = (Ah+Al)[M,K] * (Bh+Bl)[N,K]^T (fp32 out)
// CTA 128x128, 8 warps as 4(M)x2(N), warp tile 32x64 (2 m-frags x 8 n-frags).
// BK=64 (4 k16-steps per chunk), SW128 smem, 3-stage cp.async pipeline.
// ---------------------------------------------------------------------------
#define GK        64
#define TILE_B    (128 * GK * 2)        // 16384 B per bf16 tile
#define STAGE_B   (4 * TILE_B)          // 65536 B  (Ah, Al, Bh, Bl)
#define NSTAGE    3
#define GEMM_SMEM (NSTAGE * STAGE_B)    // 196608 B
#define NCHUNK    (D_MODEL / GK)        // 32

__global__ __launch_bounds__(256) void gemm_mma_x3_kernel(
    const __nv_bfloat16* __restrict__ Ah, const __nv_bfloat16* __restrict__ Al,
    const __nv_bfloat16* __restrict__ Bh, const __nv_bfloat16* __restrict__ Bl,
    float* __restrict__ C)
{
    extern __shared__ char smem[];
    const uint32_t smem_base = smem_u32(smem);
    const int tid  = threadIdx.x;
    const int wid  = tid >> 5;
    const int lane = tid & 31;
    const int wm   = wid & 3;       // 0..3 -> m offset wm*32
    const int wn   = wid >> 2;      // 0..1 -> n offset wn*64
    const int row0 = blockIdx.y * 128;
    const int col0 = blockIdx.x * 128;

    // per-thread copy coordinates: 4 x (row, 16B-segment) per 16KB tile
    int cr[4], cs[4];
    uint32_t csw[4];
#pragma unroll
    for (int i = 0; i < 4; i++) {
        int idx = tid + i * 256;
        cr[i]  = idx >> 3;          // 0..127
        cs[i]  = idx & 7;           // 0..7
        csw[i] = SMEM_SWIZZLE_128B((uint32_t)(cr[i] * 128 + cs[i] * 16));
    }

    auto copy_stage = [&](int st, int kc) {
        const uint32_t sb = smem_base + st * STAGE_B;
#pragma unroll
        for (int i = 0; i < 4; i++) {
            const size_t aoff = (size_t)(row0 + cr[i]) * D_MODEL + kc * GK + cs[i] * 8;
            const size_t boff = (size_t)(col0 + cr[i]) * D_MODEL + kc * GK + cs[i] * 8;
            cp_async16(sb + 0 * TILE_B + csw[i], Ah + aoff);
            cp_async16(sb + 1 * TILE_B + csw[i], Al + aoff);
            cp_async16(sb + 2 * TILE_B + csw[i], Bh + boff);
            cp_async16(sb + 3 * TILE_B + csw[i], Bl + boff);
        }
    };

    float acc[2][8][4];
#pragma unroll
    for (int mf = 0; mf < 2; mf++)
#pragma unroll
        for (int nf = 0; nf < 8; nf++)
#pragma unroll
            for (int r = 0; r < 4; r++) acc[mf][nf][r] = 0.f;

    // ldmatrix lane geometry (same pattern for A and B, K-major NT layout)
    const int quad = lane >> 3;
    const int r16  = (lane & 7) | ((quad & 1) << 3);
    const int cbq  = (quad >> 1) << 4;     // 0 or 16 bytes (k-halves)

    copy_stage(0, 0);
    asm volatile("cp.async.commit_group;");
    copy_stage(1, 1);
    asm volatile("cp.async.commit_group;");

    for (int kc = 0; kc < NCHUNK; kc++) {
        if (kc + 2 < NCHUNK) copy_stage((kc + 2) % NSTAGE, kc + 2);
        asm volatile("cp.async.commit_group;");
        asm volatile("cp.async.wait_group 2;");
        __syncthreads();

        const uint32_t sb  = smem_base + (kc % NSTAGE) * STAGE_B;
        const uint32_t sAh = sb + 0 * TILE_B;
        const uint32_t sAl = sb + 1 * TILE_B;
        const uint32_t sBh = sb + 2 * TILE_B;
        const uint32_t sBl = sb + 3 * TILE_B;

#pragma unroll
        for (int ks = 0; ks < 4; ks++) {
            uint32_t ah[2][4], al[2][4], bh[8][2], bl[8][2];
#pragma unroll
            for (int mf = 0; mf < 2; mf++) {
                const int row = wm * 32 + mf * 16 + r16;
                const uint32_t off =
                    SMEM_SWIZZLE_128B((uint32_t)(row * 128 + cbq + ks * 32));
                ldsm4(ah[mf], sAh + off);
                ldsm4(al[mf], sAl + off);
            }
#pragma unroll
            for (int p = 0; p < 4; p++) {
                const int row = wn * 64 + p * 16 + r16;
                const uint32_t off =
                    SMEM_SWIZZLE_128B((uint32_t)(row * 128 + cbq + ks * 32));
                uint32_t q[4];
                ldsm4(q, sBh + off);
                bh[2 * p][0] = q[0]; bh[2 * p][1] = q[2];
                bh[2 * p + 1][0] = q[1]; bh[2 * p + 1][1] = q[3];
                ldsm4(q, sBl + off);
                bl[2 * p][0] = q[0]; bl[2 * p][1] = q[2];
                bl[2 * p + 1][0] = q[1]; bl[2 * p + 1][1] = q[3];
            }
#pragma unroll
            for (int mf = 0; mf < 2; mf++)
#pragma unroll
                for (int nf = 0; nf < 8; nf++) {
                    mma16816(acc[mf][nf], ah[mf], bh[nf]);
                    mma16816(acc[mf][nf], ah[mf], bl[nf]);
                    mma16816(acc[mf][nf], al[mf], bh[nf]);
                }
        }
        __syncthreads();
    }

    // epilogue: lane l holds rows (l/4, l/4+8), cols (l%4)*2,+1 of each frag
#pragma unroll
    for (int mf = 0; mf < 2; mf++) {
        const int row = row0 + wm * 32 + mf * 16 + (lane >> 2);
#pragma unroll
        for (int nf = 0; nf < 8; nf++) {
            const int col = col0 + wn * 64 + nf * 8 + (lane & 3) * 2;
            float* p0 = C + (size_t)row * D_MODEL + col;
            float* p1 = C + (size_t)(row + 8) * D_MODEL + col;
            *(float2*)p0 = make_float2(acc[mf][nf][0], acc[mf][nf][1]);
            *(float2*)p1 = make_float2(acc[mf][nf][2], acc[mf][nf][3]);
        }
    }
}

// ---------------------------------------------------------------------------
// Flash attention (fp32 SIMT) -- unchanged, known-correct from R4
// ---------------------------------------------------------------------------
#define BQ     64
#define BKV    64
#define QS_STR 68
#define ATTN_SMEM_FLOATS (128 * QS_STR * 2 + BKV * HDIM + BKV * QS_STR)

__global__ __launch_bounds__(256) void attn_kernel()
{
    extern __shared__ __align__(16) float sm[];
    float* Qs = sm;
    float* Ks = Qs + 128 * QS_STR;
    float* Vs = Ks + 128 * QS_STR;
    float* Ps = Vs + BKV * HDIM;

    const int tid = threadIdx.x;
    const int tx  = tid & 15;
    const int ty  = tid >> 4;
    const int b   = blockIdx.z;
    const int h   = blockIdx.y;
    const int q0  = blockIdx.x * BQ;
    const float scale = 0.0883883476483184f;

    const float* Qg = g_Q + (size_t)(b * S_LEN + q0) * D_MODEL + h * HDIM;
    const float* Kg = g_K + (size_t)(b * S_LEN) * D_MODEL + h * HDIM;
    const float* Vg = g_V + (size_t)(b * S_LEN) * D_MODEL + h * HDIM;

#pragma unroll
    for (int i = 0; i < 8; i++) {
        int idx = tid + i * 256;
        int r = idx >> 5;
        int c = (idx & 31) * 4;
        float4 v = *(const float4*)(Qg + (size_t)r * D_MODEL + c);
        Qs[(c + 0) * QS_STR + r] = v.x * scale;
        Qs[(c + 1) * QS_STR + r] = v.y * scale;
        Qs[(c + 2) * QS_STR + r] = v.z * scale;
        Qs[(c + 3) * QS_STR + r] = v.w * scale;
    }

    float m_i[4], l_i[4], acc[4][8];
#pragma unroll
    for (int i = 0; i < 4; i++) {
        m_i[i] = -1e30f; l_i[i] = 0.f;
#pragma unroll
        for (int j = 0; j < 8; j++) acc[i][j] = 0.f;
    }

    for (int t = 0; t < S_LEN / BKV; t++) {
        const float* Kt = Kg + (size_t)(t * BKV) * D_MODEL;
        const float* Vt = Vg + (size_t)(t * BKV) * D_MODEL;

        __syncthreads();
#pragma unroll
        for (int i = 0; i < 8; i++) {
            int idx = tid + i * 256;
            int r = idx >> 5;
            int c = (idx & 31) * 4;
            float4 kv = *(const float4*)(Kt + (size_t)r * D_MODEL + c);
            Ks[(c + 0) * QS_STR + r] = kv.x;
            Ks[(c + 1) * QS_STR + r] = kv.y;
            Ks[(c + 2) * QS_STR + r] = kv.z;
            Ks[(c + 3) * QS_STR + r] = kv.w;
            float4 vv = *(const float4*)(Vt + (size_t)r * D_MODEL + c);
            *(float4*)(Vs + r * HDIM + c) = vv;
        }
        __syncthreads();

        float s[4][4];
#pragma unroll
        for (int i = 0; i < 4; i++)
#pragma unroll
            for (int j = 0; j < 4; j++) s[i][j] = 0.f;

#pragma unroll 8
        for (int d = 0; d < HDIM; d++) {
            float4 qv = *(const float4*)(Qs + d * QS_STR + ty * 4);
            float4 kv = *(const float4*)(Ks + d * QS_STR + tx * 4);
            float qa[4] = {qv.x, qv.y, qv.z, qv.w};
            float kb[4] = {kv.x, kv.y, kv.z, kv.w};
#pragma unroll
            for (int i = 0; i < 4; i++)
#pragma unroll
                for (int j = 0; j < 4; j++)
                    s[i][j] = fmaf(qa[i], kb[j], s[i][j]);
        }

#pragma unroll
        for (int i = 0; i < 4; i++) {
            float mx = fmaxf(fmaxf(s[i][0], s[i][1]), fmaxf(s[i][2], s[i][3]));
            mx = fmaxf(mx, __shfl_xor_sync(0xffffffffu, mx, 1));
            mx = fmaxf(mx, __shfl_xor_sync(0xffffffffu, mx, 2));
            mx = fmaxf(mx, __shfl_xor_sync(0xffffffffu, mx, 4));
            mx = fmaxf(mx, __shfl_xor_sync(0xffffffffu, mx, 8));
            float mnew  = fmaxf(m_i[i], mx);
            float alpha = __expf(m_i[i] - mnew);
            m_i[i] = mnew;
            float rs = 0.f;
#pragma unroll
            for (int j = 0; j < 4; j++) {
                float p = __expf(s[i][j] - mnew);
                s[i][j] = p;
                rs += p;
            }
            rs += __shfl_xor_sync(0xffffffffu, rs, 1);
            rs += __shfl_xor_sync(0xffffffffu, rs, 2);
            rs += __shfl_xor_sync(0xffffffffu, rs, 4);
            rs += __shfl_xor_sync(0xffffffffu, rs, 8);
            l_i[i] = l_i[i] * alpha + rs;
#pragma unroll
            for (int j = 0; j < 8; j++) acc[i][j] *= alpha;
        }

#pragma unroll
        for (int j = 0; j < 4; j++) {
            *(float4*)(Ps + (tx * 4 + j) * QS_STR + ty * 4) =
                make_float4(s[0][j], s[1][j], s[2][j], s[3][j]);
        }
        __syncthreads();

#pragma unroll 4
        for (int kk = 0; kk < BKV; kk++) {
            float4 pa = *(const float4*)(Ps + kk * QS_STR + ty * 4);
            float4 v0 = *(const float4*)(Vs + kk * HDIM + tx * 8);
            float4 v1 = *(const float4*)(Vs + kk * HDIM + tx * 8 + 4);
            float aa[4] = {pa.x, pa.y, pa.z, pa.w};
            float bb[8] = {v0.x, v0.y, v0.z, v0.w, v1.x, v1.y, v1.z, v1.w};
#pragma unroll
            for (int i = 0; i < 4; i++)
#pragma unroll
                for (int j = 0; j < 8; j++)
                    acc[i][j] = fmaf(aa[i], bb[j], acc[i][j]);
        }
    }

    float* Cg = g_ctx + (size_t)(b * S_LEN + q0) * D_MODEL + h * HDIM;
#pragma unroll
    for (int i = 0; i < 4; i++) {
        float inv = 1.0f / l_i[i];
        float* cp = Cg + (size_t)(ty * 4 + i) * D_MODEL + tx * 8;
        *(float4*)cp = make_float4(acc[i][0] * inv, acc[i][1] * inv,
                                   acc[i][2] * inv, acc[i][3] * inv);
        *(float4*)(cp + 4) = make_float4(acc[i][4] * inv, acc[i][5] * inv,
                                         acc[i][6] * inv, acc[i][7] * inv);
    }
}

// ---------------------------------------------------------------------------
extern "C" void kernel_launch(void* const* d_in, const int* in_sizes, int n_in,
                              void* d_out, int out_size)
{
    const float* x  = (const float*)d_in[0];
    const float* Wq = (const float*)d_in[1];
    const float* Wk = (const float*)d_in[2];
    const float* Wv = (const float*)d_in[3];
    const float* Wo = (const float*)d_in[4];
    float* out = (float*)d_out;

    float *Q, *K, *V, *ctx;
    __nv_bfloat16 *xh, *xl, *wh, *wl;
    cudaGetSymbolAddress((void**)&Q,   g_Q);
    cudaGetSymbolAddress((void**)&K,   g_K);
    cudaGetSymbolAddress((void**)&V,   g_V);
    cudaGetSymbolAddress((void**)&ctx, g_ctx);
    cudaGetSymbolAddress((void**)&xh,  g_xh);
    cudaGetSymbolAddress((void**)&xl,  g_xl);
    cudaGetSymbolAddress((void**)&wh,  g_wh);
    cudaGetSymbolAddress((void**)&wl,  g_wl);

    cudaFuncSetAttribute(gemm_mma_x3_kernel,
                         cudaFuncAttributeMaxDynamicSharedMemorySize, GEMM_SMEM);
    cudaFuncSetAttribute(attn_kernel, cudaFuncAttributeMaxDynamicSharedMemorySize,
                         ATTN_SMEM_FLOATS * (int)sizeof(float));

    const int nx4 = MROWS * D_MODEL / 4;
    const int nw4 = D_MODEL * D_MODEL / 4;
    dim3 ggrid(D_MODEL / 128, MROWS / 128);   // (16, 32)

    cvt_hilo_kernel<<<(nx4 + 255) / 256, 256>>>(x, xh, xl, nx4);

    cvt_hilo_kernel<<<(nw4 + 255) / 256, 256>>>(Wq, wh, wl, nw4);
    gemm_mma_x3_kernel<<<ggrid, 256, GEMM_SMEM>>>(xh, xl, wh, wl, Q);

    cvt_hilo_kernel<<<(nw4 + 255) / 256, 256>>>(Wk, wh, wl, nw4);
    gemm_mma_x3_kernel<<<ggrid, 256, GEMM_SMEM>>>(xh, xl, wh, wl, K);

    cvt_hilo_kernel<<<(nw4 + 255) / 256, 256>>>(Wv, wh, wl, nw4);
    gemm_mma_x3_kernel<<<ggrid, 256, GEMM_SMEM>>>(xh, xl, wh, wl, V);

    attn_kernel<<<dim3(S_LEN / BQ, NHEADS, BATCH), 256,
                  ATTN_SMEM_FLOATS * (int)sizeof(float)>>>();

    cvt_hilo_kernel<<<(nx4 + 255) / 256, 256>>>(ctx, xh, xl, nx4);
    cvt_hilo_kernel<<<(nw4 + 255) / 256, 256>>>(Wo, wh, wl, nw4);
    gemm_mma_x3_kernel<<<ggrid, 256, GEMM_SMEM>>>(xh, xl, wh, wl, out);
}

// round 10
// speedup vs baseline: 2.8676x; 1.9157x over previous
#include <cuda_runtime.h>
#include <cuda_bf16.h>
#include <cstdint>

// ---------------------------------------------------------------------------
// MultiHeadSelfAttention  B=2, S=2048, D=2048, H=16, Hd=128, fp32 in/out
//   All GEMMs + attention on mma.sync HMMA bf16 "x3" (hi/lo split).
//   (tcgen05 unavailable: harness builds at virtual arch compute_103.)
// ---------------------------------------------------------------------------

#define S_LEN   2048
#define D_MODEL 2048
#define BATCH   2
#define NHEADS  16
#define HDIM    128
#define MROWS   (BATCH * S_LEN)   // 4096

// ------------------------- scratch (static, allocation-free) ---------------
__device__ __nv_bfloat16 g_xh[(size_t)MROWS * D_MODEL];   // x, later ctx (hi)
__device__ __nv_bfloat16 g_xl[(size_t)MROWS * D_MODEL];   // x, later ctx (lo)
__device__ __nv_bfloat16 g_wh[(size_t)D_MODEL * D_MODEL];
__device__ __nv_bfloat16 g_wl[(size_t)D_MODEL * D_MODEL];
__device__ __nv_bfloat16 g_qh[(size_t)MROWS * D_MODEL];   // pre-scaled by 1/sqrt(Hd)
__device__ __nv_bfloat16 g_ql[(size_t)MROWS * D_MODEL];
__device__ __nv_bfloat16 g_kh[(size_t)MROWS * D_MODEL];
__device__ __nv_bfloat16 g_kl[(size_t)MROWS * D_MODEL];
__device__ __nv_bfloat16 g_vh[(size_t)MROWS * D_MODEL];
__device__ __nv_bfloat16 g_vl[(size_t)MROWS * D_MODEL];

// ------------------------- helpers -----------------------------------------
__device__ __forceinline__ uint32_t smem_u32(const void* p) {
    uint32_t a;
    asm("{ .reg .u64 t; cvta.to.shared.u64 t, %1; cvt.u32.u64 %0, t; }"
        : "=r"(a) : "l"(p));
    return a;
}
#define SMEM_SWIZZLE_128B(off) ((off) ^ (((off) >> 3) & 0x70))

__device__ __forceinline__ void ldsm4(uint32_t* r, uint32_t addr) {
    asm volatile("ldmatrix.sync.aligned.m8n8.x4.shared.b16 {%0,%1,%2,%3}, [%4];"
                 : "=r"(r[0]), "=r"(r[1]), "=r"(r[2]), "=r"(r[3]) : "r"(addr));
}
__device__ __forceinline__ void ldsm4t(uint32_t* r, uint32_t addr) {
    asm volatile("ldmatrix.sync.aligned.m8n8.x4.trans.shared.b16 {%0,%1,%2,%3}, [%4];"
                 : "=r"(r[0]), "=r"(r[1]), "=r"(r[2]), "=r"(r[3]) : "r"(addr));
}
__device__ __forceinline__ void mma16816(float* d, const uint32_t* a, const uint32_t* b) {
    asm volatile(
        "mma.sync.aligned.m16n8k16.row.col.f32.bf16.bf16.f32 "
        "{%0,%1,%2,%3}, {%4,%5,%6,%7}, {%8,%9}, {%0,%1,%2,%3};"
        : "+f"(d[0]), "+f"(d[1]), "+f"(d[2]), "+f"(d[3])
        : "r"(a[0]), "r"(a[1]), "r"(a[2]), "r"(a[3]), "r"(b[0]), "r"(b[1]));
}
__device__ __forceinline__ void cp_async16(uint32_t sdst, const void* gsrc) {
    asm volatile("cp.async.cg.shared.global [%0], [%1], 16;" :: "r"(sdst), "l"(gsrc));
}
__device__ __forceinline__ uint32_t pack_bf16x2(float a, float b) {
    __nv_bfloat162 v(__float2bfloat16(a), __float2bfloat16(b));
    return *(uint32_t*)&v;
}

// ---------------------------------------------------------------------------
// fp32 -> (bf16 hi, bf16 lo) split.
// ---------------------------------------------------------------------------
__global__ __launch_bounds__(256) void cvt_hilo_kernel(
    const float* __restrict__ in, __nv_bfloat16* __restrict__ hi,
    __nv_bfloat16* __restrict__ lo, int n4)
{
    int i = blockIdx.x * blockDim.x + threadIdx.x;
    if (i >= n4) return;
    float4 v = ((const float4*)in)[i];
    float x[4] = {v.x, v.y, v.z, v.w};
    __nv_bfloat16 h[4], l[4];
#pragma unroll
    for (int j = 0; j < 4; j++) {
        h[j] = __float2bfloat16(x[j]);
        l[j] = __float2bfloat16(x[j] - __bfloat162float(h[j]));
    }
    __nv_bfloat162* hp = (__nv_bfloat162*)hi;
    __nv_bfloat162* lp = (__nv_bfloat162*)lo;
    hp[2 * i]     = __nv_bfloat162(h[0], h[1]);
    hp[2 * i + 1] = __nv_bfloat162(h[2], h[3]);
    lp[2 * i]     = __nv_bfloat162(l[0], l[1]);
    lp[2 * i + 1] = __nv_bfloat162(l[2], l[3]);
}

// ---------------------------------------------------------------------------
// mma.sync GEMM-NT bf16x3 (structure identical to the passing R9 kernel).
// Epilogue: if Cf != null -> fp32; else -> bf16 hi/lo pair, scaled by oscale.
// ---------------------------------------------------------------------------
#define GK        64
#define TILE_B    (128 * GK * 2)
#define STAGE_B   (4 * TILE_B)
#define NSTAGE    3
#define GEMM_SMEM (NSTAGE * STAGE_B)
#define NCHUNK    (D_MODEL / GK)

__global__ __launch_bounds__(256) void gemm_mma_x3_kernel(
    const __nv_bfloat16* __restrict__ Ah, const __nv_bfloat16* __restrict__ Al,
    const __nv_bfloat16* __restrict__ Bh, const __nv_bfloat16* __restrict__ Bl,
    float* __restrict__ Cf, __nv_bfloat16* __restrict__ Ch,
    __nv_bfloat16* __restrict__ Cl, float oscale)
{
    extern __shared__ char smem[];
    const uint32_t smem_base = smem_u32(smem);
    const int tid  = threadIdx.x;
    const int wid  = tid >> 5;
    const int lane = tid & 31;
    const int wm   = wid & 3;
    const int wn   = wid >> 2;
    const int row0 = blockIdx.y * 128;
    const int col0 = blockIdx.x * 128;

    int cr[4], cs[4];
    uint32_t csw[4];
#pragma unroll
    for (int i = 0; i < 4; i++) {
        int idx = tid + i * 256;
        cr[i]  = idx >> 3;
        cs[i]  = idx & 7;
        csw[i] = SMEM_SWIZZLE_128B((uint32_t)(cr[i] * 128 + cs[i] * 16));
    }

    auto copy_stage = [&](int st, int kc) {
        const uint32_t sb = smem_base + st * STAGE_B;
#pragma unroll
        for (int i = 0; i < 4; i++) {
            const size_t aoff = (size_t)(row0 + cr[i]) * D_MODEL + kc * GK + cs[i] * 8;
            const size_t boff = (size_t)(col0 + cr[i]) * D_MODEL + kc * GK + cs[i] * 8;
            cp_async16(sb + 0 * TILE_B + csw[i], Ah + aoff);
            cp_async16(sb + 1 * TILE_B + csw[i], Al + aoff);
            cp_async16(sb + 2 * TILE_B + csw[i], Bh + boff);
            cp_async16(sb + 3 * TILE_B + csw[i], Bl + boff);
        }
    };

    float acc[2][8][4];
#pragma unroll
    for (int mf = 0; mf < 2; mf++)
#pragma unroll
        for (int nf = 0; nf < 8; nf++)
#pragma unroll
            for (int r = 0; r < 4; r++) acc[mf][nf][r] = 0.f;

    const int quad = lane >> 3;
    const int r16  = (lane & 7) | ((quad & 1) << 3);
    const int cbq  = (quad >> 1) << 4;

    copy_stage(0, 0);
    asm volatile("cp.async.commit_group;");
    copy_stage(1, 1);
    asm volatile("cp.async.commit_group;");

    for (int kc = 0; kc < NCHUNK; kc++) {
        if (kc + 2 < NCHUNK) copy_stage((kc + 2) % NSTAGE, kc + 2);
        asm volatile("cp.async.commit_group;");
        asm volatile("cp.async.wait_group 2;");
        __syncthreads();

        const uint32_t sb  = smem_base + (kc % NSTAGE) * STAGE_B;
        const uint32_t sAh = sb + 0 * TILE_B;
        const uint32_t sAl = sb + 1 * TILE_B;
        const uint32_t sBh = sb + 2 * TILE_B;
        const uint32_t sBl = sb + 3 * TILE_B;

#pragma unroll
        for (int ks = 0; ks < 4; ks++) {
            uint32_t ah[2][4], al[2][4], bh[8][2], bl[8][2];
#pragma unroll
            for (int mf = 0; mf < 2; mf++) {
                const int row = wm * 32 + mf * 16 + r16;
                const uint32_t off =
                    SMEM_SWIZZLE_128B((uint32_t)(row * 128 + cbq + ks * 32));
                ldsm4(ah[mf], sAh + off);
                ldsm4(al[mf], sAl + off);
            }
#pragma unroll
            for (int p = 0; p < 4; p++) {
                const int row = wn * 64 + p * 16 + r16;
                const uint32_t off =
                    SMEM_SWIZZLE_128B((uint32_t)(row * 128 + cbq + ks * 32));
                uint32_t q[4];
                ldsm4(q, sBh + off);
                bh[2 * p][0] = q[0]; bh[2 * p][1] = q[2];
                bh[2 * p + 1][0] = q[1]; bh[2 * p + 1][1] = q[3];
                ldsm4(q, sBl + off);
                bl[2 * p][0] = q[0]; bl[2 * p][1] = q[2];
                bl[2 * p + 1][0] = q[1]; bl[2 * p + 1][1] = q[3];
            }
#pragma unroll
            for (int mf = 0; mf < 2; mf++)
#pragma unroll
                for (int nf = 0; nf < 8; nf++) {
                    mma16816(acc[mf][nf], ah[mf], bh[nf]);
                    mma16816(acc[mf][nf], ah[mf], bl[nf]);
                    mma16816(acc[mf][nf], al[mf], bh[nf]);
                }
        }
        __syncthreads();
    }

#pragma unroll
    for (int mf = 0; mf < 2; mf++) {
        const int row = row0 + wm * 32 + mf * 16 + (lane >> 2);
#pragma unroll
        for (int nf = 0; nf < 8; nf++) {
            const int col = col0 + wn * 64 + nf * 8 + (lane & 3) * 2;
            if (Cf) {
                float* p0 = Cf + (size_t)row * D_MODEL + col;
                float* p1 = Cf + (size_t)(row + 8) * D_MODEL + col;
                *(float2*)p0 = make_float2(acc[mf][nf][0], acc[mf][nf][1]);
                *(float2*)p1 = make_float2(acc[mf][nf][2], acc[mf][nf][3]);
            } else {
                float v[4];
#pragma unroll
                for (int r = 0; r < 4; r++) v[r] = acc[mf][nf][r] * oscale;
                __nv_bfloat16 hh[4];
                float lo[4];
#pragma unroll
                for (int r = 0; r < 4; r++) {
                    hh[r] = __float2bfloat16(v[r]);
                    lo[r] = v[r] - __bfloat162float(hh[r]);
                }
                *(uint32_t*)(Ch + (size_t)row * D_MODEL + col) =
                    pack_bf16x2(__bfloat162float(hh[0]), __bfloat162float(hh[1]));
                *(uint32_t*)(Ch + (size_t)(row + 8) * D_MODEL + col) =
                    pack_bf16x2(__bfloat162float(hh[2]), __bfloat162float(hh[3]));
                *(uint32_t*)(Cl + (size_t)row * D_MODEL + col) = pack_bf16x2(lo[0], lo[1]);
                *(uint32_t*)(Cl + (size_t)(row + 8) * D_MODEL + col) = pack_bf16x2(lo[2], lo[3]);
            }
        }
    }
}

// ---------------------------------------------------------------------------
// Tensor-core flash attention, bf16x3.
// CTA: 64 q-rows x one (b,h); stream KV in 64-row blocks; 8 warps, 256 thr.
// QK^T: warps 2(M)x4(N), warp tile 32x16.  PV: warps 2(M)x4(N), tile 32x32.
// S -> smem (f32) -> SIMT online softmax -> P hi/lo (smem) -> PV mma.
// ---------------------------------------------------------------------------
#define AT_QH   0
#define AT_QL   16384
#define AT_KST  32768            // 2 stages x (Kh 16K + Kl 16K)
#define AT_VST  98304            // 2 stages x (Vh 16K + Vl 16K)
#define AT_SS   163840           // 64 x 68 f32
#define AT_PH   181248           // 64 x 64 bf16 swizzled
#define AT_PL   189440
#define AT_AL   197632           // alpha[64] f32
#define AT_LR   197888           // l[64] f32
#define AT_SMEM 198144
#define NKV     (S_LEN / 64)     // 32

// copy one 64x128 bf16 tile (row-major, stride D_MODEL) into chunked SW128 smem
__device__ __forceinline__ void at_copy_tile(uint32_t dst, const __nv_bfloat16* src,
                                             int tid) {
#pragma unroll
    for (int i = 0; i < 4; i++) {
        int idx = tid + i * 256;
        int c   = idx >> 9;          // d-chunk 0/1
        int r   = (idx >> 3) & 63;   // row
        int sg  = idx & 7;           // 16B segment
        uint32_t so = dst + c * 8192 +
                      SMEM_SWIZZLE_128B((uint32_t)(r * 128 + sg * 16));
        cp_async16(so, src + (size_t)r * D_MODEL + c * 64 + sg * 8);
    }
}

__global__ __launch_bounds__(256) void attn_mma_kernel()
{
    extern __shared__ char smbuf[];
    const uint32_t sb = smem_u32(smbuf);
    const int tid  = threadIdx.x;
    const int wid  = tid >> 5;
    const int lane = tid & 31;
    const int b    = blockIdx.z;
    const int h    = blockIdx.y;
    const int q0   = blockIdx.x * 64;

    const int r16 = (lane & 7) | (((lane >> 3) & 1) << 3);
    const int cbq = ((lane >> 4) & 1) << 4;
    const int wm  = wid & 1;        // M warp coord (both phases)
    const int wn  = wid >> 1;       // N warp coord (both phases)

    const size_t hoff = (size_t)h * HDIM;
    const __nv_bfloat16* Qhg = g_qh + (size_t)(b * S_LEN + q0) * D_MODEL + hoff;
    const __nv_bfloat16* Qlg = g_ql + (size_t)(b * S_LEN + q0) * D_MODEL + hoff;
    const __nv_bfloat16* Khg = g_kh + (size_t)(b * S_LEN) * D_MODEL + hoff;
    const __nv_bfloat16* Klg = g_kl + (size_t)(b * S_LEN) * D_MODEL + hoff;
    const __nv_bfloat16* Vhg = g_vh + (size_t)(b * S_LEN) * D_MODEL + hoff;
    const __nv_bfloat16* Vlg = g_vl + (size_t)(b * S_LEN) * D_MODEL + hoff;

    float* Ssp   = (float*)(smbuf + AT_SS);
    float* alphp = (float*)(smbuf + AT_AL);
    float* lrowp = (float*)(smbuf + AT_LR);

    // preload Q + stage 0 of K/V
    at_copy_tile(sb + AT_QH, Qhg, tid);
    at_copy_tile(sb + AT_QL, Qlg, tid);
    at_copy_tile(sb + AT_KST,         Khg, tid);
    at_copy_tile(sb + AT_KST + 16384, Klg, tid);
    at_copy_tile(sb + AT_VST,         Vhg, tid);
    at_copy_tile(sb + AT_VST + 16384, Vlg, tid);
    asm volatile("cp.async.commit_group;");

    float m_i = -1e30f, l_i = 0.f;     // softmax state: row = tid>>2
    float o_acc[2][4][4];
#pragma unroll
    for (int mf = 0; mf < 2; mf++)
#pragma unroll
        for (int nf = 0; nf < 4; nf++)
#pragma unroll
            for (int r = 0; r < 4; r++) o_acc[mf][nf][r] = 0.f;

    const int srow = tid >> 2;          // softmax row
    const int scol = (tid & 3) * 16;    // softmax col base

    for (int it = 0; it < NKV; it++) {
        const int st = it & 1;
        asm volatile("cp.async.wait_group 0;");
        __syncthreads();                                  // stage it ready

        // ---- S = Q K^T (x3) ----
        float sacc[2][2][4];
#pragma unroll
        for (int mf = 0; mf < 2; mf++)
#pragma unroll
            for (int nf = 0; nf < 2; nf++)
#pragma unroll
                for (int r = 0; r < 4; r++) sacc[mf][nf][r] = 0.f;

        const uint32_t kb_h = sb + AT_KST + st * 32768;
        const uint32_t kb_l = kb_h + 16384;
#pragma unroll
        for (int ks = 0; ks < 8; ks++) {
            const int chunk = ks >> 2;
            const int kbyte = (ks & 3) * 32 + cbq;
            uint32_t ah[2][4], al[2][4];
#pragma unroll
            for (int mf = 0; mf < 2; mf++) {
                const uint32_t off = chunk * 8192 +
                    SMEM_SWIZZLE_128B((uint32_t)((wm * 32 + mf * 16 + r16) * 128 + kbyte));
                ldsm4(ah[mf], sb + AT_QH + off);
                ldsm4(al[mf], sb + AT_QL + off);
            }
            const uint32_t offb = chunk * 8192 +
                SMEM_SWIZZLE_128B((uint32_t)((wn * 16 + r16) * 128 + kbyte));
            uint32_t qh[4], ql[4];
            ldsm4(qh, kb_h + offb);
            ldsm4(ql, kb_l + offb);
            uint32_t bh[2][2] = {{qh[0], qh[2]}, {qh[1], qh[3]}};
            uint32_t bl[2][2] = {{ql[0], ql[2]}, {ql[1], ql[3]}};
#pragma unroll
            for (int mf = 0; mf < 2; mf++)
#pragma unroll
                for (int nf = 0; nf < 2; nf++) {
                    mma16816(sacc[mf][nf], ah[mf], bh[nf]);
                    mma16816(sacc[mf][nf], ah[mf], bl[nf]);
                    mma16816(sacc[mf][nf], al[mf], bh[nf]);
                }
        }

        // ---- store S to smem ----
#pragma unroll
        for (int mf = 0; mf < 2; mf++) {
            const int row = wm * 32 + mf * 16 + (lane >> 2);
#pragma unroll
            for (int nf = 0; nf < 2; nf++) {
                const int col = wn * 16 + nf * 8 + (lane & 3) * 2;
                *(float2*)(Ssp + row * 68 + col) =
                    make_float2(sacc[mf][nf][0], sacc[mf][nf][1]);
                *(float2*)(Ssp + (row + 8) * 68 + col) =
                    make_float2(sacc[mf][nf][2], sacc[mf][nf][3]);
            }
        }
        __syncthreads();                                  // S visible; iter-1 fully done

        // ---- prefetch next K/V stage (overlaps softmax + PV) ----
        if (it + 1 < NKV) {
            const int ns = (it + 1) & 1;
            const size_t roff = (size_t)((it + 1) * 64) * D_MODEL;
            at_copy_tile(sb + AT_KST + ns * 32768,         Khg + roff, tid);
            at_copy_tile(sb + AT_KST + ns * 32768 + 16384, Klg + roff, tid);
            at_copy_tile(sb + AT_VST + ns * 32768,         Vhg + roff, tid);
            at_copy_tile(sb + AT_VST + ns * 32768 + 16384, Vlg + roff, tid);
            asm volatile("cp.async.commit_group;");
        }

        // ---- online softmax (4 threads per row) ----
        {
            float sv[16];
#pragma unroll
            for (int u = 0; u < 4; u++)
                *(float4*)(sv + u * 4) = *(float4*)(Ssp + srow * 68 + scol + u * 4);
            float mx = sv[0];
#pragma unroll
            for (int u = 1; u < 16; u++) mx = fmaxf(mx, sv[u]);
            mx = fmaxf(mx, __shfl_xor_sync(0xffffffffu, mx, 1));
            mx = fmaxf(mx, __shfl_xor_sync(0xffffffffu, mx, 2));
            const float mnew  = fmaxf(m_i, mx);
            const float alpha = __expf(m_i - mnew);
            m_i = mnew;
            float sum = 0.f;
            float p[16];
#pragma unroll
            for (int u = 0; u < 16; u++) {
                p[u] = __expf(sv[u] - mnew);
                sum += p[u];
            }
            sum += __shfl_xor_sync(0xffffffffu, sum, 1);
            sum += __shfl_xor_sync(0xffffffffu, sum, 2);
            l_i = l_i * alpha + sum;
            // write P hi/lo (K-major 64x64, SW128)
#pragma unroll
            for (int u2 = 0; u2 < 8; u2++) {
                const uint32_t off =
                    SMEM_SWIZZLE_128B((uint32_t)(srow * 128 + (scol + u2 * 2) * 2));
                const float p0 = p[u2 * 2], p1 = p[u2 * 2 + 1];
                const __nv_bfloat16 h0 = __float2bfloat16(p0);
                const __nv_bfloat16 h1 = __float2bfloat16(p1);
                *(uint32_t*)(smbuf + AT_PH + off) =
                    pack_bf16x2(__bfloat162float(h0), __bfloat162float(h1));
                *(uint32_t*)(smbuf + AT_PL + off) =
                    pack_bf16x2(p0 - __bfloat162float(h0), p1 - __bfloat162float(h1));
            }
            if ((tid & 3) == 0) alphp[srow] = alpha;
        }
        __syncthreads();                                  // P, alpha visible

        // ---- rescale O ----
#pragma unroll
        for (int mf = 0; mf < 2; mf++) {
            const float a0 = alphp[wm * 32 + mf * 16 + (lane >> 2)];
            const float a1 = alphp[wm * 32 + mf * 16 + (lane >> 2) + 8];
#pragma unroll
            for (int nf = 0; nf < 4; nf++) {
                o_acc[mf][nf][0] *= a0; o_acc[mf][nf][1] *= a0;
                o_acc[mf][nf][2] *= a1; o_acc[mf][nf][3] *= a1;
            }
        }

        // ---- O += P V (x3) ----
        const uint32_t vb_h = sb + AT_VST + st * 32768;
        const uint32_t vb_l = vb_h + 16384;
        const int g  = lane >> 3;
        const int kg = (g & 1) << 3;
        const int ng = (g >> 1) << 3;
#pragma unroll
        for (int kpv = 0; kpv < 4; kpv++) {
            uint32_t aph[2][4], apl[2][4];
#pragma unroll
            for (int mf = 0; mf < 2; mf++) {
                const uint32_t off =
                    SMEM_SWIZZLE_128B((uint32_t)((wm * 32 + mf * 16 + r16) * 128 +
                                                 kpv * 32 + cbq));
                ldsm4(aph[mf], sb + AT_PH + off);
                ldsm4(apl[mf], sb + AT_PL + off);
            }
            uint32_t bvh[4][2], bvl[4][2];
#pragma unroll
            for (int pr = 0; pr < 2; pr++) {
                const int kr = kpv * 16 + kg + (lane & 7);
                const int nc = wn * 32 + pr * 16 + ng;
                const uint32_t off = (uint32_t)(nc >> 6) * 8192 +
                    SMEM_SWIZZLE_128B((uint32_t)(kr * 128 + (nc & 63) * 2));
                uint32_t t4[4];
                ldsm4t(t4, vb_h + off);
                bvh[2 * pr][0] = t4[0]; bvh[2 * pr][1] = t4[1];
                bvh[2 * pr + 1][0] = t4[2]; bvh[2 * pr + 1][1] = t4[3];
                ldsm4t(t4, vb_l + off);
                bvl[2 * pr][0] = t4[0]; bvl[2 * pr][1] = t4[1];
                bvl[2 * pr + 1][0] = t4[2]; bvl[2 * pr + 1][1] = t4[3];
            }
#pragma unroll
            for (int mf = 0; mf < 2; mf++)
#pragma unroll
                for (int nf = 0; nf < 4; nf++) {
                    mma16816(o_acc[mf][nf], aph[mf], bvh[nf]);
                    mma16816(o_acc[mf][nf], aph[mf], bvl[nf]);
                    mma16816(o_acc[mf][nf], apl[mf], bvh[nf]);
                }
        }
    }

    // ---- epilogue: 1/l, write ctx hi/lo (reused x buffers) ----
    if ((tid & 3) == 0) lrowp[srow] = l_i;
    __syncthreads();
    if (tid < 64) lrowp[tid] = 1.0f / lrowp[tid];
    __syncthreads();

    __nv_bfloat16* Chg = g_xh + (size_t)(b * S_LEN + q0) * D_MODEL + hoff;
    __nv_bfloat16* Clg = g_xl + (size_t)(b * S_LEN + q0) * D_MODEL + hoff;
#pragma unroll
    for (int mf = 0; mf < 2; mf++) {
        const int ra  = wm * 32 + mf * 16 + (lane >> 2);
        const float i0 = lrowp[ra];
        const float i1 = lrowp[ra + 8];
#pragma unroll
        for (int nf = 0; nf < 4; nf++) {
            const int col = wn * 32 + nf * 8 + (lane & 3) * 2;
            float v0 = o_acc[mf][nf][0] * i0, v1 = o_acc[mf][nf][1] * i0;
            float v2 = o_acc[mf][nf][2] * i1, v3 = o_acc[mf][nf][3] * i1;
            __nv_bfloat16 h0 = __float2bfloat16(v0), h1 = __float2bfloat16(v1);
            __nv_bfloat16 h2 = __float2bfloat16(v2), h3 = __float2bfloat16(v3);
            *(uint32_t*)(Chg + (size_t)ra * D_MODEL + col) =
                pack_bf16x2(__bfloat162float(h0), __bfloat162float(h1));
            *(uint32_t*)(Chg + (size_t)(ra + 8) * D_MODEL + col) =
                pack_bf16x2(__bfloat162float(h2), __bfloat162float(h3));
            *(uint32_t*)(Clg + (size_t)ra * D_MODEL + col) =
                pack_bf16x2(v0 - __bfloat162float(h0), v1 - __bfloat162float(h1));
            *(uint32_t*)(Clg + (size_t)(ra + 8) * D_MODEL + col) =
                pack_bf16x2(v2 - __bfloat162float(h2), v3 - __bfloat162float(h3));
        }
    }
}

// ---------------------------------------------------------------------------
extern "C" void kernel_launch(void* const* d_in, const int* in_sizes, int n_in,
                              void* d_out, int out_size)
{
    const float* x  = (const float*)d_in[0];
    const float* Wq = (const float*)d_in[1];
    const float* Wk = (const float*)d_in[2];
    const float* Wv = (const float*)d_in[3];
    const float* Wo = (const float*)d_in[4];
    float* out = (float*)d_out;

    __nv_bfloat16 *xh, *xl, *wh, *wl, *qh, *ql, *kh, *kl, *vh, *vl;
    cudaGetSymbolAddress((void**)&xh, g_xh);
    cudaGetSymbolAddress((void**)&xl, g_xl);
    cudaGetSymbolAddress((void**)&wh, g_wh);
    cudaGetSymbolAddress((void**)&wl, g_wl);
    cudaGetSymbolAddress((void**)&qh, g_qh);
    cudaGetSymbolAddress((void**)&ql, g_ql);
    cudaGetSymbolAddress((void**)&kh, g_kh);
    cudaGetSymbolAddress((void**)&kl, g_kl);
    cudaGetSymbolAddress((void**)&vh, g_vh);
    cudaGetSymbolAddress((void**)&vl, g_vl);

    cudaFuncSetAttribute(gemm_mma_x3_kernel,
                         cudaFuncAttributeMaxDynamicSharedMemorySize, GEMM_SMEM);
    cudaFuncSetAttribute(attn_mma_kernel,
                         cudaFuncAttributeMaxDynamicSharedMemorySize, AT_SMEM);

    const int nx4 = MROWS * D_MODEL / 4;
    const int nw4 = D_MODEL * D_MODEL / 4;
    dim3 ggrid(D_MODEL / 128, MROWS / 128);
    const float qscale = 0.08838834764831845f;   // 1/sqrt(128)

    cvt_hilo_kernel<<<(nx4 + 255) / 256, 256>>>(x, xh, xl, nx4);

    cvt_hilo_kernel<<<(nw4 + 255) / 256, 256>>>(Wq, wh, wl, nw4);
    gemm_mma_x3_kernel<<<ggrid, 256, GEMM_SMEM>>>(xh, xl, wh, wl,
                                                  nullptr, qh, ql, qscale);
    cvt_hilo_kernel<<<(nw4 + 255) / 256, 256>>>(Wk, wh, wl, nw4);
    gemm_mma_x3_kernel<<<ggrid, 256, GEMM_SMEM>>>(xh, xl, wh, wl,
                                                  nullptr, kh, kl, 1.0f);
    cvt_hilo_kernel<<<(nw4 + 255) / 256, 256>>>(Wv, wh, wl, nw4);
    gemm_mma_x3_kernel<<<ggrid, 256, GEMM_SMEM>>>(xh, xl, wh, wl,
                                                  nullptr, vh, vl, 1.0f);

    // attention writes ctx hi/lo back into xh/xl (x no longer needed)
    attn_mma_kernel<<<dim3(S_LEN / 64, NHEADS, BATCH), 256, AT_SMEM>>>();

    cvt_hilo_kernel<<<(nw4 + 255) / 256, 256>>>(Wo, wh, wl, nw4);
    gemm_mma_x3_kernel<<<ggrid, 256, GEMM_SMEM>>>(xh, xl, wh, wl,
                                                  out, nullptr, nullptr, 1.0f);
}

// round 11
// speedup vs baseline: 3.1958x; 1.1145x over previous
#include <cuda_runtime.h>
#include <cuda_bf16.h>
#include <cuda_fp16.h>
#include <cstdint>

// ---------------------------------------------------------------------------
// MultiHeadSelfAttention  B=2, S=2048, D=2048, H=16, Hd=128, fp32 in/out
//   Q,K GEMMs:  mma.sync bf16 "x3" (hi/lo, 3 passes)       err ~1e-5
//   V,Wo GEMMs: mma.sync fp16 "x2" (A hi/lo, B fp16 single) err ~2.8e-4 each
//   Attention:  bf16x3 flash attention (unchanged from R10)
//   (tcgen05 unavailable: harness builds at virtual arch compute_103.)
// ---------------------------------------------------------------------------

#define S_LEN   2048
#define D_MODEL 2048
#define BATCH   2
#define NHEADS  16
#define HDIM    128
#define MROWS   (BATCH * S_LEN)   // 4096

// ------------------------- scratch (static, allocation-free) ---------------
__device__ __nv_bfloat16 g_xh[(size_t)MROWS * D_MODEL];   // x (bf16 hi)
__device__ __nv_bfloat16 g_xl[(size_t)MROWS * D_MODEL];   // x (bf16 lo)
__device__ __half        g_xh2[(size_t)MROWS * D_MODEL];  // x (fp16 hi)
__device__ __half        g_xl2[(size_t)MROWS * D_MODEL];  // x (fp16 lo)
__device__ __nv_bfloat16 g_wh[(size_t)D_MODEL * D_MODEL]; // Wq/Wk bf16 hi
__device__ __nv_bfloat16 g_wl[(size_t)D_MODEL * D_MODEL]; // Wq/Wk bf16 lo
__device__ __half        g_wf[(size_t)D_MODEL * D_MODEL]; // Wv/Wo fp16
__device__ __nv_bfloat16 g_qh[(size_t)MROWS * D_MODEL];   // pre-scaled 1/sqrt(Hd)
__device__ __nv_bfloat16 g_ql[(size_t)MROWS * D_MODEL];
__device__ __nv_bfloat16 g_kh[(size_t)MROWS * D_MODEL];
__device__ __nv_bfloat16 g_kl[(size_t)MROWS * D_MODEL];
__device__ __nv_bfloat16 g_vh[(size_t)MROWS * D_MODEL];
__device__ __nv_bfloat16 g_vl[(size_t)MROWS * D_MODEL];
__device__ __half        g_ch[(size_t)MROWS * D_MODEL];   // ctx fp16 hi
__device__ __half        g_cl[(size_t)MROWS * D_MODEL];   // ctx fp16 lo

// ------------------------- helpers -----------------------------------------
__device__ __forceinline__ uint32_t smem_u32(const void* p) {
    uint32_t a;
    asm("{ .reg .u64 t; cvta.to.shared.u64 t, %1; cvt.u32.u64 %0, t; }"
        : "=r"(a) : "l"(p));
    return a;
}
#define SMEM_SWIZZLE_128B(off) ((off) ^ (((off) >> 3) & 0x70))

__device__ __forceinline__ void ldsm4(uint32_t* r, uint32_t addr) {
    asm volatile("ldmatrix.sync.aligned.m8n8.x4.shared.b16 {%0,%1,%2,%3}, [%4];"
                 : "=r"(r[0]), "=r"(r[1]), "=r"(r[2]), "=r"(r[3]) : "r"(addr));
}
__device__ __forceinline__ void ldsm4t(uint32_t* r, uint32_t addr) {
    asm volatile("ldmatrix.sync.aligned.m8n8.x4.trans.shared.b16 {%0,%1,%2,%3}, [%4];"
                 : "=r"(r[0]), "=r"(r[1]), "=r"(r[2]), "=r"(r[3]) : "r"(addr));
}
__device__ __forceinline__ void mma16816(float* d, const uint32_t* a, const uint32_t* b) {
    asm volatile(
        "mma.sync.aligned.m16n8k16.row.col.f32.bf16.bf16.f32 "
        "{%0,%1,%2,%3}, {%4,%5,%6,%7}, {%8,%9}, {%0,%1,%2,%3};"
        : "+f"(d[0]), "+f"(d[1]), "+f"(d[2]), "+f"(d[3])
        : "r"(a[0]), "r"(a[1]), "r"(a[2]), "r"(a[3]), "r"(b[0]), "r"(b[1]));
}
__device__ __forceinline__ void mma16816h(float* d, const uint32_t* a, const uint32_t* b) {
    asm volatile(
        "mma.sync.aligned.m16n8k16.row.col.f32.f16.f16.f32 "
        "{%0,%1,%2,%3}, {%4,%5,%6,%7}, {%8,%9}, {%0,%1,%2,%3};"
        : "+f"(d[0]), "+f"(d[1]), "+f"(d[2]), "+f"(d[3])
        : "r"(a[0]), "r"(a[1]), "r"(a[2]), "r"(a[3]), "r"(b[0]), "r"(b[1]));
}
__device__ __forceinline__ void cp_async16(uint32_t sdst, const void* gsrc) {
    asm volatile("cp.async.cg.shared.global [%0], [%1], 16;" :: "r"(sdst), "l"(gsrc));
}
__device__ __forceinline__ uint32_t pack_bf16x2(float a, float b) {
    __nv_bfloat162 v(__float2bfloat16(a), __float2bfloat16(b));
    return *(uint32_t*)&v;
}
__device__ __forceinline__ uint32_t pack_h2(float a, float b) {
    __half2 v(__float2half(a), __float2half(b));
    return *(uint32_t*)&v;
}

// ---------------------------------------------------------------------------
// Conversions
// ---------------------------------------------------------------------------
// x -> bf16 hi/lo AND fp16 hi/lo in one pass (read x once)
__global__ __launch_bounds__(256) void cvt_x_kernel(
    const float* __restrict__ in,
    __nv_bfloat16* __restrict__ bh, __nv_bfloat16* __restrict__ bl,
    __half* __restrict__ hh, __half* __restrict__ hl, int n4)
{
    int i = blockIdx.x * blockDim.x + threadIdx.x;
    if (i >= n4) return;
    float4 v = ((const float4*)in)[i];
    float x[4] = {v.x, v.y, v.z, v.w};
    float b_h[4], b_l[4], h_h[4], h_l[4];
#pragma unroll
    for (int j = 0; j < 4; j++) {
        __nv_bfloat16 bb = __float2bfloat16(x[j]);
        b_h[j] = __bfloat162float(bb);
        b_l[j] = x[j] - b_h[j];
        __half ph = __float2half(x[j]);
        h_h[j] = __half2float(ph);
        h_l[j] = x[j] - h_h[j];
    }
    ((uint32_t*)bh)[2 * i]     = pack_bf16x2(b_h[0], b_h[1]);
    ((uint32_t*)bh)[2 * i + 1] = pack_bf16x2(b_h[2], b_h[3]);
    ((uint32_t*)bl)[2 * i]     = pack_bf16x2(b_l[0], b_l[1]);
    ((uint32_t*)bl)[2 * i + 1] = pack_bf16x2(b_l[2], b_l[3]);
    ((uint32_t*)hh)[2 * i]     = pack_h2(h_h[0], h_h[1]);
    ((uint32_t*)hh)[2 * i + 1] = pack_h2(h_h[2], h_h[3]);
    ((uint32_t*)hl)[2 * i]     = pack_h2(h_l[0], h_l[1]);
    ((uint32_t*)hl)[2 * i + 1] = pack_h2(h_l[2], h_l[3]);
}

// fp32 -> bf16 hi/lo (Wq, Wk)
__global__ __launch_bounds__(256) void cvt_hilo_kernel(
    const float* __restrict__ in, __nv_bfloat16* __restrict__ hi,
    __nv_bfloat16* __restrict__ lo, int n4)
{
    int i = blockIdx.x * blockDim.x + threadIdx.x;
    if (i >= n4) return;
    float4 v = ((const float4*)in)[i];
    float x[4] = {v.x, v.y, v.z, v.w};
    float h[4], l[4];
#pragma unroll
    for (int j = 0; j < 4; j++) {
        __nv_bfloat16 b = __float2bfloat16(x[j]);
        h[j] = __bfloat162float(b);
        l[j] = x[j] - h[j];
    }
    ((uint32_t*)hi)[2 * i]     = pack_bf16x2(h[0], h[1]);
    ((uint32_t*)hi)[2 * i + 1] = pack_bf16x2(h[2], h[3]);
    ((uint32_t*)lo)[2 * i]     = pack_bf16x2(l[0], l[1]);
    ((uint32_t*)lo)[2 * i + 1] = pack_bf16x2(l[2], l[3]);
}

// fp32 -> single fp16 (Wv, Wo)
__global__ __launch_bounds__(256) void cvt_h16_kernel(
    const float* __restrict__ in, __half* __restrict__ out, int n4)
{
    int i = blockIdx.x * blockDim.x + threadIdx.x;
    if (i >= n4) return;
    float4 v = ((const float4*)in)[i];
    ((uint32_t*)out)[2 * i]     = pack_h2(v.x, v.y);
    ((uint32_t*)out)[2 * i + 1] = pack_h2(v.z, v.w);
}

// ---------------------------------------------------------------------------
// bf16x3 GEMM-NT (unchanged from R10, validated).  C = (Ah+Al)(Bh+Bl)^T.
// ---------------------------------------------------------------------------
#define GK        64
#define TILE_B    (128 * GK * 2)
#define STAGE_B   (4 * TILE_B)
#define NSTAGE    3
#define GEMM_SMEM (NSTAGE * STAGE_B)
#define NCHUNK    (D_MODEL / GK)

__global__ __launch_bounds__(256) void gemm_mma_x3_kernel(
    const __nv_bfloat16* __restrict__ Ah, const __nv_bfloat16* __restrict__ Al,
    const __nv_bfloat16* __restrict__ Bh, const __nv_bfloat16* __restrict__ Bl,
    float* __restrict__ Cf, __nv_bfloat16* __restrict__ Ch,
    __nv_bfloat16* __restrict__ Cl, float oscale)
{
    extern __shared__ char smem[];
    const uint32_t smem_base = smem_u32(smem);
    const int tid  = threadIdx.x;
    const int wid  = tid >> 5;
    const int lane = tid & 31;
    const int wm   = wid & 3;
    const int wn   = wid >> 2;
    const int row0 = blockIdx.y * 128;
    const int col0 = blockIdx.x * 128;

    int cr[4], cs[4];
    uint32_t csw[4];
#pragma unroll
    for (int i = 0; i < 4; i++) {
        int idx = tid + i * 256;
        cr[i]  = idx >> 3;
        cs[i]  = idx & 7;
        csw[i] = SMEM_SWIZZLE_128B((uint32_t)(cr[i] * 128 + cs[i] * 16));
    }

    auto copy_stage = [&](int st, int kc) {
        const uint32_t sb = smem_base + st * STAGE_B;
#pragma unroll
        for (int i = 0; i < 4; i++) {
            const size_t aoff = (size_t)(row0 + cr[i]) * D_MODEL + kc * GK + cs[i] * 8;
            const size_t boff = (size_t)(col0 + cr[i]) * D_MODEL + kc * GK + cs[i] * 8;
            cp_async16(sb + 0 * TILE_B + csw[i], Ah + aoff);
            cp_async16(sb + 1 * TILE_B + csw[i], Al + aoff);
            cp_async16(sb + 2 * TILE_B + csw[i], Bh + boff);
            cp_async16(sb + 3 * TILE_B + csw[i], Bl + boff);
        }
    };

    float acc[2][8][4];
#pragma unroll
    for (int mf = 0; mf < 2; mf++)
#pragma unroll
        for (int nf = 0; nf < 8; nf++)
#pragma unroll
            for (int r = 0; r < 4; r++) acc[mf][nf][r] = 0.f;

    const int quad = lane >> 3;
    const int r16  = (lane & 7) | ((quad & 1) << 3);
    const int cbq  = (quad >> 1) << 4;

    copy_stage(0, 0);
    asm volatile("cp.async.commit_group;");
    copy_stage(1, 1);
    asm volatile("cp.async.commit_group;");

    for (int kc = 0; kc < NCHUNK; kc++) {
        if (kc + 2 < NCHUNK) copy_stage((kc + 2) % NSTAGE, kc + 2);
        asm volatile("cp.async.commit_group;");
        asm volatile("cp.async.wait_group 2;");
        __syncthreads();

        const uint32_t sb  = smem_base + (kc % NSTAGE) * STAGE_B;
        const uint32_t sAh = sb + 0 * TILE_B;
        const uint32_t sAl = sb + 1 * TILE_B;
        const uint32_t sBh = sb + 2 * TILE_B;
        const uint32_t sBl = sb + 3 * TILE_B;

#pragma unroll
        for (int ks = 0; ks < 4; ks++) {
            uint32_t ah[2][4], al[2][4], bh[8][2], bl[8][2];
#pragma unroll
            for (int mf = 0; mf < 2; mf++) {
                const int row = wm * 32 + mf * 16 + r16;
                const uint32_t off =
                    SMEM_SWIZZLE_128B((uint32_t)(row * 128 + cbq + ks * 32));
                ldsm4(ah[mf], sAh + off);
                ldsm4(al[mf], sAl + off);
            }
#pragma unroll
            for (int p = 0; p < 4; p++) {
                const int row = wn * 64 + p * 16 + r16;
                const uint32_t off =
                    SMEM_SWIZZLE_128B((uint32_t)(row * 128 + cbq + ks * 32));
                uint32_t q[4];
                ldsm4(q, sBh + off);
                bh[2 * p][0] = q[0]; bh[2 * p][1] = q[2];
                bh[2 * p + 1][0] = q[1]; bh[2 * p + 1][1] = q[3];
                ldsm4(q, sBl + off);
                bl[2 * p][0] = q[0]; bl[2 * p][1] = q[2];
                bl[2 * p + 1][0] = q[1]; bl[2 * p + 1][1] = q[3];
            }
#pragma unroll
            for (int mf = 0; mf < 2; mf++)
#pragma unroll
                for (int nf = 0; nf < 8; nf++) {
                    mma16816(acc[mf][nf], ah[mf], bh[nf]);
                    mma16816(acc[mf][nf], ah[mf], bl[nf]);
                    mma16816(acc[mf][nf], al[mf], bh[nf]);
                }
        }
        __syncthreads();
    }

#pragma unroll
    for (int mf = 0; mf < 2; mf++) {
        const int row = row0 + wm * 32 + mf * 16 + (lane >> 2);
#pragma unroll
        for (int nf = 0; nf < 8; nf++) {
            const int col = col0 + wn * 64 + nf * 8 + (lane & 3) * 2;
            if (Cf) {
                float* p0 = Cf + (size_t)row * D_MODEL + col;
                float* p1 = Cf + (size_t)(row + 8) * D_MODEL + col;
                *(float2*)p0 = make_float2(acc[mf][nf][0], acc[mf][nf][1]);
                *(float2*)p1 = make_float2(acc[mf][nf][2], acc[mf][nf][3]);
            } else {
                float v[4];
#pragma unroll
                for (int r = 0; r < 4; r++) v[r] = acc[mf][nf][r] * oscale;
                float h[4], l[4];
#pragma unroll
                for (int r = 0; r < 4; r++) {
                    h[r] = __bfloat162float(__float2bfloat16(v[r]));
                    l[r] = v[r] - h[r];
                }
                *(uint32_t*)(Ch + (size_t)row * D_MODEL + col) = pack_bf16x2(h[0], h[1]);
                *(uint32_t*)(Ch + (size_t)(row + 8) * D_MODEL + col) = pack_bf16x2(h[2], h[3]);
                *(uint32_t*)(Cl + (size_t)row * D_MODEL + col) = pack_bf16x2(l[0], l[1]);
                *(uint32_t*)(Cl + (size_t)(row + 8) * D_MODEL + col) = pack_bf16x2(l[2], l[3]);
            }
        }
    }
}

// ---------------------------------------------------------------------------
// fp16x2 GEMM-NT:  C = (Ah+Al)[M,K] * fp16(B)[N,K]^T  (2 passes, B single)
// 3 tiles/stage (48KB), 4-stage cp.async pipeline, B fragments reused.
// ---------------------------------------------------------------------------
#define STAGE_B2   (3 * TILE_B)          // 49152
#define NSTAGE2    4
#define GEMM_SMEM2 (NSTAGE2 * STAGE_B2)  // 196608

__global__ __launch_bounds__(256) void gemm_mma_f16x2_kernel(
    const __half* __restrict__ Ah, const __half* __restrict__ Al,
    const __half* __restrict__ B,
    float* __restrict__ Cf, __nv_bfloat16* __restrict__ Ch,
    __nv_bfloat16* __restrict__ Cl, float oscale)
{
    extern __shared__ char smem[];
    const uint32_t smem_base = smem_u32(smem);
    const int tid  = threadIdx.x;
    const int wid  = tid >> 5;
    const int lane = tid & 31;
    const int wm   = wid & 3;
    const int wn   = wid >> 2;
    const int row0 = blockIdx.y * 128;
    const int col0 = blockIdx.x * 128;

    int cr[4], cs[4];
    uint32_t csw[4];
#pragma unroll
    for (int i = 0; i < 4; i++) {
        int idx = tid + i * 256;
        cr[i]  = idx >> 3;
        cs[i]  = idx & 7;
        csw[i] = SMEM_SWIZZLE_128B((uint32_t)(cr[i] * 128 + cs[i] * 16));
    }

    auto copy_stage = [&](int st, int kc) {
        const uint32_t sb = smem_base + st * STAGE_B2;
#pragma unroll
        for (int i = 0; i < 4; i++) {
            const size_t aoff = (size_t)(row0 + cr[i]) * D_MODEL + kc * GK + cs[i] * 8;
            const size_t boff = (size_t)(col0 + cr[i]) * D_MODEL + kc * GK + cs[i] * 8;
            cp_async16(sb + 0 * TILE_B + csw[i], Ah + aoff);
            cp_async16(sb + 1 * TILE_B + csw[i], Al + aoff);
            cp_async16(sb + 2 * TILE_B + csw[i], B + boff);
        }
    };

    float acc[2][8][4];
#pragma unroll
    for (int mf = 0; mf < 2; mf++)
#pragma unroll
        for (int nf = 0; nf < 8; nf++)
#pragma unroll
            for (int r = 0; r < 4; r++) acc[mf][nf][r] = 0.f;

    const int quad = lane >> 3;
    const int r16  = (lane & 7) | ((quad & 1) << 3);
    const int cbq  = (quad >> 1) << 4;

    copy_stage(0, 0);
    asm volatile("cp.async.commit_group;");
    copy_stage(1, 1);
    asm volatile("cp.async.commit_group;");
    copy_stage(2, 2);
    asm volatile("cp.async.commit_group;");

    for (int kc = 0; kc < NCHUNK; kc++) {
        if (kc + 3 < NCHUNK) copy_stage((kc + 3) % NSTAGE2, kc + 3);
        asm volatile("cp.async.commit_group;");
        asm volatile("cp.async.wait_group 3;");
        __syncthreads();

        const uint32_t sb  = smem_base + (kc % NSTAGE2) * STAGE_B2;
        const uint32_t sAh = sb + 0 * TILE_B;
        const uint32_t sAl = sb + 1 * TILE_B;
        const uint32_t sB  = sb + 2 * TILE_B;

#pragma unroll
        for (int ks = 0; ks < 4; ks++) {
            uint32_t ah[2][4], al[2][4], bb[8][2];
#pragma unroll
            for (int mf = 0; mf < 2; mf++) {
                const int row = wm * 32 + mf * 16 + r16;
                const uint32_t off =
                    SMEM_SWIZZLE_128B((uint32_t)(row * 128 + cbq + ks * 32));
                ldsm4(ah[mf], sAh + off);
                ldsm4(al[mf], sAl + off);
            }
#pragma unroll
            for (int p = 0; p < 4; p++) {
                const int row = wn * 64 + p * 16 + r16;
                const uint32_t off =
                    SMEM_SWIZZLE_128B((uint32_t)(row * 128 + cbq + ks * 32));
                uint32_t q[4];
                ldsm4(q, sB + off);
                bb[2 * p][0] = q[0]; bb[2 * p][1] = q[2];
                bb[2 * p + 1][0] = q[1]; bb[2 * p + 1][1] = q[3];
            }
#pragma unroll
            for (int mf = 0; mf < 2; mf++)
#pragma unroll
                for (int nf = 0; nf < 8; nf++) {
                    mma16816h(acc[mf][nf], ah[mf], bb[nf]);
                    mma16816h(acc[mf][nf], al[mf], bb[nf]);
                }
        }
        __syncthreads();
    }

#pragma unroll
    for (int mf = 0; mf < 2; mf++) {
        const int row = row0 + wm * 32 + mf * 16 + (lane >> 2);
#pragma unroll
        for (int nf = 0; nf < 8; nf++) {
            const int col = col0 + wn * 64 + nf * 8 + (lane & 3) * 2;
            if (Cf) {
                float* p0 = Cf + (size_t)row * D_MODEL + col;
                float* p1 = Cf + (size_t)(row + 8) * D_MODEL + col;
                *(float2*)p0 = make_float2(acc[mf][nf][0], acc[mf][nf][1]);
                *(float2*)p1 = make_float2(acc[mf][nf][2], acc[mf][nf][3]);
            } else {
                float v[4], h[4], l[4];
#pragma unroll
                for (int r = 0; r < 4; r++) v[r] = acc[mf][nf][r] * oscale;
#pragma unroll
                for (int r = 0; r < 4; r++) {
                    h[r] = __bfloat162float(__float2bfloat16(v[r]));
                    l[r] = v[r] - h[r];
                }
                *(uint32_t*)(Ch + (size_t)row * D_MODEL + col) = pack_bf16x2(h[0], h[1]);
                *(uint32_t*)(Ch + (size_t)(row + 8) * D_MODEL + col) = pack_bf16x2(h[2], h[3]);
                *(uint32_t*)(Cl + (size_t)row * D_MODEL + col) = pack_bf16x2(l[0], l[1]);
                *(uint32_t*)(Cl + (size_t)(row + 8) * D_MODEL + col) = pack_bf16x2(l[2], l[3]);
            }
        }
    }
}

// ---------------------------------------------------------------------------
// Tensor-core flash attention, bf16x3 (unchanged except ctx epilogue -> fp16)
// ---------------------------------------------------------------------------
#define AT_QH   0
#define AT_QL   16384
#define AT_KST  32768
#define AT_VST  98304
#define AT_SS   163840
#define AT_PH   181248
#define AT_PL   189440
#define AT_AL   197632
#define AT_LR   197888
#define AT_SMEM 198144
#define NKV     (S_LEN / 64)

__device__ __forceinline__ void at_copy_tile(uint32_t dst, const __nv_bfloat16* src,
                                             int tid) {
#pragma unroll
    for (int i = 0; i < 4; i++) {
        int idx = tid + i * 256;
        int c   = idx >> 9;
        int r   = (idx >> 3) & 63;
        int sg  = idx & 7;
        uint32_t so = dst + c * 8192 +
                      SMEM_SWIZZLE_128B((uint32_t)(r * 128 + sg * 16));
        cp_async16(so, src + (size_t)r * D_MODEL + c * 64 + sg * 8);
    }
}

__global__ __launch_bounds__(256) void attn_mma_kernel()
{
    extern __shared__ char smbuf[];
    const uint32_t sb = smem_u32(smbuf);
    const int tid  = threadIdx.x;
    const int wid  = tid >> 5;
    const int lane = tid & 31;
    const int b    = blockIdx.z;
    const int h    = blockIdx.y;
    const int q0   = blockIdx.x * 64;

    const int r16 = (lane & 7) | (((lane >> 3) & 1) << 3);
    const int cbq = ((lane >> 4) & 1) << 4;
    const int wm  = wid & 1;
    const int wn  = wid >> 1;

    const size_t hoff = (size_t)h * HDIM;
    const __nv_bfloat16* Qhg = g_qh + (size_t)(b * S_LEN + q0) * D_MODEL + hoff;
    const __nv_bfloat16* Qlg = g_ql + (size_t)(b * S_LEN + q0) * D_MODEL + hoff;
    const __nv_bfloat16* Khg = g_kh + (size_t)(b * S_LEN) * D_MODEL + hoff;
    const __nv_bfloat16* Klg = g_kl + (size_t)(b * S_LEN) * D_MODEL + hoff;
    const __nv_bfloat16* Vhg = g_vh + (size_t)(b * S_LEN) * D_MODEL + hoff;
    const __nv_bfloat16* Vlg = g_vl + (size_t)(b * S_LEN) * D_MODEL + hoff;

    float* Ssp   = (float*)(smbuf + AT_SS);
    float* alphp = (float*)(smbuf + AT_AL);
    float* lrowp = (float*)(smbuf + AT_LR);

    at_copy_tile(sb + AT_QH, Qhg, tid);
    at_copy_tile(sb + AT_QL, Qlg, tid);
    at_copy_tile(sb + AT_KST,         Khg, tid);
    at_copy_tile(sb + AT_KST + 16384, Klg, tid);
    at_copy_tile(sb + AT_VST,         Vhg, tid);
    at_copy_tile(sb + AT_VST + 16384, Vlg, tid);
    asm volatile("cp.async.commit_group;");

    float m_i = -1e30f, l_i = 0.f;
    float o_acc[2][4][4];
#pragma unroll
    for (int mf = 0; mf < 2; mf++)
#pragma unroll
        for (int nf = 0; nf < 4; nf++)
#pragma unroll
            for (int r = 0; r < 4; r++) o_acc[mf][nf][r] = 0.f;

    const int srow = tid >> 2;
    const int scol = (tid & 3) * 16;

    for (int it = 0; it < NKV; it++) {
        const int st = it & 1;
        asm volatile("cp.async.wait_group 0;");
        __syncthreads();

        float sacc[2][2][4];
#pragma unroll
        for (int mf = 0; mf < 2; mf++)
#pragma unroll
            for (int nf = 0; nf < 2; nf++)
#pragma unroll
                for (int r = 0; r < 4; r++) sacc[mf][nf][r] = 0.f;

        const uint32_t kb_h = sb + AT_KST + st * 32768;
        const uint32_t kb_l = kb_h + 16384;
#pragma unroll
        for (int ks = 0; ks < 8; ks++) {
            const int chunk = ks >> 2;
            const int kbyte = (ks & 3) * 32 + cbq;
            uint32_t ah[2][4], al[2][4];
#pragma unroll
            for (int mf = 0; mf < 2; mf++) {
                const uint32_t off = chunk * 8192 +
                    SMEM_SWIZZLE_128B((uint32_t)((wm * 32 + mf * 16 + r16) * 128 + kbyte));
                ldsm4(ah[mf], sb + AT_QH + off);
                ldsm4(al[mf], sb + AT_QL + off);
            }
            const uint32_t offb = chunk * 8192 +
                SMEM_SWIZZLE_128B((uint32_t)((wn * 16 + r16) * 128 + kbyte));
            uint32_t qh[4], ql[4];
            ldsm4(qh, kb_h + offb);
            ldsm4(ql, kb_l + offb);
            uint32_t bh[2][2] = {{qh[0], qh[2]}, {qh[1], qh[3]}};
            uint32_t bl[2][2] = {{ql[0], ql[2]}, {ql[1], ql[3]}};
#pragma unroll
            for (int mf = 0; mf < 2; mf++)
#pragma unroll
                for (int nf = 0; nf < 2; nf++) {
                    mma16816(sacc[mf][nf], ah[mf], bh[nf]);
                    mma16816(sacc[mf][nf], ah[mf], bl[nf]);
                    mma16816(sacc[mf][nf], al[mf], bh[nf]);
                }
        }

#pragma unroll
        for (int mf = 0; mf < 2; mf++) {
            const int row = wm * 32 + mf * 16 + (lane >> 2);
#pragma unroll
            for (int nf = 0; nf < 2; nf++) {
                const int col = wn * 16 + nf * 8 + (lane & 3) * 2;
                *(float2*)(Ssp + row * 68 + col) =
                    make_float2(sacc[mf][nf][0], sacc[mf][nf][1]);
                *(float2*)(Ssp + (row + 8) * 68 + col) =
                    make_float2(sacc[mf][nf][2], sacc[mf][nf][3]);
            }
        }
        __syncthreads();

        if (it + 1 < NKV) {
            const int ns = (it + 1) & 1;
            const size_t roff = (size_t)((it + 1) * 64) * D_MODEL;
            at_copy_tile(sb + AT_KST + ns * 32768,         Khg + roff, tid);
            at_copy_tile(sb + AT_KST + ns * 32768 + 16384, Klg + roff, tid);
            at_copy_tile(sb + AT_VST + ns * 32768,         Vhg + roff, tid);
            at_copy_tile(sb + AT_VST + ns * 32768 + 16384, Vlg + roff, tid);
            asm volatile("cp.async.commit_group;");
        }

        {
            float sv[16];
#pragma unroll
            for (int u = 0; u < 4; u++)
                *(float4*)(sv + u * 4) = *(float4*)(Ssp + srow * 68 + scol + u * 4);
            float mx = sv[0];
#pragma unroll
            for (int u = 1; u < 16; u++) mx = fmaxf(mx, sv[u]);
            mx = fmaxf(mx, __shfl_xor_sync(0xffffffffu, mx, 1));
            mx = fmaxf(mx, __shfl_xor_sync(0xffffffffu, mx, 2));
            const float mnew  = fmaxf(m_i, mx);
            const float alpha = __expf(m_i - mnew);
            m_i = mnew;
            float sum = 0.f;
            float p[16];
#pragma unroll
            for (int u = 0; u < 16; u++) {
                p[u] = __expf(sv[u] - mnew);
                sum += p[u];
            }
            sum += __shfl_xor_sync(0xffffffffu, sum, 1);
            sum += __shfl_xor_sync(0xffffffffu, sum, 2);
            l_i = l_i * alpha + sum;
#pragma unroll
            for (int u2 = 0; u2 < 8; u2++) {
                const uint32_t off =
                    SMEM_SWIZZLE_128B((uint32_t)(srow * 128 + (scol + u2 * 2) * 2));
                const float p0 = p[u2 * 2], p1 = p[u2 * 2 + 1];
                const __nv_bfloat16 h0 = __float2bfloat16(p0);
                const __nv_bfloat16 h1 = __float2bfloat16(p1);
                *(uint32_t*)(smbuf + AT_PH + off) =
                    pack_bf16x2(__bfloat162float(h0), __bfloat162float(h1));
                *(uint32_t*)(smbuf + AT_PL + off) =
                    pack_bf16x2(p0 - __bfloat162float(h0), p1 - __bfloat162float(h1));
            }
            if ((tid & 3) == 0) alphp[srow] = alpha;
        }
        __syncthreads();

#pragma unroll
        for (int mf = 0; mf < 2; mf++) {
            const float a0 = alphp[wm * 32 + mf * 16 + (lane >> 2)];
            const float a1 = alphp[wm * 32 + mf * 16 + (lane >> 2) + 8];
#pragma unroll
            for (int nf = 0; nf < 4; nf++) {
                o_acc[mf][nf][0] *= a0; o_acc[mf][nf][1] *= a0;
                o_acc[mf][nf][2] *= a1; o_acc[mf][nf][3] *= a1;
            }
        }

        const uint32_t vb_h = sb + AT_VST + st * 32768;
        const uint32_t vb_l = vb_h + 16384;
        const int g  = lane >> 3;
        const int kg = (g & 1) << 3;
        const int ng = (g >> 1) << 3;
#pragma unroll
        for (int kpv = 0; kpv < 4; kpv++) {
            uint32_t aph[2][4], apl[2][4];
#pragma unroll
            for (int mf = 0; mf < 2; mf++) {
                const uint32_t off =
                    SMEM_SWIZZLE_128B((uint32_t)((wm * 32 + mf * 16 + r16) * 128 +
                                                 kpv * 32 + cbq));
                ldsm4(aph[mf], sb + AT_PH + off);
                ldsm4(apl[mf], sb + AT_PL + off);
            }
            uint32_t bvh[4][2], bvl[4][2];
#pragma unroll
            for (int pr = 0; pr < 2; pr++) {
                const int kr = kpv * 16 + kg + (lane & 7);
                const int nc = wn * 32 + pr * 16 + ng;
                const uint32_t off = (uint32_t)(nc >> 6) * 8192 +
                    SMEM_SWIZZLE_128B((uint32_t)(kr * 128 + (nc & 63) * 2));
                uint32_t t4[4];
                ldsm4t(t4, vb_h + off);
                bvh[2 * pr][0] = t4[0]; bvh[2 * pr][1] = t4[1];
                bvh[2 * pr + 1][0] = t4[2]; bvh[2 * pr + 1][1] = t4[3];
                ldsm4t(t4, vb_l + off);
                bvl[2 * pr][0] = t4[0]; bvl[2 * pr][1] = t4[1];
                bvl[2 * pr + 1][0] = t4[2]; bvl[2 * pr + 1][1] = t4[3];
            }
#pragma unroll
            for (int mf = 0; mf < 2; mf++)
#pragma unroll
                for (int nf = 0; nf < 4; nf++) {
                    mma16816(o_acc[mf][nf], aph[mf], bvh[nf]);
                    mma16816(o_acc[mf][nf], aph[mf], bvl[nf]);
                    mma16816(o_acc[mf][nf], apl[mf], bvh[nf]);
                }
        }
    }

    if ((tid & 3) == 0) lrowp[srow] = l_i;
    __syncthreads();
    if (tid < 64) lrowp[tid] = 1.0f / lrowp[tid];
    __syncthreads();

    // ctx epilogue -> fp16 hi/lo (consumed by fp16x2 Wo GEMM)
    __half* Chg = g_ch + (size_t)(b * S_LEN + q0) * D_MODEL + hoff;
    __half* Clg = g_cl + (size_t)(b * S_LEN + q0) * D_MODEL + hoff;
#pragma unroll
    for (int mf = 0; mf < 2; mf++) {
        const int ra  = wm * 32 + mf * 16 + (lane >> 2);
        const float i0 = lrowp[ra];
        const float i1 = lrowp[ra + 8];
#pragma unroll
        for (int nf = 0; nf < 4; nf++) {
            const int col = wn * 32 + nf * 8 + (lane & 3) * 2;
            float v0 = o_acc[mf][nf][0] * i0, v1 = o_acc[mf][nf][1] * i0;
            float v2 = o_acc[mf][nf][2] * i1, v3 = o_acc[mf][nf][3] * i1;
            float h0 = __half2float(__float2half(v0));
            float h1 = __half2float(__float2half(v1));
            float h2 = __half2float(__float2half(v2));
            float h3 = __half2float(__float2half(v3));
            *(uint32_t*)(Chg + (size_t)ra * D_MODEL + col)       = pack_h2(h0, h1);
            *(uint32_t*)(Chg + (size_t)(ra + 8) * D_MODEL + col) = pack_h2(h2, h3);
            *(uint32_t*)(Clg + (size_t)ra * D_MODEL + col)       = pack_h2(v0 - h0, v1 - h1);
            *(uint32_t*)(Clg + (size_t)(ra + 8) * D_MODEL + col) = pack_h2(v2 - h2, v3 - h3);
        }
    }
}

// ---------------------------------------------------------------------------
extern "C" void kernel_launch(void* const* d_in, const int* in_sizes, int n_in,
                              void* d_out, int out_size)
{
    const float* x  = (const float*)d_in[0];
    const float* Wq = (const float*)d_in[1];
    const float* Wk = (const float*)d_in[2];
    const float* Wv = (const float*)d_in[3];
    const float* Wo = (const float*)d_in[4];
    float* out = (float*)d_out;

    __nv_bfloat16 *xh, *xl, *wh, *wl, *qh, *ql, *kh, *kl, *vh, *vl;
    __half *xh2, *xl2, *wf, *ch, *cl;
    cudaGetSymbolAddress((void**)&xh,  g_xh);
    cudaGetSymbolAddress((void**)&xl,  g_xl);
    cudaGetSymbolAddress((void**)&xh2, g_xh2);
    cudaGetSymbolAddress((void**)&xl2, g_xl2);
    cudaGetSymbolAddress((void**)&wh,  g_wh);
    cudaGetSymbolAddress((void**)&wl,  g_wl);
    cudaGetSymbolAddress((void**)&wf,  g_wf);
    cudaGetSymbolAddress((void**)&qh,  g_qh);
    cudaGetSymbolAddress((void**)&ql,  g_ql);
    cudaGetSymbolAddress((void**)&kh,  g_kh);
    cudaGetSymbolAddress((void**)&kl,  g_kl);
    cudaGetSymbolAddress((void**)&vh,  g_vh);
    cudaGetSymbolAddress((void**)&vl,  g_vl);
    cudaGetSymbolAddress((void**)&ch,  g_ch);
    cudaGetSymbolAddress((void**)&cl,  g_cl);

    cudaFuncSetAttribute(gemm_mma_x3_kernel,
                         cudaFuncAttributeMaxDynamicSharedMemorySize, GEMM_SMEM);
    cudaFuncSetAttribute(gemm_mma_f16x2_kernel,
                         cudaFuncAttributeMaxDynamicSharedMemorySize, GEMM_SMEM2);
    cudaFuncSetAttribute(attn_mma_kernel,
                         cudaFuncAttributeMaxDynamicSharedMemorySize, AT_SMEM);

    const int nx4 = MROWS * D_MODEL / 4;
    const int nw4 = D_MODEL * D_MODEL / 4;
    dim3 ggrid(D_MODEL / 128, MROWS / 128);
    const float qscale = 0.08838834764831845f;   // 1/sqrt(128)

    // x -> bf16 pair (Q,K GEMMs) + fp16 pair (V GEMM), one read of x
    cvt_x_kernel<<<(nx4 + 255) / 256, 256>>>(x, xh, xl, xh2, xl2, nx4);

    cvt_hilo_kernel<<<(nw4 + 255) / 256, 256>>>(Wq, wh, wl, nw4);
    gemm_mma_x3_kernel<<<ggrid, 256, GEMM_SMEM>>>(xh, xl, wh, wl,
                                                  nullptr, qh, ql, qscale);
    cvt_hilo_kernel<<<(nw4 + 255) / 256, 256>>>(Wk, wh, wl, nw4);
    gemm_mma_x3_kernel<<<ggrid, 256, GEMM_SMEM>>>(xh, xl, wh, wl,
                                                  nullptr, kh, kl, 1.0f);
    cvt_h16_kernel<<<(nw4 + 255) / 256, 256>>>(Wv, wf, nw4);
    gemm_mma_f16x2_kernel<<<ggrid, 256, GEMM_SMEM2>>>(xh2, xl2, wf,
                                                      nullptr, vh, vl, 1.0f);

    attn_mma_kernel<<<dim3(S_LEN / 64, NHEADS, BATCH), 256, AT_SMEM>>>();

    cvt_h16_kernel<<<(nw4 + 255) / 256, 256>>>(Wo, wf, nw4);
    gemm_mma_f16x2_kernel<<<ggrid, 256, GEMM_SMEM2>>>(ch, cl, wf,
                                                      out, nullptr, nullptr, 1.0f);
}

// round 12
// speedup vs baseline: 4.1471x; 1.2977x over previous
#include <cuda_runtime.h>
#include <cuda_fp16.h>
#include <cstdint>

// ---------------------------------------------------------------------------
// MultiHeadSelfAttention  B=2, S=2048, D=2048, H=16, Hd=128, fp32 in/out
//   Everything on mma.sync fp16 "x2": C = (Ah+Al)*B16 (A exact fp16 pair,
//   B single fp16).  Calibrated err ~2e-4/GEMM -> total ~5e-4 < 1e-3.
//   (tcgen05 unavailable: harness builds at virtual arch compute_103.)
// ---------------------------------------------------------------------------

#define S_LEN   2048
#define D_MODEL 2048
#define BATCH   2
#define NHEADS  16
#define HDIM    128
#define MROWS   (BATCH * S_LEN)   // 4096

// ------------------------- scratch (static, allocation-free) ---------------
__device__ __half g_xh[(size_t)MROWS * D_MODEL];    // x fp16 hi
__device__ __half g_xl[(size_t)MROWS * D_MODEL];    // x fp16 lo
__device__ __half g_wf[(size_t)D_MODEL * D_MODEL];  // current weight fp16
__device__ __half g_qh[(size_t)MROWS * D_MODEL];    // Q hi (pre-scaled 1/sqrt(Hd))
__device__ __half g_ql[(size_t)MROWS * D_MODEL];    // Q lo
__device__ __half g_k16[(size_t)MROWS * D_MODEL];   // K single fp16
__device__ __half g_v16[(size_t)MROWS * D_MODEL];   // V single fp16
__device__ __half g_ch[(size_t)MROWS * D_MODEL];    // ctx fp16 hi
__device__ __half g_cl[(size_t)MROWS * D_MODEL];    // ctx fp16 lo

// ------------------------- helpers -----------------------------------------
__device__ __forceinline__ uint32_t smem_u32(const void* p) {
    uint32_t a;
    asm("{ .reg .u64 t; cvta.to.shared.u64 t, %1; cvt.u32.u64 %0, t; }"
        : "=r"(a) : "l"(p));
    return a;
}
#define SMEM_SWIZZLE_128B(off) ((off) ^ (((off) >> 3) & 0x70))

__device__ __forceinline__ void ldsm4(uint32_t* r, uint32_t addr) {
    asm volatile("ldmatrix.sync.aligned.m8n8.x4.shared.b16 {%0,%1,%2,%3}, [%4];"
                 : "=r"(r[0]), "=r"(r[1]), "=r"(r[2]), "=r"(r[3]) : "r"(addr));
}
__device__ __forceinline__ void ldsm4t(uint32_t* r, uint32_t addr) {
    asm volatile("ldmatrix.sync.aligned.m8n8.x4.trans.shared.b16 {%0,%1,%2,%3}, [%4];"
                 : "=r"(r[0]), "=r"(r[1]), "=r"(r[2]), "=r"(r[3]) : "r"(addr));
}
__device__ __forceinline__ void mma16816h(float* d, const uint32_t* a, const uint32_t* b) {
    asm volatile(
        "mma.sync.aligned.m16n8k16.row.col.f32.f16.f16.f32 "
        "{%0,%1,%2,%3}, {%4,%5,%6,%7}, {%8,%9}, {%0,%1,%2,%3};"
        : "+f"(d[0]), "+f"(d[1]), "+f"(d[2]), "+f"(d[3])
        : "r"(a[0]), "r"(a[1]), "r"(a[2]), "r"(a[3]), "r"(b[0]), "r"(b[1]));
}
__device__ __forceinline__ void cp_async16(uint32_t sdst, const void* gsrc) {
    asm volatile("cp.async.cg.shared.global [%0], [%1], 16;" :: "r"(sdst), "l"(gsrc));
}
__device__ __forceinline__ uint32_t pack_h2(float a, float b) {
    __half2 v(__float2half(a), __float2half(b));
    return *(uint32_t*)&v;
}

// ---------------------------------------------------------------------------
// Conversions
// ---------------------------------------------------------------------------
// x -> fp16 hi/lo
__global__ __launch_bounds__(256) void cvt_x_kernel(
    const float* __restrict__ in, __half* __restrict__ hh,
    __half* __restrict__ hl, int n4)
{
    int i = blockIdx.x * blockDim.x + threadIdx.x;
    if (i >= n4) return;
    float4 v = ((const float4*)in)[i];
    float x[4] = {v.x, v.y, v.z, v.w};
    float h[4], l[4];
#pragma unroll
    for (int j = 0; j < 4; j++) {
        h[j] = __half2float(__float2half(x[j]));
        l[j] = x[j] - h[j];
    }
    ((uint32_t*)hh)[2 * i]     = pack_h2(h[0], h[1]);
    ((uint32_t*)hh)[2 * i + 1] = pack_h2(h[2], h[3]);
    ((uint32_t*)hl)[2 * i]     = pack_h2(l[0], l[1]);
    ((uint32_t*)hl)[2 * i + 1] = pack_h2(l[2], l[3]);
}

// fp32 -> single fp16 (weights)
__global__ __launch_bounds__(256) void cvt_h16_kernel(
    const float* __restrict__ in, __half* __restrict__ out, int n4)
{
    int i = blockIdx.x * blockDim.x + threadIdx.x;
    if (i >= n4) return;
    float4 v = ((const float4*)in)[i];
    ((uint32_t*)out)[2 * i]     = pack_h2(v.x, v.y);
    ((uint32_t*)out)[2 * i + 1] = pack_h2(v.z, v.w);
}

// ---------------------------------------------------------------------------
// fp16x2 GEMM-NT:  C = (Ah+Al)[M,K] * B16[N,K]^T.
// CTA 128x128, 8 warps 4(M)x2(N), BK=64, 4-stage cp.async, SW128 smem.
// Output modes: Cf (fp32) | Hh+Hl (fp16 pair, *oscale) | Hh only (fp16 single).
// ---------------------------------------------------------------------------
#define GK        64
#define TILE_B    (128 * GK * 2)         // 16384
#define STAGE_B2  (3 * TILE_B)           // 49152
#define NSTAGE2   4
#define GEMM_SMEM (NSTAGE2 * STAGE_B2)   // 196608
#define NCHUNK    (D_MODEL / GK)         // 32

__global__ __launch_bounds__(256) void gemm_mma_f16x2_kernel(
    const __half* __restrict__ Ah, const __half* __restrict__ Al,
    const __half* __restrict__ B,
    float* __restrict__ Cf, __half* __restrict__ Hh,
    __half* __restrict__ Hl, float oscale)
{
    extern __shared__ char smem[];
    const uint32_t smem_base = smem_u32(smem);
    const int tid  = threadIdx.x;
    const int wid  = tid >> 5;
    const int lane = tid & 31;
    const int wm   = wid & 3;
    const int wn   = wid >> 2;
    const int row0 = blockIdx.y * 128;
    const int col0 = blockIdx.x * 128;

    int cr[4], cs[4];
    uint32_t csw[4];
#pragma unroll
    for (int i = 0; i < 4; i++) {
        int idx = tid + i * 256;
        cr[i]  = idx >> 3;
        cs[i]  = idx & 7;
        csw[i] = SMEM_SWIZZLE_128B((uint32_t)(cr[i] * 128 + cs[i] * 16));
    }

    auto copy_stage = [&](int st, int kc) {
        const uint32_t sb = smem_base + st * STAGE_B2;
#pragma unroll
        for (int i = 0; i < 4; i++) {
            const size_t aoff = (size_t)(row0 + cr[i]) * D_MODEL + kc * GK + cs[i] * 8;
            const size_t boff = (size_t)(col0 + cr[i]) * D_MODEL + kc * GK + cs[i] * 8;
            cp_async16(sb + 0 * TILE_B + csw[i], Ah + aoff);
            cp_async16(sb + 1 * TILE_B + csw[i], Al + aoff);
            cp_async16(sb + 2 * TILE_B + csw[i], B + boff);
        }
    };

    float acc[2][8][4];
#pragma unroll
    for (int mf = 0; mf < 2; mf++)
#pragma unroll
        for (int nf = 0; nf < 8; nf++)
#pragma unroll
            for (int r = 0; r < 4; r++) acc[mf][nf][r] = 0.f;

    const int quad = lane >> 3;
    const int r16  = (lane & 7) | ((quad & 1) << 3);
    const int cbq  = (quad >> 1) << 4;

    copy_stage(0, 0);
    asm volatile("cp.async.commit_group;");
    copy_stage(1, 1);
    asm volatile("cp.async.commit_group;");
    copy_stage(2, 2);
    asm volatile("cp.async.commit_group;");

    for (int kc = 0; kc < NCHUNK; kc++) {
        if (kc + 3 < NCHUNK) copy_stage((kc + 3) % NSTAGE2, kc + 3);
        asm volatile("cp.async.commit_group;");
        asm volatile("cp.async.wait_group 3;");
        __syncthreads();

        const uint32_t sb  = smem_base + (kc % NSTAGE2) * STAGE_B2;
        const uint32_t sAh = sb + 0 * TILE_B;
        const uint32_t sAl = sb + 1 * TILE_B;
        const uint32_t sB  = sb + 2 * TILE_B;

#pragma unroll
        for (int ks = 0; ks < 4; ks++) {
            uint32_t ah[2][4], al[2][4], bb[8][2];
#pragma unroll
            for (int mf = 0; mf < 2; mf++) {
                const int row = wm * 32 + mf * 16 + r16;
                const uint32_t off =
                    SMEM_SWIZZLE_128B((uint32_t)(row * 128 + cbq + ks * 32));
                ldsm4(ah[mf], sAh + off);
                ldsm4(al[mf], sAl + off);
            }
#pragma unroll
            for (int p = 0; p < 4; p++) {
                const int row = wn * 64 + p * 16 + r16;
                const uint32_t off =
                    SMEM_SWIZZLE_128B((uint32_t)(row * 128 + cbq + ks * 32));
                uint32_t q[4];
                ldsm4(q, sB + off);
                bb[2 * p][0] = q[0]; bb[2 * p][1] = q[2];
                bb[2 * p + 1][0] = q[1]; bb[2 * p + 1][1] = q[3];
            }
#pragma unroll
            for (int mf = 0; mf < 2; mf++)
#pragma unroll
                for (int nf = 0; nf < 8; nf++) {
                    mma16816h(acc[mf][nf], ah[mf], bb[nf]);
                    mma16816h(acc[mf][nf], al[mf], bb[nf]);
                }
        }
        __syncthreads();
    }

#pragma unroll
    for (int mf = 0; mf < 2; mf++) {
        const int row = row0 + wm * 32 + mf * 16 + (lane >> 2);
#pragma unroll
        for (int nf = 0; nf < 8; nf++) {
            const int col = col0 + wn * 64 + nf * 8 + (lane & 3) * 2;
            if (Cf) {
                float* p0 = Cf + (size_t)row * D_MODEL + col;
                float* p1 = Cf + (size_t)(row + 8) * D_MODEL + col;
                *(float2*)p0 = make_float2(acc[mf][nf][0], acc[mf][nf][1]);
                *(float2*)p1 = make_float2(acc[mf][nf][2], acc[mf][nf][3]);
            } else if (Hl) {
                float v[4], h[4], l[4];
#pragma unroll
                for (int r = 0; r < 4; r++) {
                    v[r] = acc[mf][nf][r] * oscale;
                    h[r] = __half2float(__float2half(v[r]));
                    l[r] = v[r] - h[r];
                }
                *(uint32_t*)(Hh + (size_t)row * D_MODEL + col)       = pack_h2(h[0], h[1]);
                *(uint32_t*)(Hh + (size_t)(row + 8) * D_MODEL + col) = pack_h2(h[2], h[3]);
                *(uint32_t*)(Hl + (size_t)row * D_MODEL + col)       = pack_h2(l[0], l[1]);
                *(uint32_t*)(Hl + (size_t)(row + 8) * D_MODEL + col) = pack_h2(l[2], l[3]);
            } else {
                *(uint32_t*)(Hh + (size_t)row * D_MODEL + col) =
                    pack_h2(acc[mf][nf][0], acc[mf][nf][1]);
                *(uint32_t*)(Hh + (size_t)(row + 8) * D_MODEL + col) =
                    pack_h2(acc[mf][nf][2], acc[mf][nf][3]);
            }
        }
    }
}

// ---------------------------------------------------------------------------
// Tensor-core flash attention, fp16x2.
//   S = (Qh+Ql) K16^T  (2 MMAs)        O += (Ph+Pl) V16  (2 MMAs)
// K,V single fp16 (16KB/tile), double-buffered.  Same geometry as R10/R11.
// ---------------------------------------------------------------------------
#define AT_QH   0
#define AT_QL   16384
#define AT_KST  32768            // 2 stages x 16384
#define AT_VST  65536            // 2 stages x 16384
#define AT_SS   98304            // 64 x 68 f32 = 17408
#define AT_PH   115712           // 64 x 64 fp16 = 8192
#define AT_PL   123904
#define AT_AL   132096           // alpha[64]
#define AT_LR   132352           // l[64]
#define AT_SMEM 132608
#define NKV     (S_LEN / 64)     // 32

__device__ __forceinline__ void at_copy_tile(uint32_t dst, const __half* src,
                                             int tid) {
#pragma unroll
    for (int i = 0; i < 4; i++) {
        int idx = tid + i * 256;
        int c   = idx >> 9;
        int r   = (idx >> 3) & 63;
        int sg  = idx & 7;
        uint32_t so = dst + c * 8192 +
                      SMEM_SWIZZLE_128B((uint32_t)(r * 128 + sg * 16));
        cp_async16(so, src + (size_t)r * D_MODEL + c * 64 + sg * 8);
    }
}

__global__ __launch_bounds__(256) void attn_mma_kernel()
{
    extern __shared__ char smbuf[];
    const uint32_t sb = smem_u32(smbuf);
    const int tid  = threadIdx.x;
    const int wid  = tid >> 5;
    const int lane = tid & 31;
    const int b    = blockIdx.z;
    const int h    = blockIdx.y;
    const int q0   = blockIdx.x * 64;

    const int r16 = (lane & 7) | (((lane >> 3) & 1) << 3);
    const int cbq = ((lane >> 4) & 1) << 4;
    const int wm  = wid & 1;
    const int wn  = wid >> 1;

    const size_t hoff = (size_t)h * HDIM;
    const __half* Qhg = g_qh  + (size_t)(b * S_LEN + q0) * D_MODEL + hoff;
    const __half* Qlg = g_ql  + (size_t)(b * S_LEN + q0) * D_MODEL + hoff;
    const __half* Kg  = g_k16 + (size_t)(b * S_LEN) * D_MODEL + hoff;
    const __half* Vg  = g_v16 + (size_t)(b * S_LEN) * D_MODEL + hoff;

    float* Ssp   = (float*)(smbuf + AT_SS);
    float* alphp = (float*)(smbuf + AT_AL);
    float* lrowp = (float*)(smbuf + AT_LR);

    at_copy_tile(sb + AT_QH, Qhg, tid);
    at_copy_tile(sb + AT_QL, Qlg, tid);
    at_copy_tile(sb + AT_KST, Kg, tid);
    at_copy_tile(sb + AT_VST, Vg, tid);
    asm volatile("cp.async.commit_group;");

    float m_i = -1e30f, l_i = 0.f;
    float o_acc[2][4][4];
#pragma unroll
    for (int mf = 0; mf < 2; mf++)
#pragma unroll
        for (int nf = 0; nf < 4; nf++)
#pragma unroll
            for (int r = 0; r < 4; r++) o_acc[mf][nf][r] = 0.f;

    const int srow = tid >> 2;
    const int scol = (tid & 3) * 16;

    for (int it = 0; it < NKV; it++) {
        const int st = it & 1;
        asm volatile("cp.async.wait_group 0;");
        __syncthreads();

        // ---- S = (Qh+Ql) K16^T ----
        float sacc[2][2][4];
#pragma unroll
        for (int mf = 0; mf < 2; mf++)
#pragma unroll
            for (int nf = 0; nf < 2; nf++)
#pragma unroll
                for (int r = 0; r < 4; r++) sacc[mf][nf][r] = 0.f;

        const uint32_t kb = sb + AT_KST + st * 16384;
#pragma unroll
        for (int ks = 0; ks < 8; ks++) {
            const int chunk = ks >> 2;
            const int kbyte = (ks & 3) * 32 + cbq;
            uint32_t ah[2][4], al[2][4];
#pragma unroll
            for (int mf = 0; mf < 2; mf++) {
                const uint32_t off = chunk * 8192 +
                    SMEM_SWIZZLE_128B((uint32_t)((wm * 32 + mf * 16 + r16) * 128 + kbyte));
                ldsm4(ah[mf], sb + AT_QH + off);
                ldsm4(al[mf], sb + AT_QL + off);
            }
            const uint32_t offb = chunk * 8192 +
                SMEM_SWIZZLE_128B((uint32_t)((wn * 16 + r16) * 128 + kbyte));
            uint32_t q[4];
            ldsm4(q, kb + offb);
            uint32_t bb[2][2] = {{q[0], q[2]}, {q[1], q[3]}};
#pragma unroll
            for (int mf = 0; mf < 2; mf++)
#pragma unroll
                for (int nf = 0; nf < 2; nf++) {
                    mma16816h(sacc[mf][nf], ah[mf], bb[nf]);
                    mma16816h(sacc[mf][nf], al[mf], bb[nf]);
                }
        }

#pragma unroll
        for (int mf = 0; mf < 2; mf++) {
            const int row = wm * 32 + mf * 16 + (lane >> 2);
#pragma unroll
            for (int nf = 0; nf < 2; nf++) {
                const int col = wn * 16 + nf * 8 + (lane & 3) * 2;
                *(float2*)(Ssp + row * 68 + col) =
                    make_float2(sacc[mf][nf][0], sacc[mf][nf][1]);
                *(float2*)(Ssp + (row + 8) * 68 + col) =
                    make_float2(sacc[mf][nf][2], sacc[mf][nf][3]);
            }
        }
        __syncthreads();

        // ---- prefetch next K/V stage ----
        if (it + 1 < NKV) {
            const int ns = (it + 1) & 1;
            const size_t roff = (size_t)((it + 1) * 64) * D_MODEL;
            at_copy_tile(sb + AT_KST + ns * 16384, Kg + roff, tid);
            at_copy_tile(sb + AT_VST + ns * 16384, Vg + roff, tid);
            asm volatile("cp.async.commit_group;");
        }

        // ---- online softmax ----
        {
            float sv[16];
#pragma unroll
            for (int u = 0; u < 4; u++)
                *(float4*)(sv + u * 4) = *(float4*)(Ssp + srow * 68 + scol + u * 4);
            float mx = sv[0];
#pragma unroll
            for (int u = 1; u < 16; u++) mx = fmaxf(mx, sv[u]);
            mx = fmaxf(mx, __shfl_xor_sync(0xffffffffu, mx, 1));
            mx = fmaxf(mx, __shfl_xor_sync(0xffffffffu, mx, 2));
            const float mnew  = fmaxf(m_i, mx);
            const float alpha = __expf(m_i - mnew);
            m_i = mnew;
            float sum = 0.f;
            float p[16];
#pragma unroll
            for (int u = 0; u < 16; u++) {
                p[u] = __expf(sv[u] - mnew);
                sum += p[u];
            }
            sum += __shfl_xor_sync(0xffffffffu, sum, 1);
            sum += __shfl_xor_sync(0xffffffffu, sum, 2);
            l_i = l_i * alpha + sum;
            // write P hi/lo fp16 (K-major 64x64, SW128)
#pragma unroll
            for (int u2 = 0; u2 < 8; u2++) {
                const uint32_t off =
                    SMEM_SWIZZLE_128B((uint32_t)(srow * 128 + (scol + u2 * 2) * 2));
                const float p0 = p[u2 * 2], p1 = p[u2 * 2 + 1];
                const float h0 = __half2float(__float2half(p0));
                const float h1 = __half2float(__float2half(p1));
                *(uint32_t*)(smbuf + AT_PH + off) = pack_h2(h0, h1);
                *(uint32_t*)(smbuf + AT_PL + off) = pack_h2(p0 - h0, p1 - h1);
            }
            if ((tid & 3) == 0) alphp[srow] = alpha;
        }
        __syncthreads();

        // ---- rescale O ----
#pragma unroll
        for (int mf = 0; mf < 2; mf++) {
            const float a0 = alphp[wm * 32 + mf * 16 + (lane >> 2)];
            const float a1 = alphp[wm * 32 + mf * 16 + (lane >> 2) + 8];
#pragma unroll
            for (int nf = 0; nf < 4; nf++) {
                o_acc[mf][nf][0] *= a0; o_acc[mf][nf][1] *= a0;
                o_acc[mf][nf][2] *= a1; o_acc[mf][nf][3] *= a1;
            }
        }

        // ---- O += (Ph+Pl) V16 ----
        const uint32_t vb = sb + AT_VST + st * 16384;
        const int g  = lane >> 3;
        const int kg = (g & 1) << 3;
        const int ng = (g >> 1) << 3;
#pragma unroll
        for (int kpv = 0; kpv < 4; kpv++) {
            uint32_t aph[2][4], apl[2][4];
#pragma unroll
            for (int mf = 0; mf < 2; mf++) {
                const uint32_t off =
                    SMEM_SWIZZLE_128B((uint32_t)((wm * 32 + mf * 16 + r16) * 128 +
                                                 kpv * 32 + cbq));
                ldsm4(aph[mf], sb + AT_PH + off);
                ldsm4(apl[mf], sb + AT_PL + off);
            }
            uint32_t bv[4][2];
#pragma unroll
            for (int pr = 0; pr < 2; pr++) {
                const int kr = kpv * 16 + kg + (lane & 7);
                const int nc = wn * 32 + pr * 16 + ng;
                const uint32_t off = (uint32_t)(nc >> 6) * 8192 +
                    SMEM_SWIZZLE_128B((uint32_t)(kr * 128 + (nc & 63) * 2));
                uint32_t t4[4];
                ldsm4t(t4, vb + off);
                bv[2 * pr][0] = t4[0]; bv[2 * pr][1] = t4[1];
                bv[2 * pr + 1][0] = t4[2]; bv[2 * pr + 1][1] = t4[3];
            }
#pragma unroll
            for (int mf = 0; mf < 2; mf++)
#pragma unroll
                for (int nf = 0; nf < 4; nf++) {
                    mma16816h(o_acc[mf][nf], aph[mf], bv[nf]);
                    mma16816h(o_acc[mf][nf], apl[mf], bv[nf]);
                }
        }
    }

    // ---- epilogue ----
    if ((tid & 3) == 0) lrowp[srow] = l_i;
    __syncthreads();
    if (tid < 64) lrowp[tid] = 1.0f / lrowp[tid];
    __syncthreads();

    __half* Chg = g_ch + (size_t)(b * S_LEN + q0) * D_MODEL + hoff;
    __half* Clg = g_cl + (size_t)(b * S_LEN + q0) * D_MODEL + hoff;
#pragma unroll
    for (int mf = 0; mf < 2; mf++) {
        const int ra  = wm * 32 + mf * 16 + (lane >> 2);
        const float i0 = lrowp[ra];
        const float i1 = lrowp[ra + 8];
#pragma unroll
        for (int nf = 0; nf < 4; nf++) {
            const int col = wn * 32 + nf * 8 + (lane & 3) * 2;
            float v0 = o_acc[mf][nf][0] * i0, v1 = o_acc[mf][nf][1] * i0;
            float v2 = o_acc[mf][nf][2] * i1, v3 = o_acc[mf][nf][3] * i1;
            float h0 = __half2float(__float2half(v0));
            float h1 = __half2float(__float2half(v1));
            float h2 = __half2float(__float2half(v2));
            float h3 = __half2float(__float2half(v3));
            *(uint32_t*)(Chg + (size_t)ra * D_MODEL + col)       = pack_h2(h0, h1);
            *(uint32_t*)(Chg + (size_t)(ra + 8) * D_MODEL + col) = pack_h2(h2, h3);
            *(uint32_t*)(Clg + (size_t)ra * D_MODEL + col)       = pack_h2(v0 - h0, v1 - h1);
            *(uint32_t*)(Clg + (size_t)(ra + 8) * D_MODEL + col) = pack_h2(v2 - h2, v3 - h3);
        }
    }
}

// ---------------------------------------------------------------------------
extern "C" void kernel_launch(void* const* d_in, const int* in_sizes, int n_in,
                              void* d_out, int out_size)
{
    const float* x  = (const float*)d_in[0];
    const float* Wq = (const float*)d_in[1];
    const float* Wk = (const float*)d_in[2];
    const float* Wv = (const float*)d_in[3];
    const float* Wo = (const float*)d_in[4];
    float* out = (float*)d_out;

    __half *xh, *xl, *wf, *qh, *ql, *k16, *v16, *ch, *cl;
    cudaGetSymbolAddress((void**)&xh,  g_xh);
    cudaGetSymbolAddress((void**)&xl,  g_xl);
    cudaGetSymbolAddress((void**)&wf,  g_wf);
    cudaGetSymbolAddress((void**)&qh,  g_qh);
    cudaGetSymbolAddress((void**)&ql,  g_ql);
    cudaGetSymbolAddress((void**)&k16, g_k16);
    cudaGetSymbolAddress((void**)&v16, g_v16);
    cudaGetSymbolAddress((void**)&ch,  g_ch);
    cudaGetSymbolAddress((void**)&cl,  g_cl);

    cudaFuncSetAttribute(gemm_mma_f16x2_kernel,
                         cudaFuncAttributeMaxDynamicSharedMemorySize, GEMM_SMEM);
    cudaFuncSetAttribute(attn_mma_kernel,
                         cudaFuncAttributeMaxDynamicSharedMemorySize, AT_SMEM);

    const int nx4 = MROWS * D_MODEL / 4;
    const int nw4 = D_MODEL * D_MODEL / 4;
    dim3 ggrid(D_MODEL / 128, MROWS / 128);
    const float qscale = 0.08838834764831845f;   // 1/sqrt(128)

    cvt_x_kernel<<<(nx4 + 255) / 256, 256>>>(x, xh, xl, nx4);

    cvt_h16_kernel<<<(nw4 + 255) / 256, 256>>>(Wq, wf, nw4);
    gemm_mma_f16x2_kernel<<<ggrid, 256, GEMM_SMEM>>>(xh, xl, wf,
                                                     nullptr, qh, ql, qscale);
    cvt_h16_kernel<<<(nw4 + 255) / 256, 256>>>(Wk, wf, nw4);
    gemm_mma_f16x2_kernel<<<ggrid, 256, GEMM_SMEM>>>(xh, xl, wf,
                                                     nullptr, k16, nullptr, 1.0f);
    cvt_h16_kernel<<<(nw4 + 255) / 256, 256>>>(Wv, wf, nw4);
    gemm_mma_f16x2_kernel<<<ggrid, 256, GEMM_SMEM>>>(xh, xl, wf,
                                                     nullptr, v16, nullptr, 1.0f);

    attn_mma_kernel<<<dim3(S_LEN / 64, NHEADS, BATCH), 256, AT_SMEM>>>();

    cvt_h16_kernel<<<(nw4 + 255) / 256, 256>>>(Wo, wf, nw4);
    gemm_mma_f16x2_kernel<<<ggrid, 256, GEMM_SMEM>>>(ch, cl, wf,
                                                     out, nullptr, nullptr, 1.0f);
}

// round 14
// speedup vs baseline: 4.9808x; 1.2010x over previous
#include <cuda_runtime.h>
#include <cuda_fp16.h>
#include <cstdint>

// ---------------------------------------------------------------------------
// MultiHeadSelfAttention  B=2, S=2048, D=2048, H=16, Hd=128, fp32 in/out
//   Q,K GEMMs: fp16 "x2" (x exact fp16 pair * W fp16)     ~2e-4 each
//   V,Wo GEMMs: pure fp16 1-pass (linear error paths)      ~1.4e-4 each
//   Attention: fp16x2 flash attention (Q pair, K/V single, P pair)
//   Calibrated total rel_err ~5.3e-4 < 1e-3.
//   (tcgen05 unavailable: harness builds at virtual arch compute_103.)
// ---------------------------------------------------------------------------

#define S_LEN   2048
#define D_MODEL 2048
#define BATCH   2
#define NHEADS  16
#define HDIM    128
#define MROWS   (BATCH * S_LEN)   // 4096

// ------------------------- scratch (static, allocation-free) ---------------
__device__ __half g_xh[(size_t)MROWS * D_MODEL];     // x fp16 hi
__device__ __half g_xl[(size_t)MROWS * D_MODEL];     // x fp16 lo
__device__ __half g_wq16[(size_t)D_MODEL * D_MODEL];
__device__ __half g_wk16[(size_t)D_MODEL * D_MODEL];
__device__ __half g_wv16[(size_t)D_MODEL * D_MODEL];
__device__ __half g_wo16[(size_t)D_MODEL * D_MODEL];
__device__ __half g_qh[(size_t)MROWS * D_MODEL];     // Q hi (pre-scaled 1/sqrt(Hd))
__device__ __half g_ql[(size_t)MROWS * D_MODEL];     // Q lo
__device__ __half g_k16[(size_t)MROWS * D_MODEL];    // K single fp16
__device__ __half g_v16[(size_t)MROWS * D_MODEL];    // V single fp16
__device__ __half g_ch[(size_t)MROWS * D_MODEL];     // ctx single fp16

// ------------------------- helpers -----------------------------------------
__device__ __forceinline__ uint32_t smem_u32(const void* p) {
    uint32_t a;
    asm("{ .reg .u64 t; cvta.to.shared.u64 t, %1; cvt.u32.u64 %0, t; }"
        : "=r"(a) : "l"(p));
    return a;
}
#define SMEM_SWIZZLE_128B(off) ((off) ^ (((off) >> 3) & 0x70))

__device__ __forceinline__ void ldsm4(uint32_t* r, uint32_t addr) {
    asm volatile("ldmatrix.sync.aligned.m8n8.x4.shared.b16 {%0,%1,%2,%3}, [%4];"
                 : "=r"(r[0]), "=r"(r[1]), "=r"(r[2]), "=r"(r[3]) : "r"(addr));
}
__device__ __forceinline__ void ldsm4t(uint32_t* r, uint32_t addr) {
    asm volatile("ldmatrix.sync.aligned.m8n8.x4.trans.shared.b16 {%0,%1,%2,%3}, [%4];"
                 : "=r"(r[0]), "=r"(r[1]), "=r"(r[2]), "=r"(r[3]) : "r"(addr));
}
__device__ __forceinline__ void mma16816h(float* d, const uint32_t* a, const uint32_t* b) {
    asm volatile(
        "mma.sync.aligned.m16n8k16.row.col.f32.f16.f16.f32 "
        "{%0,%1,%2,%3}, {%4,%5,%6,%7}, {%8,%9}, {%0,%1,%2,%3};"
        : "+f"(d[0]), "+f"(d[1]), "+f"(d[2]), "+f"(d[3])
        : "r"(a[0]), "r"(a[1]), "r"(a[2]), "r"(a[3]), "r"(b[0]), "r"(b[1]));
}
__device__ __forceinline__ void cp_async16(uint32_t sdst, const void* gsrc) {
    asm volatile("cp.async.cg.shared.global [%0], [%1], 16;" :: "r"(sdst), "l"(gsrc));
}
__device__ __forceinline__ uint32_t pack_h2(float a, float b) {
    __half2 v(__float2half(a), __float2half(b));
    return *(uint32_t*)&v;
}

// ---------------------------------------------------------------------------
// Conversions
// ---------------------------------------------------------------------------
// x -> fp16 hi/lo
__global__ __launch_bounds__(256) void cvt_x_kernel(
    const float* __restrict__ in, __half* __restrict__ hh,
    __half* __restrict__ hl, int n4)
{
    int i = blockIdx.x * blockDim.x + threadIdx.x;
    if (i >= n4) return;
    float4 v = ((const float4*)in)[i];
    float x[4] = {v.x, v.y, v.z, v.w};
    float h[4], l[4];
#pragma unroll
    for (int j = 0; j < 4; j++) {
        h[j] = __half2float(__float2half(x[j]));
        l[j] = x[j] - h[j];
    }
    ((uint32_t*)hh)[2 * i]     = pack_h2(h[0], h[1]);
    ((uint32_t*)hh)[2 * i + 1] = pack_h2(h[2], h[3]);
    ((uint32_t*)hl)[2 * i]     = pack_h2(l[0], l[1]);
    ((uint32_t*)hl)[2 * i + 1] = pack_h2(l[2], l[3]);
}

// all 4 weights -> fp16 in one launch (n4 elements*4 each, n4 % 256·? ok)
__global__ __launch_bounds__(256) void cvt_w4_kernel(
    const float* __restrict__ a0, const float* __restrict__ a1,
    const float* __restrict__ a2, const float* __restrict__ a3,
    __half* __restrict__ o0, __half* __restrict__ o1,
    __half* __restrict__ o2, __half* __restrict__ o3, int n4)
{
    int idx = blockIdx.x * blockDim.x + threadIdx.x;
    int w = idx / n4;
    int i = idx - w * n4;
    if (w >= 4) return;
    const float* src = (w == 0) ? a0 : (w == 1) ? a1 : (w == 2) ? a2 : a3;
    __half* dst      = (w == 0) ? o0 : (w == 1) ? o1 : (w == 2) ? o2 : o3;
    float4 v = ((const float4*)src)[i];
    ((uint32_t*)dst)[2 * i]     = pack_h2(v.x, v.y);
    ((uint32_t*)dst)[2 * i + 1] = pack_h2(v.z, v.w);
}

// ---------------------------------------------------------------------------
// Common GEMM geometry
// ---------------------------------------------------------------------------
#define GK        64
#define TILE_B    (128 * GK * 2)         // 16384
#define NCHUNK    (D_MODEL / GK)         // 32

// ---------------------------------------------------------------------------
// fp16x2 GEMM-NT:  C = (Ah+Al)[M,K] * B16[N,K]^T.  (Q, K projections)
// 3 tiles/stage, 4-stage cp.async.  Output: fp16 pair (*oscale) or fp16 single.
// ---------------------------------------------------------------------------
#define STAGE_B2   (3 * TILE_B)          // 49152
#define NSTAGE2    4
#define GEMM_SMEM2 (NSTAGE2 * STAGE_B2)  // 196608

__global__ __launch_bounds__(256) void gemm_mma_f16x2_kernel(
    const __half* __restrict__ Ah, const __half* __restrict__ Al,
    const __half* __restrict__ B,
    __half* __restrict__ Hh, __half* __restrict__ Hl, float oscale)
{
    extern __shared__ char smem[];
    const uint32_t smem_base = smem_u32(smem);
    const int tid  = threadIdx.x;
    const int wid  = tid >> 5;
    const int lane = tid & 31;
    const int wm   = wid & 3;
    const int wn   = wid >> 2;
    const int row0 = blockIdx.y * 128;
    const int col0 = blockIdx.x * 128;

    int cr[4], cs[4];
    uint32_t csw[4];
#pragma unroll
    for (int i = 0; i < 4; i++) {
        int idx = tid + i * 256;
        cr[i]  = idx >> 3;
        cs[i]  = idx & 7;
        csw[i] = SMEM_SWIZZLE_128B((uint32_t)(cr[i] * 128 + cs[i] * 16));
    }

    auto copy_stage = [&](int st, int kc) {
        const uint32_t sb = smem_base + st * STAGE_B2;
#pragma unroll
        for (int i = 0; i < 4; i++) {
            const size_t aoff = (size_t)(row0 + cr[i]) * D_MODEL + kc * GK + cs[i] * 8;
            const size_t boff = (size_t)(col0 + cr[i]) * D_MODEL + kc * GK + cs[i] * 8;
            cp_async16(sb + 0 * TILE_B + csw[i], Ah + aoff);
            cp_async16(sb + 1 * TILE_B + csw[i], Al + aoff);
            cp_async16(sb + 2 * TILE_B + csw[i], B + boff);
        }
    };

    float acc[2][8][4];
#pragma unroll
    for (int mf = 0; mf < 2; mf++)
#pragma unroll
        for (int nf = 0; nf < 8; nf++)
#pragma unroll
            for (int r = 0; r < 4; r++) acc[mf][nf][r] = 0.f;

    const int quad = lane >> 3;
    const int r16  = (lane & 7) | ((quad & 1) << 3);
    const int cbq  = (quad >> 1) << 4;

    copy_stage(0, 0);
    asm volatile("cp.async.commit_group;");
    copy_stage(1, 1);
    asm volatile("cp.async.commit_group;");
    copy_stage(2, 2);
    asm volatile("cp.async.commit_group;");

    for (int kc = 0; kc < NCHUNK; kc++) {
        if (kc + 3 < NCHUNK) copy_stage((kc + 3) % NSTAGE2, kc + 3);
        asm volatile("cp.async.commit_group;");
        asm volatile("cp.async.wait_group 3;");
        __syncthreads();

        const uint32_t sb  = smem_base + (kc % NSTAGE2) * STAGE_B2;
        const uint32_t sAh = sb + 0 * TILE_B;
        const uint32_t sAl = sb + 1 * TILE_B;
        const uint32_t sB  = sb + 2 * TILE_B;

#pragma unroll
        for (int ks = 0; ks < 4; ks++) {
            uint32_t ah[2][4], al[2][4], bb[8][2];
#pragma unroll
            for (int mf = 0; mf < 2; mf++) {
                const int row = wm * 32 + mf * 16 + r16;
                const uint32_t off =
                    SMEM_SWIZZLE_128B((uint32_t)(row * 128 + cbq + ks * 32));
                ldsm4(ah[mf], sAh + off);
                ldsm4(al[mf], sAl + off);
            }
#pragma unroll
            for (int p = 0; p < 4; p++) {
                const int row = wn * 64 + p * 16 + r16;
                const uint32_t off =
                    SMEM_SWIZZLE_128B((uint32_t)(row * 128 + cbq + ks * 32));
                uint32_t q[4];
                ldsm4(q, sB + off);
                bb[2 * p][0] = q[0]; bb[2 * p][1] = q[2];
                bb[2 * p + 1][0] = q[1]; bb[2 * p + 1][1] = q[3];
            }
#pragma unroll
            for (int mf = 0; mf < 2; mf++)
#pragma unroll
                for (int nf = 0; nf < 8; nf++) {
                    mma16816h(acc[mf][nf], ah[mf], bb[nf]);
                    mma16816h(acc[mf][nf], al[mf], bb[nf]);
                }
        }
        __syncthreads();
    }

#pragma unroll
    for (int mf = 0; mf < 2; mf++) {
        const int row = row0 + wm * 32 + mf * 16 + (lane >> 2);
#pragma unroll
        for (int nf = 0; nf < 8; nf++) {
            const int col = col0 + wn * 64 + nf * 8 + (lane & 3) * 2;
            if (Hl) {
                float v[4], h[4], l[4];
#pragma unroll
                for (int r = 0; r < 4; r++) {
                    v[r] = acc[mf][nf][r] * oscale;
                    h[r] = __half2float(__float2half(v[r]));
                    l[r] = v[r] - h[r];
                }
                *(uint32_t*)(Hh + (size_t)row * D_MODEL + col)       = pack_h2(h[0], h[1]);
                *(uint32_t*)(Hh + (size_t)(row + 8) * D_MODEL + col) = pack_h2(h[2], h[3]);
                *(uint32_t*)(Hl + (size_t)row * D_MODEL + col)       = pack_h2(l[0], l[1]);
                *(uint32_t*)(Hl + (size_t)(row + 8) * D_MODEL + col) = pack_h2(l[2], l[3]);
            } else {
                *(uint32_t*)(Hh + (size_t)row * D_MODEL + col) =
                    pack_h2(acc[mf][nf][0], acc[mf][nf][1]);
                *(uint32_t*)(Hh + (size_t)(row + 8) * D_MODEL + col) =
                    pack_h2(acc[mf][nf][2], acc[mf][nf][3]);
            }
        }
    }
}

// ---------------------------------------------------------------------------
// fp16 1-pass GEMM-NT:  C = A16[M,K] * B16[N,K]^T.  (V, Wo)
// 2 tiles/stage (32KB), 3-stage pipeline -> 96KB smem (2 CTAs/SM possible).
// Output: fp32 (Cf) or fp16 single (Hh).
// ---------------------------------------------------------------------------
#define STAGE_B1   (2 * TILE_B)          // 32768
#define NSTAGE1    3
#define GEMM_SMEM1 (NSTAGE1 * STAGE_B1)  // 98304

__global__ __launch_bounds__(256) void gemm_mma_f16x1_kernel(
    const __half* __restrict__ A, const __half* __restrict__ B,
    float* __restrict__ Cf, __half* __restrict__ Hh)
{
    extern __shared__ char smem[];
    const uint32_t smem_base = smem_u32(smem);
    const int tid  = threadIdx.x;
    const int wid  = tid >> 5;
    const int lane = tid & 31;
    const int wm   = wid & 3;
    const int wn   = wid >> 2;
    const int row0 = blockIdx.y * 128;
    const int col0 = blockIdx.x * 128;

    int cr[4], cs[4];
    uint32_t csw[4];
#pragma unroll
    for (int i = 0; i < 4; i++) {
        int idx = tid + i * 256;
        cr[i]  = idx >> 3;
        cs[i]  = idx & 7;
        csw[i] = SMEM_SWIZZLE_128B((uint32_t)(cr[i] * 128 + cs[i] * 16));
    }

    auto copy_stage = [&](int st, int kc) {
        const uint32_t sb = smem_base + st * STAGE_B1;
#pragma unroll
        for (int i = 0; i < 4; i++) {
            const size_t aoff = (size_t)(row0 + cr[i]) * D_MODEL + kc * GK + cs[i] * 8;
            const size_t boff = (size_t)(col0 + cr[i]) * D_MODEL + kc * GK + cs[i] * 8;
            cp_async16(sb + 0 * TILE_B + csw[i], A + aoff);
            cp_async16(sb + 1 * TILE_B + csw[i], B + boff);
        }
    };

    float acc[2][8][4];
#pragma unroll
    for (int mf = 0; mf < 2; mf++)
#pragma unroll
        for (int nf = 0; nf < 8; nf++)
#pragma unroll
            for (int r = 0; r < 4; r++) acc[mf][nf][r] = 0.f;

    const int quad = lane >> 3;
    const int r16  = (lane & 7) | ((quad & 1) << 3);
    const int cbq  = (quad >> 1) << 4;

    copy_stage(0, 0);
    asm volatile("cp.async.commit_group;");
    copy_stage(1, 1);
    asm volatile("cp.async.commit_group;");

    for (int kc = 0; kc < NCHUNK; kc++) {
        if (kc + 2 < NCHUNK) copy_stage((kc + 2) % NSTAGE1, kc + 2);
        asm volatile("cp.async.commit_group;");
        asm volatile("cp.async.wait_group 2;");
        __syncthreads();

        const uint32_t sb = smem_base + (kc % NSTAGE1) * STAGE_B1;
        const uint32_t sA = sb + 0 * TILE_B;
        const uint32_t sB = sb + 1 * TILE_B;

#pragma unroll
        for (int ks = 0; ks < 4; ks++) {
            uint32_t aa[2][4], bb[8][2];
#pragma unroll
            for (int mf = 0; mf < 2; mf++) {
                const int row = wm * 32 + mf * 16 + r16;
                const uint32_t off =
                    SMEM_SWIZZLE_128B((uint32_t)(row * 128 + cbq + ks * 32));
                ldsm4(aa[mf], sA + off);
            }
#pragma unroll
            for (int p = 0; p < 4; p++) {
                const int row = wn * 64 + p * 16 + r16;
                const uint32_t off =
                    SMEM_SWIZZLE_128B((uint32_t)(row * 128 + cbq + ks * 32));
                uint32_t q[4];
                ldsm4(q, sB + off);
                bb[2 * p][0] = q[0]; bb[2 * p][1] = q[2];
                bb[2 * p + 1][0] = q[1]; bb[2 * p + 1][1] = q[3];
            }
#pragma unroll
            for (int mf = 0; mf < 2; mf++)
#pragma unroll
                for (int nf = 0; nf < 8; nf++)
                    mma16816h(acc[mf][nf], aa[mf], bb[nf]);
        }
        __syncthreads();
    }

#pragma unroll
    for (int mf = 0; mf < 2; mf++) {
        const int row = row0 + wm * 32 + mf * 16 + (lane >> 2);
#pragma unroll
        for (int nf = 0; nf < 8; nf++) {
            const int col = col0 + wn * 64 + nf * 8 + (lane & 3) * 2;
            if (Cf) {
                float* p0 = Cf + (size_t)row * D_MODEL + col;
                float* p1 = Cf + (size_t)(row + 8) * D_MODEL + col;
                *(float2*)p0 = make_float2(acc[mf][nf][0], acc[mf][nf][1]);
                *(float2*)p1 = make_float2(acc[mf][nf][2], acc[mf][nf][3]);
            } else {
                *(uint32_t*)(Hh + (size_t)row * D_MODEL + col) =
                    pack_h2(acc[mf][nf][0], acc[mf][nf][1]);
                *(uint32_t*)(Hh + (size_t)(row + 8) * D_MODEL + col) =
                    pack_h2(acc[mf][nf][2], acc[mf][nf][3]);
            }
        }
    }
}

// ---------------------------------------------------------------------------
// Tensor-core flash attention, fp16x2 (Q pair, K/V single, P pair).
// ctx written as single fp16 (Wo GEMM is 1-pass).
// ---------------------------------------------------------------------------
#define AT_QH   0
#define AT_QL   16384
#define AT_KST  32768            // 2 stages x 16384
#define AT_VST  65536            // 2 stages x 16384
#define AT_SS   98304            // 64 x 68 f32
#define AT_PH   115712           // 64 x 64 fp16 SW128
#define AT_PL   123904
#define AT_AL   132096
#define AT_LR   132352
#define AT_SMEM 132608
#define NKV     (S_LEN / 64)     // 32

__device__ __forceinline__ void at_copy_tile(uint32_t dst, const __half* src,
                                             int tid) {
#pragma unroll
    for (int i = 0; i < 4; i++) {
        int idx = tid + i * 256;
        int c   = idx >> 9;
        int r   = (idx >> 3) & 63;
        int sg  = idx & 7;
        uint32_t so = dst + c * 8192 +
                      SMEM_SWIZZLE_128B((uint32_t)(r * 128 + sg * 16));
        cp_async16(so, src + (size_t)r * D_MODEL + c * 64 + sg * 8);
    }
}

__global__ __launch_bounds__(256) void attn_mma_kernel()
{
    extern __shared__ char smbuf[];
    const uint32_t sb = smem_u32(smbuf);
    const int tid  = threadIdx.x;
    const int wid  = tid >> 5;
    const int lane = tid & 31;
    const int b    = blockIdx.z;
    const int h    = blockIdx.y;
    const int q0   = blockIdx.x * 64;

    const int r16 = (lane & 7) | (((lane >> 3) & 1) << 3);
    const int cbq = ((lane >> 4) & 1) << 4;
    const int wm  = wid & 1;
    const int wn  = wid >> 1;

    const size_t hoff = (size_t)h * HDIM;
    const __half* Qhg = g_qh  + (size_t)(b * S_LEN + q0) * D_MODEL + hoff;
    const __half* Qlg = g_ql  + (size_t)(b * S_LEN + q0) * D_MODEL + hoff;
    const __half* Kg  = g_k16 + (size_t)(b * S_LEN) * D_MODEL + hoff;
    const __half* Vg  = g_v16 + (size_t)(b * S_LEN) * D_MODEL + hoff;

    float* Ssp   = (float*)(smbuf + AT_SS);
    float* alphp = (float*)(smbuf + AT_AL);
    float* lrowp = (float*)(smbuf + AT_LR);

    at_copy_tile(sb + AT_QH, Qhg, tid);
    at_copy_tile(sb + AT_QL, Qlg, tid);
    at_copy_tile(sb + AT_KST, Kg, tid);
    at_copy_tile(sb + AT_VST, Vg, tid);
    asm volatile("cp.async.commit_group;");

    float m_i = -1e30f, l_i = 0.f;
    float o_acc[2][4][4];
#pragma unroll
    for (int mf = 0; mf < 2; mf++)
#pragma unroll
        for (int nf = 0; nf < 4; nf++)
#pragma unroll
            for (int r = 0; r < 4; r++) o_acc[mf][nf][r] = 0.f;

    const int srow = tid >> 2;
    const int scol = (tid & 3) * 16;

    for (int it = 0; it < NKV; it++) {
        const int st = it & 1;
        asm volatile("cp.async.wait_group 0;");
        __syncthreads();

        // ---- S = (Qh+Ql) K16^T ----
        float sacc[2][2][4];
#pragma unroll
        for (int mf = 0; mf < 2; mf++)
#pragma unroll
            for (int nf = 0; nf < 2; nf++)
#pragma unroll
                for (int r = 0; r < 4; r++) sacc[mf][nf][r] = 0.f;

        const uint32_t kb = sb + AT_KST + st * 16384;
#pragma unroll
        for (int ks = 0; ks < 8; ks++) {
            const int chunk = ks >> 2;
            const int kbyte = (ks & 3) * 32 + cbq;
            uint32_t ah[2][4], al[2][4];
#pragma unroll
            for (int mf = 0; mf < 2; mf++) {
                const uint32_t off = chunk * 8192 +
                    SMEM_SWIZZLE_128B((uint32_t)((wm * 32 + mf * 16 + r16) * 128 + kbyte));
                ldsm4(ah[mf], sb + AT_QH + off);
                ldsm4(al[mf], sb + AT_QL + off);
            }
            const uint32_t offb = chunk * 8192 +
                SMEM_SWIZZLE_128B((uint32_t)((wn * 16 + r16) * 128 + kbyte));
            uint32_t q[4];
            ldsm4(q, kb + offb);
            uint32_t bb[2][2] = {{q[0], q[2]}, {q[1], q[3]}};
#pragma unroll
            for (int mf = 0; mf < 2; mf++)
#pragma unroll
                for (int nf = 0; nf < 2; nf++) {
                    mma16816h(sacc[mf][nf], ah[mf], bb[nf]);
                    mma16816h(sacc[mf][nf], al[mf], bb[nf]);
                }
        }

#pragma unroll
        for (int mf = 0; mf < 2; mf++) {
            const int row = wm * 32 + mf * 16 + (lane >> 2);
#pragma unroll
            for (int nf = 0; nf < 2; nf++) {
                const int col = wn * 16 + nf * 8 + (lane & 3) * 2;
                *(float2*)(Ssp + row * 68 + col) =
                    make_float2(sacc[mf][nf][0], sacc[mf][nf][1]);
                *(float2*)(Ssp + (row + 8) * 68 + col) =
                    make_float2(sacc[mf][nf][2], sacc[mf][nf][3]);
            }
        }
        __syncthreads();

        if (it + 1 < NKV) {
            const int ns = (it + 1) & 1;
            const size_t roff = (size_t)((it + 1) * 64) * D_MODEL;
            at_copy_tile(sb + AT_KST + ns * 16384, Kg + roff, tid);
            at_copy_tile(sb + AT_VST + ns * 16384, Vg + roff, tid);
            asm volatile("cp.async.commit_group;");
        }

        // ---- online softmax ----
        {
            float sv[16];
#pragma unroll
            for (int u = 0; u < 4; u++)
                *(float4*)(sv + u * 4) = *(float4*)(Ssp + srow * 68 + scol + u * 4);
            float mx = sv[0];
#pragma unroll
            for (int u = 1; u < 16; u++) mx = fmaxf(mx, sv[u]);
            mx = fmaxf(mx, __shfl_xor_sync(0xffffffffu, mx, 1));
            mx = fmaxf(mx, __shfl_xor_sync(0xffffffffu, mx, 2));
            const float mnew  = fmaxf(m_i, mx);
            const float alpha = __expf(m_i - mnew);
            m_i = mnew;
            float sum = 0.f;
            float p[16];
#pragma unroll
            for (int u = 0; u < 16; u++) {
                p[u] = __expf(sv[u] - mnew);
                sum += p[u];
            }
            sum += __shfl_xor_sync(0xffffffffu, sum, 1);
            sum += __shfl_xor_sync(0xffffffffu, sum, 2);
            l_i = l_i * alpha + sum;
#pragma unroll
            for (int u2 = 0; u2 < 8; u2++) {
                const uint32_t off =
                    SMEM_SWIZZLE_128B((uint32_t)(srow * 128 + (scol + u2 * 2) * 2));
                const float p0 = p[u2 * 2], p1 = p[u2 * 2 + 1];
                const float h0 = __half2float(__float2half(p0));
                const float h1 = __half2float(__float2half(p1));
                *(uint32_t*)(smbuf + AT_PH + off) = pack_h2(h0, h1);
                *(uint32_t*)(smbuf + AT_PL + off) = pack_h2(p0 - h0, p1 - h1);
            }
            if ((tid & 3) == 0) alphp[srow] = alpha;
        }
        __syncthreads();

        // ---- rescale O ----
#pragma unroll
        for (int mf = 0; mf < 2; mf++) {
            const float a0 = alphp[wm * 32 + mf * 16 + (lane >> 2)];
            const float a1 = alphp[wm * 32 + mf * 16 + (lane >> 2) + 8];
#pragma unroll
            for (int nf = 0; nf < 4; nf++) {
                o_acc[mf][nf][0] *= a0; o_acc[mf][nf][1] *= a0;
                o_acc[mf][nf][2] *= a1; o_acc[mf][nf][3] *= a1;
            }
        }

        // ---- O += (Ph+Pl) V16 ----
        const uint32_t vb = sb + AT_VST + st * 16384;
        const int g  = lane >> 3;
        const int kg = (g & 1) << 3;
        const int ng = (g >> 1) << 3;
#pragma unroll
        for (int kpv = 0; kpv < 4; kpv++) {
            uint32_t aph[2][4], apl[2][4];
#pragma unroll
            for (int mf = 0; mf < 2; mf++) {
                const uint32_t off =
                    SMEM_SWIZZLE_128B((uint32_t)((wm * 32 + mf * 16 + r16) * 128 +
                                                 kpv * 32 + cbq));
                ldsm4(aph[mf], sb + AT_PH + off);
                ldsm4(apl[mf], sb + AT_PL + off);
            }
            uint32_t bv[4][2];
#pragma unroll
            for (int pr = 0; pr < 2; pr++) {
                const int kr = kpv * 16 + kg + (lane & 7);
                const int nc = wn * 32 + pr * 16 + ng;
                const uint32_t off = (uint32_t)(nc >> 6) * 8192 +
                    SMEM_SWIZZLE_128B((uint32_t)(kr * 128 + (nc & 63) * 2));
                uint32_t t4[4];
                ldsm4t(t4, vb + off);
                bv[2 * pr][0] = t4[0]; bv[2 * pr][1] = t4[1];
                bv[2 * pr + 1][0] = t4[2]; bv[2 * pr + 1][1] = t4[3];
            }
#pragma unroll
            for (int mf = 0; mf < 2; mf++)
#pragma unroll
                for (int nf = 0; nf < 4; nf++) {
                    mma16816h(o_acc[mf][nf], aph[mf], bv[nf]);
                    mma16816h(o_acc[mf][nf], apl[mf], bv[nf]);
                }
        }
    }

    // ---- epilogue: ctx single fp16 ----
    if ((tid & 3) == 0) lrowp[srow] = l_i;
    __syncthreads();
    if (tid < 64) lrowp[tid] = 1.0f / lrowp[tid];
    __syncthreads();

    __half* Chg = g_ch + (size_t)(b * S_LEN + q0) * D_MODEL + hoff;
#pragma unroll
    for (int mf = 0; mf < 2; mf++) {
        const int ra  = wm * 32 + mf * 16 + (lane >> 2);
        const float i0 = lrowp[ra];
        const float i1 = lrowp[ra + 8];
#pragma unroll
        for (int nf = 0; nf < 4; nf++) {
            const int col = wn * 32 + nf * 8 + (lane & 3) * 2;
            *(uint32_t*)(Chg + (size_t)ra * D_MODEL + col) =
                pack_h2(o_acc[mf][nf][0] * i0, o_acc[mf][nf][1] * i0);
            *(uint32_t*)(Chg + (size_t)(ra + 8) * D_MODEL + col) =
                pack_h2(o_acc[mf][nf][2] * i1, o_acc[mf][nf][3] * i1);
        }
    }
}

// ---------------------------------------------------------------------------
extern "C" void kernel_launch(void* const* d_in, const int* in_sizes, int n_in,
                              void* d_out, int out_size)
{
    const float* x  = (const float*)d_in[0];
    const float* Wq = (const float*)d_in[1];
    const float* Wk = (const float*)d_in[2];
    const float* Wv = (const float*)d_in[3];
    const float* Wo = (const float*)d_in[4];
    float* out = (float*)d_out;

    __half *xh, *xl, *wq16, *wk16, *wv16, *wo16, *qh, *ql, *k16, *v16, *ch;
    cudaGetSymbolAddress((void**)&xh,   g_xh);
    cudaGetSymbolAddress((void**)&xl,   g_xl);
    cudaGetSymbolAddress((void**)&wq16, g_wq16);
    cudaGetSymbolAddress((void**)&wk16, g_wk16);
    cudaGetSymbolAddress((void**)&wv16, g_wv16);
    cudaGetSymbolAddress((void**)&wo16, g_wo16);
    cudaGetSymbolAddress((void**)&qh,   g_qh);
    cudaGetSymbolAddress((void**)&ql,   g_ql);
    cudaGetSymbolAddress((void**)&k16,  g_k16);
    cudaGetSymbolAddress((void**)&v16,  g_v16);
    cudaGetSymbolAddress((void**)&ch,   g_ch);

    cudaFuncSetAttribute(gemm_mma_f16x2_kernel,
                         cudaFuncAttributeMaxDynamicSharedMemorySize, GEMM_SMEM2);
    cudaFuncSetAttribute(gemm_mma_f16x1_kernel,
                         cudaFuncAttributeMaxDynamicSharedMemorySize, GEMM_SMEM1);
    cudaFuncSetAttribute(attn_mma_kernel,
                         cudaFuncAttributeMaxDynamicSharedMemorySize, AT_SMEM);

    const int nx4 = MROWS * D_MODEL / 4;
    const int nw4 = D_MODEL * D_MODEL / 4;
    dim3 ggrid(D_MODEL / 128, MROWS / 128);
    const float qscale = 0.08838834764831845f;   // 1/sqrt(128)

    cvt_x_kernel<<<(nx4 + 255) / 256, 256>>>(x, xh, xl, nx4);
    cvt_w4_kernel<<<(4 * nw4 + 255) / 256, 256>>>(Wq, Wk, Wv, Wo,
                                                  wq16, wk16, wv16, wo16, nw4);

    gemm_mma_f16x2_kernel<<<ggrid, 256, GEMM_SMEM2>>>(xh, xl, wq16, qh, ql, qscale);
    gemm_mma_f16x2_kernel<<<ggrid, 256, GEMM_SMEM2>>>(xh, xl, wk16, k16, nullptr, 1.0f);
    gemm_mma_f16x1_kernel<<<ggrid, 256, GEMM_SMEM1>>>(xh, wv16, nullptr, v16);

    attn_mma_kernel<<<dim3(S_LEN / 64, NHEADS, BATCH), 256, AT_SMEM>>>();

    gemm_mma_f16x1_kernel<<<ggrid, 256, GEMM_SMEM1>>>(ch, wo16, out, nullptr);
}

// round 15
// speedup vs baseline: 5.3635x; 1.0768x over previous
#include <cuda_runtime.h>
#include <cuda_fp16.h>
#include <cstdint>

// ---------------------------------------------------------------------------
// MultiHeadSelfAttention  B=2, S=2048, D=2048, H=16, Hd=128, fp32 in/out
//   Q,K GEMMs: fp16 "x2" (x pair * W fp16), fused into ONE launch (grid.z=2),
//              2-stage pipeline + 2 CTAs/SM (occupancy fix from R14 ncu).
//   V,Wo GEMMs: pure fp16 1-pass.   Attention: fp16x2 flash (unchanged).
//   rel_err ~5.6e-4 (identical numerics to R14's passing kernel).
// ---------------------------------------------------------------------------

#define S_LEN   2048
#define D_MODEL 2048
#define BATCH   2
#define NHEADS  16
#define HDIM    128
#define MROWS   (BATCH * S_LEN)   // 4096

// ------------------------- scratch (static, allocation-free) ---------------
__device__ __half g_xh[(size_t)MROWS * D_MODEL];     // x fp16 hi
__device__ __half g_xl[(size_t)MROWS * D_MODEL];     // x fp16 lo
__device__ __half g_wq16[(size_t)D_MODEL * D_MODEL];
__device__ __half g_wk16[(size_t)D_MODEL * D_MODEL];
__device__ __half g_wv16[(size_t)D_MODEL * D_MODEL];
__device__ __half g_wo16[(size_t)D_MODEL * D_MODEL];
__device__ __half g_qh[(size_t)MROWS * D_MODEL];     // Q hi (pre-scaled)
__device__ __half g_ql[(size_t)MROWS * D_MODEL];     // Q lo
__device__ __half g_k16[(size_t)MROWS * D_MODEL];    // K single fp16
__device__ __half g_v16[(size_t)MROWS * D_MODEL];    // V single fp16
__device__ __half g_ch[(size_t)MROWS * D_MODEL];     // ctx single fp16

// ------------------------- helpers -----------------------------------------
__device__ __forceinline__ uint32_t smem_u32(const void* p) {
    uint32_t a;
    asm("{ .reg .u64 t; cvta.to.shared.u64 t, %1; cvt.u32.u64 %0, t; }"
        : "=r"(a) : "l"(p));
    return a;
}
#define SMEM_SWIZZLE_128B(off) ((off) ^ (((off) >> 3) & 0x70))

__device__ __forceinline__ void ldsm4(uint32_t* r, uint32_t addr) {
    asm volatile("ldmatrix.sync.aligned.m8n8.x4.shared.b16 {%0,%1,%2,%3}, [%4];"
                 : "=r"(r[0]), "=r"(r[1]), "=r"(r[2]), "=r"(r[3]) : "r"(addr));
}
__device__ __forceinline__ void ldsm4t(uint32_t* r, uint32_t addr) {
    asm volatile("ldmatrix.sync.aligned.m8n8.x4.trans.shared.b16 {%0,%1,%2,%3}, [%4];"
                 : "=r"(r[0]), "=r"(r[1]), "=r"(r[2]), "=r"(r[3]) : "r"(addr));
}
__device__ __forceinline__ void mma16816h(float* d, const uint32_t* a, const uint32_t* b) {
    asm volatile(
        "mma.sync.aligned.m16n8k16.row.col.f32.f16.f16.f32 "
        "{%0,%1,%2,%3}, {%4,%5,%6,%7}, {%8,%9}, {%0,%1,%2,%3};"
        : "+f"(d[0]), "+f"(d[1]), "+f"(d[2]), "+f"(d[3])
        : "r"(a[0]), "r"(a[1]), "r"(a[2]), "r"(a[3]), "r"(b[0]), "r"(b[1]));
}
__device__ __forceinline__ void cp_async16(uint32_t sdst, const void* gsrc) {
    asm volatile("cp.async.cg.shared.global [%0], [%1], 16;" :: "r"(sdst), "l"(gsrc));
}
__device__ __forceinline__ uint32_t pack_h2(float a, float b) {
    __half2 v(__float2half(a), __float2half(b));
    return *(uint32_t*)&v;
}

// ---------------------------------------------------------------------------
// Conversions
// ---------------------------------------------------------------------------
__global__ __launch_bounds__(256) void cvt_x_kernel(
    const float* __restrict__ in, __half* __restrict__ hh,
    __half* __restrict__ hl, int n4)
{
    int i = blockIdx.x * blockDim.x + threadIdx.x;
    if (i >= n4) return;
    float4 v = ((const float4*)in)[i];
    float x[4] = {v.x, v.y, v.z, v.w};
    float h[4], l[4];
#pragma unroll
    for (int j = 0; j < 4; j++) {
        h[j] = __half2float(__float2half(x[j]));
        l[j] = x[j] - h[j];
    }
    ((uint32_t*)hh)[2 * i]     = pack_h2(h[0], h[1]);
    ((uint32_t*)hh)[2 * i + 1] = pack_h2(h[2], h[3]);
    ((uint32_t*)hl)[2 * i]     = pack_h2(l[0], l[1]);
    ((uint32_t*)hl)[2 * i + 1] = pack_h2(l[2], l[3]);
}

__global__ __launch_bounds__(256) void cvt_w4_kernel(
    const float* __restrict__ a0, const float* __restrict__ a1,
    const float* __restrict__ a2, const float* __restrict__ a3,
    __half* __restrict__ o0, __half* __restrict__ o1,
    __half* __restrict__ o2, __half* __restrict__ o3, int n4)
{
    int idx = blockIdx.x * blockDim.x + threadIdx.x;
    int w = idx / n4;
    int i = idx - w * n4;
    if (w >= 4) return;
    const float* src = (w == 0) ? a0 : (w == 1) ? a1 : (w == 2) ? a2 : a3;
    __half* dst      = (w == 0) ? o0 : (w == 1) ? o1 : (w == 2) ? o2 : o3;
    float4 v = ((const float4*)src)[i];
    ((uint32_t*)dst)[2 * i]     = pack_h2(v.x, v.y);
    ((uint32_t*)dst)[2 * i + 1] = pack_h2(v.z, v.w);
}

// ---------------------------------------------------------------------------
// Common GEMM geometry
// ---------------------------------------------------------------------------
#define GK        64
#define TILE_B    (128 * GK * 2)         // 16384
#define NCHUNK    (D_MODEL / GK)         // 32

// ---------------------------------------------------------------------------
// Fused Q+K fp16x2 GEMM (grid.z selects weight/output).
// 3 tiles/stage, 2-stage pipeline (96KB) + launch_bounds(256,2) -> 2 CTAs/SM.
// z=0: Q = (xh+xl) Wq^T * qscale -> (qh, ql) pair.  z=1: K -> k16 single.
// ---------------------------------------------------------------------------
#define STAGE_B2   (3 * TILE_B)          // 49152
#define NSTAGE2    2
#define GEMM_SMEM2 (NSTAGE2 * STAGE_B2)  // 98304

__global__ __launch_bounds__(256, 2) void gemm_qk_f16x2_kernel(
    const __half* __restrict__ Ah, const __half* __restrict__ Al,
    const __half* __restrict__ Bq, const __half* __restrict__ Bk,
    __half* __restrict__ Qh, __half* __restrict__ Ql,
    __half* __restrict__ K16, float qscale)
{
    extern __shared__ char smem[];
    const uint32_t smem_base = smem_u32(smem);
    const int tid  = threadIdx.x;
    const int wid  = tid >> 5;
    const int lane = tid & 31;
    const int wm   = wid & 3;
    const int wn   = wid >> 2;
    const int row0 = blockIdx.y * 128;
    const int col0 = blockIdx.x * 128;
    const int isK  = blockIdx.z;
    const __half* B = isK ? Bk : Bq;

    int cr[4], cs[4];
    uint32_t csw[4];
#pragma unroll
    for (int i = 0; i < 4; i++) {
        int idx = tid + i * 256;
        cr[i]  = idx >> 3;
        cs[i]  = idx & 7;
        csw[i] = SMEM_SWIZZLE_128B((uint32_t)(cr[i] * 128 + cs[i] * 16));
    }

    auto copy_stage = [&](int st, int kc) {
        const uint32_t sb = smem_base + st * STAGE_B2;
#pragma unroll
        for (int i = 0; i < 4; i++) {
            const size_t aoff = (size_t)(row0 + cr[i]) * D_MODEL + kc * GK + cs[i] * 8;
            const size_t boff = (size_t)(col0 + cr[i]) * D_MODEL + kc * GK + cs[i] * 8;
            cp_async16(sb + 0 * TILE_B + csw[i], Ah + aoff);
            cp_async16(sb + 1 * TILE_B + csw[i], Al + aoff);
            cp_async16(sb + 2 * TILE_B + csw[i], B + boff);
        }
    };

    float acc[2][8][4];
#pragma unroll
    for (int mf = 0; mf < 2; mf++)
#pragma unroll
        for (int nf = 0; nf < 8; nf++)
#pragma unroll
            for (int r = 0; r < 4; r++) acc[mf][nf][r] = 0.f;

    const int quad = lane >> 3;
    const int r16  = (lane & 7) | ((quad & 1) << 3);
    const int cbq  = (quad >> 1) << 4;

    copy_stage(0, 0);
    asm volatile("cp.async.commit_group;");

    for (int kc = 0; kc < NCHUNK; kc++) {
        if (kc + 1 < NCHUNK) {
            copy_stage((kc + 1) & 1, kc + 1);
            asm volatile("cp.async.commit_group;");
            asm volatile("cp.async.wait_group 1;");
        } else {
            asm volatile("cp.async.wait_group 0;");
        }
        __syncthreads();

        const uint32_t sb  = smem_base + (kc & 1) * STAGE_B2;
        const uint32_t sAh = sb + 0 * TILE_B;
        const uint32_t sAl = sb + 1 * TILE_B;
        const uint32_t sB  = sb + 2 * TILE_B;

#pragma unroll
        for (int ks = 0; ks < 4; ks++) {
            uint32_t ah[2][4], al[2][4], bb[8][2];
#pragma unroll
            for (int mf = 0; mf < 2; mf++) {
                const int row = wm * 32 + mf * 16 + r16;
                const uint32_t off =
                    SMEM_SWIZZLE_128B((uint32_t)(row * 128 + cbq + ks * 32));
                ldsm4(ah[mf], sAh + off);
                ldsm4(al[mf], sAl + off);
            }
#pragma unroll
            for (int p = 0; p < 4; p++) {
                const int row = wn * 64 + p * 16 + r16;
                const uint32_t off =
                    SMEM_SWIZZLE_128B((uint32_t)(row * 128 + cbq + ks * 32));
                uint32_t q[4];
                ldsm4(q, sB + off);
                bb[2 * p][0] = q[0]; bb[2 * p][1] = q[2];
                bb[2 * p + 1][0] = q[1]; bb[2 * p + 1][1] = q[3];
            }
#pragma unroll
            for (int mf = 0; mf < 2; mf++)
#pragma unroll
                for (int nf = 0; nf < 8; nf++) {
                    mma16816h(acc[mf][nf], ah[mf], bb[nf]);
                    mma16816h(acc[mf][nf], al[mf], bb[nf]);
                }
        }
        __syncthreads();
    }

#pragma unroll
    for (int mf = 0; mf < 2; mf++) {
        const int row = row0 + wm * 32 + mf * 16 + (lane >> 2);
#pragma unroll
        for (int nf = 0; nf < 8; nf++) {
            const int col = col0 + wn * 64 + nf * 8 + (lane & 3) * 2;
            if (!isK) {
                float v[4], h[4], l[4];
#pragma unroll
                for (int r = 0; r < 4; r++) {
                    v[r] = acc[mf][nf][r] * qscale;
                    h[r] = __half2float(__float2half(v[r]));
                    l[r] = v[r] - h[r];
                }
                *(uint32_t*)(Qh + (size_t)row * D_MODEL + col)       = pack_h2(h[0], h[1]);
                *(uint32_t*)(Qh + (size_t)(row + 8) * D_MODEL + col) = pack_h2(h[2], h[3]);
                *(uint32_t*)(Ql + (size_t)row * D_MODEL + col)       = pack_h2(l[0], l[1]);
                *(uint32_t*)(Ql + (size_t)(row + 8) * D_MODEL + col) = pack_h2(l[2], l[3]);
            } else {
                *(uint32_t*)(K16 + (size_t)row * D_MODEL + col) =
                    pack_h2(acc[mf][nf][0], acc[mf][nf][1]);
                *(uint32_t*)(K16 + (size_t)(row + 8) * D_MODEL + col) =
                    pack_h2(acc[mf][nf][2], acc[mf][nf][3]);
            }
        }
    }
}

// ---------------------------------------------------------------------------
// fp16 1-pass GEMM-NT (V, Wo): 2 tiles/stage, 3 stages (96KB), 2 CTAs/SM.
// ---------------------------------------------------------------------------
#define STAGE_B1   (2 * TILE_B)          // 32768
#define NSTAGE1    3
#define GEMM_SMEM1 (NSTAGE1 * STAGE_B1)  // 98304

__global__ __launch_bounds__(256, 2) void gemm_mma_f16x1_kernel(
    const __half* __restrict__ A, const __half* __restrict__ B,
    float* __restrict__ Cf, __half* __restrict__ Hh)
{
    extern __shared__ char smem[];
    const uint32_t smem_base = smem_u32(smem);
    const int tid  = threadIdx.x;
    const int wid  = tid >> 5;
    const int lane = tid & 31;
    const int wm   = wid & 3;
    const int wn   = wid >> 2;
    const int row0 = blockIdx.y * 128;
    const int col0 = blockIdx.x * 128;

    int cr[4], cs[4];
    uint32_t csw[4];
#pragma unroll
    for (int i = 0; i < 4; i++) {
        int idx = tid + i * 256;
        cr[i]  = idx >> 3;
        cs[i]  = idx & 7;
        csw[i] = SMEM_SWIZZLE_128B((uint32_t)(cr[i] * 128 + cs[i] * 16));
    }

    auto copy_stage = [&](int st, int kc) {
        const uint32_t sb = smem_base + st * STAGE_B1;
#pragma unroll
        for (int i = 0; i < 4; i++) {
            const size_t aoff = (size_t)(row0 + cr[i]) * D_MODEL + kc * GK + cs[i] * 8;
            const size_t boff = (size_t)(col0 + cr[i]) * D_MODEL + kc * GK + cs[i] * 8;
            cp_async16(sb + 0 * TILE_B + csw[i], A + aoff);
            cp_async16(sb + 1 * TILE_B + csw[i], B + boff);
        }
    };

    float acc[2][8][4];
#pragma unroll
    for (int mf = 0; mf < 2; mf++)
#pragma unroll
        for (int nf = 0; nf < 8; nf++)
#pragma unroll
            for (int r = 0; r < 4; r++) acc[mf][nf][r] = 0.f;

    const int quad = lane >> 3;
    const int r16  = (lane & 7) | ((quad & 1) << 3);
    const int cbq  = (quad >> 1) << 4;

    copy_stage(0, 0);
    asm volatile("cp.async.commit_group;");
    copy_stage(1, 1);
    asm volatile("cp.async.commit_group;");

    for (int kc = 0; kc < NCHUNK; kc++) {
        if (kc + 2 < NCHUNK) copy_stage((kc + 2) % NSTAGE1, kc + 2);
        asm volatile("cp.async.commit_group;");
        asm volatile("cp.async.wait_group 2;");
        __syncthreads();

        const uint32_t sb = smem_base + (kc % NSTAGE1) * STAGE_B1;
        const uint32_t sA = sb + 0 * TILE_B;
        const uint32_t sB = sb + 1 * TILE_B;

#pragma unroll
        for (int ks = 0; ks < 4; ks++) {
            uint32_t aa[2][4], bb[8][2];
#pragma unroll
            for (int mf = 0; mf < 2; mf++) {
                const int row = wm * 32 + mf * 16 + r16;
                const uint32_t off =
                    SMEM_SWIZZLE_128B((uint32_t)(row * 128 + cbq + ks * 32));
                ldsm4(aa[mf], sA + off);
            }
#pragma unroll
            for (int p = 0; p < 4; p++) {
                const int row = wn * 64 + p * 16 + r16;
                const uint32_t off =
                    SMEM_SWIZZLE_128B((uint32_t)(row * 128 + cbq + ks * 32));
                uint32_t q[4];
                ldsm4(q, sB + off);
                bb[2 * p][0] = q[0]; bb[2 * p][1] = q[2];
                bb[2 * p + 1][0] = q[1]; bb[2 * p + 1][1] = q[3];
            }
#pragma unroll
            for (int mf = 0; mf < 2; mf++)
#pragma unroll
                for (int nf = 0; nf < 8; nf++)
                    mma16816h(acc[mf][nf], aa[mf], bb[nf]);
        }
        __syncthreads();
    }

#pragma unroll
    for (int mf = 0; mf < 2; mf++) {
        const int row = row0 + wm * 32 + mf * 16 + (lane >> 2);
#pragma unroll
        for (int nf = 0; nf < 8; nf++) {
            const int col = col0 + wn * 64 + nf * 8 + (lane & 3) * 2;
            if (Cf) {
                float* p0 = Cf + (size_t)row * D_MODEL + col;
                float* p1 = Cf + (size_t)(row + 8) * D_MODEL + col;
                *(float2*)p0 = make_float2(acc[mf][nf][0], acc[mf][nf][1]);
                *(float2*)p1 = make_float2(acc[mf][nf][2], acc[mf][nf][3]);
            } else {
                *(uint32_t*)(Hh + (size_t)row * D_MODEL + col) =
                    pack_h2(acc[mf][nf][0], acc[mf][nf][1]);
                *(uint32_t*)(Hh + (size_t)(row + 8) * D_MODEL + col) =
                    pack_h2(acc[mf][nf][2], acc[mf][nf][3]);
            }
        }
    }
}

// ---------------------------------------------------------------------------
// Tensor-core flash attention, fp16x2 (unchanged from R14).
// ---------------------------------------------------------------------------
#define AT_QH   0
#define AT_QL   16384
#define AT_KST  32768
#define AT_VST  65536
#define AT_SS   98304
#define AT_PH   115712
#define AT_PL   123904
#define AT_AL   132096
#define AT_LR   132352
#define AT_SMEM 132608
#define NKV     (S_LEN / 64)

__device__ __forceinline__ void at_copy_tile(uint32_t dst, const __half* src,
                                             int tid) {
#pragma unroll
    for (int i = 0; i < 4; i++) {
        int idx = tid + i * 256;
        int c   = idx >> 9;
        int r   = (idx >> 3) & 63;
        int sg  = idx & 7;
        uint32_t so = dst + c * 8192 +
                      SMEM_SWIZZLE_128B((uint32_t)(r * 128 + sg * 16));
        cp_async16(so, src + (size_t)r * D_MODEL + c * 64 + sg * 8);
    }
}

__global__ __launch_bounds__(256) void attn_mma_kernel()
{
    extern __shared__ char smbuf[];
    const uint32_t sb = smem_u32(smbuf);
    const int tid  = threadIdx.x;
    const int wid  = tid >> 5;
    const int lane = tid & 31;
    const int b    = blockIdx.z;
    const int h    = blockIdx.y;
    const int q0   = blockIdx.x * 64;

    const int r16 = (lane & 7) | (((lane >> 3) & 1) << 3);
    const int cbq = ((lane >> 4) & 1) << 4;
    const int wm  = wid & 1;
    const int wn  = wid >> 1;

    const size_t hoff = (size_t)h * HDIM;
    const __half* Qhg = g_qh  + (size_t)(b * S_LEN + q0) * D_MODEL + hoff;
    const __half* Qlg = g_ql  + (size_t)(b * S_LEN + q0) * D_MODEL + hoff;
    const __half* Kg  = g_k16 + (size_t)(b * S_LEN) * D_MODEL + hoff;
    const __half* Vg  = g_v16 + (size_t)(b * S_LEN) * D_MODEL + hoff;

    float* Ssp   = (float*)(smbuf + AT_SS);
    float* alphp = (float*)(smbuf + AT_AL);
    float* lrowp = (float*)(smbuf + AT_LR);

    at_copy_tile(sb + AT_QH, Qhg, tid);
    at_copy_tile(sb + AT_QL, Qlg, tid);
    at_copy_tile(sb + AT_KST, Kg, tid);
    at_copy_tile(sb + AT_VST, Vg, tid);
    asm volatile("cp.async.commit_group;");

    float m_i = -1e30f, l_i = 0.f;
    float o_acc[2][4][4];
#pragma unroll
    for (int mf = 0; mf < 2; mf++)
#pragma unroll
        for (int nf = 0; nf < 4; nf++)
#pragma unroll
            for (int r = 0; r < 4; r++) o_acc[mf][nf][r] = 0.f;

    const int srow = tid >> 2;
    const int scol = (tid & 3) * 16;

    for (int it = 0; it < NKV; it++) {
        const int st = it & 1;
        asm volatile("cp.async.wait_group 0;");
        __syncthreads();

        float sacc[2][2][4];
#pragma unroll
        for (int mf = 0; mf < 2; mf++)
#pragma unroll
            for (int nf = 0; nf < 2; nf++)
#pragma unroll
                for (int r = 0; r < 4; r++) sacc[mf][nf][r] = 0.f;

        const uint32_t kb = sb + AT_KST + st * 16384;
#pragma unroll
        for (int ks = 0; ks < 8; ks++) {
            const int chunk = ks >> 2;
            const int kbyte = (ks & 3) * 32 + cbq;
            uint32_t ah[2][4], al[2][4];
#pragma unroll
            for (int mf = 0; mf < 2; mf++) {
                const uint32_t off = chunk * 8192 +
                    SMEM_SWIZZLE_128B((uint32_t)((wm * 32 + mf * 16 + r16) * 128 + kbyte));
                ldsm4(ah[mf], sb + AT_QH + off);
                ldsm4(al[mf], sb + AT_QL + off);
            }
            const uint32_t offb = chunk * 8192 +
                SMEM_SWIZZLE_128B((uint32_t)((wn * 16 + r16) * 128 + kbyte));
            uint32_t q[4];
            ldsm4(q, kb + offb);
            uint32_t bb[2][2] = {{q[0], q[2]}, {q[1], q[3]}};
#pragma unroll
            for (int mf = 0; mf < 2; mf++)
#pragma unroll
                for (int nf = 0; nf < 2; nf++) {
                    mma16816h(sacc[mf][nf], ah[mf], bb[nf]);
                    mma16816h(sacc[mf][nf], al[mf], bb[nf]);
                }
        }

#pragma unroll
        for (int mf = 0; mf < 2; mf++) {
            const int row = wm * 32 + mf * 16 + (lane >> 2);
#pragma unroll
            for (int nf = 0; nf < 2; nf++) {
                const int col = wn * 16 + nf * 8 + (lane & 3) * 2;
                *(float2*)(Ssp + row * 68 + col) =
                    make_float2(sacc[mf][nf][0], sacc[mf][nf][1]);
                *(float2*)(Ssp + (row + 8) * 68 + col) =
                    make_float2(sacc[mf][nf][2], sacc[mf][nf][3]);
            }
        }
        __syncthreads();

        if (it + 1 < NKV) {
            const int ns = (it + 1) & 1;
            const size_t roff = (size_t)((it + 1) * 64) * D_MODEL;
            at_copy_tile(sb + AT_KST + ns * 16384, Kg + roff, tid);
            at_copy_tile(sb + AT_VST + ns * 16384, Vg + roff, tid);
            asm volatile("cp.async.commit_group;");
        }

        {
            float sv[16];
#pragma unroll
            for (int u = 0; u < 4; u++)
                *(float4*)(sv + u * 4) = *(float4*)(Ssp + srow * 68 + scol + u * 4);
            float mx = sv[0];
#pragma unroll
            for (int u = 1; u < 16; u++) mx = fmaxf(mx, sv[u]);
            mx = fmaxf(mx, __shfl_xor_sync(0xffffffffu, mx, 1));
            mx = fmaxf(mx, __shfl_xor_sync(0xffffffffu, mx, 2));
            const float mnew  = fmaxf(m_i, mx);
            const float alpha = __expf(m_i - mnew);
            m_i = mnew;
            float sum = 0.f;
            float p[16];
#pragma unroll
            for (int u = 0; u < 16; u++) {
                p[u] = __expf(sv[u] - mnew);
                sum += p[u];
            }
            sum += __shfl_xor_sync(0xffffffffu, sum, 1);
            sum += __shfl_xor_sync(0xffffffffu, sum, 2);
            l_i = l_i * alpha + sum;
#pragma unroll
            for (int u2 = 0; u2 < 8; u2++) {
                const uint32_t off =
                    SMEM_SWIZZLE_128B((uint32_t)(srow * 128 + (scol + u2 * 2) * 2));
                const float p0 = p[u2 * 2], p1 = p[u2 * 2 + 1];
                const float h0 = __half2float(__float2half(p0));
                const float h1 = __half2float(__float2half(p1));
                *(uint32_t*)(smbuf + AT_PH + off) = pack_h2(h0, h1);
                *(uint32_t*)(smbuf + AT_PL + off) = pack_h2(p0 - h0, p1 - h1);
            }
            if ((tid & 3) == 0) alphp[srow] = alpha;
        }
        __syncthreads();

#pragma unroll
        for (int mf = 0; mf < 2; mf++) {
            const float a0 = alphp[wm * 32 + mf * 16 + (lane >> 2)];
            const float a1 = alphp[wm * 32 + mf * 16 + (lane >> 2) + 8];
#pragma unroll
            for (int nf = 0; nf < 4; nf++) {
                o_acc[mf][nf][0] *= a0; o_acc[mf][nf][1] *= a0;
                o_acc[mf][nf][2] *= a1; o_acc[mf][nf][3] *= a1;
            }
        }

        const uint32_t vb = sb + AT_VST + st * 16384;
        const int g  = lane >> 3;
        const int kg = (g & 1) << 3;
        const int ng = (g >> 1) << 3;
#pragma unroll
        for (int kpv = 0; kpv < 4; kpv++) {
            uint32_t aph[2][4], apl[2][4];
#pragma unroll
            for (int mf = 0; mf < 2; mf++) {
                const uint32_t off =
                    SMEM_SWIZZLE_128B((uint32_t)((wm * 32 + mf * 16 + r16) * 128 +
                                                 kpv * 32 + cbq));
                ldsm4(aph[mf], sb + AT_PH + off);
                ldsm4(apl[mf], sb + AT_PL + off);
            }
            uint32_t bv[4][2];
#pragma unroll
            for (int pr = 0; pr < 2; pr++) {
                const int kr = kpv * 16 + kg + (lane & 7);
                const int nc = wn * 32 + pr * 16 + ng;
                const uint32_t off = (uint32_t)(nc >> 6) * 8192 +
                    SMEM_SWIZZLE_128B((uint32_t)(kr * 128 + (nc & 63) * 2));
                uint32_t t4[4];
                ldsm4t(t4, vb + off);
                bv[2 * pr][0] = t4[0]; bv[2 * pr][1] = t4[1];
                bv[2 * pr + 1][0] = t4[2]; bv[2 * pr + 1][1] = t4[3];
            }
#pragma unroll
            for (int mf = 0; mf < 2; mf++)
#pragma unroll
                for (int nf = 0; nf < 4; nf++) {
                    mma16816h(o_acc[mf][nf], aph[mf], bv[nf]);
                    mma16816h(o_acc[mf][nf], apl[mf], bv[nf]);
                }
        }
    }

    if ((tid & 3) == 0) lrowp[srow] = l_i;
    __syncthreads();
    if (tid < 64) lrowp[tid] = 1.0f / lrowp[tid];
    __syncthreads();

    __half* Chg = g_ch + (size_t)(b * S_LEN + q0) * D_MODEL + hoff;
#pragma unroll
    for (int mf = 0; mf < 2; mf++) {
        const int ra  = wm * 32 + mf * 16 + (lane >> 2);
        const float i0 = lrowp[ra];
        const float i1 = lrowp[ra + 8];
#pragma unroll
        for (int nf = 0; nf < 4; nf++) {
            const int col = wn * 32 + nf * 8 + (lane & 3) * 2;
            *(uint32_t*)(Chg + (size_t)ra * D_MODEL + col) =
                pack_h2(o_acc[mf][nf][0] * i0, o_acc[mf][nf][1] * i0);
            *(uint32_t*)(Chg + (size_t)(ra + 8) * D_MODEL + col) =
                pack_h2(o_acc[mf][nf][2] * i1, o_acc[mf][nf][3] * i1);
        }
    }
}

// ---------------------------------------------------------------------------
extern "C" void kernel_launch(void* const* d_in, const int* in_sizes, int n_in,
                              void* d_out, int out_size)
{
    const float* x  = (const float*)d_in[0];
    const float* Wq = (const float*)d_in[1];
    const float* Wk = (const float*)d_in[2];
    const float* Wv = (const float*)d_in[3];
    const float* Wo = (const float*)d_in[4];
    float* out = (float*)d_out;

    __half *xh, *xl, *wq16, *wk16, *wv16, *wo16, *qh, *ql, *k16, *v16, *ch;
    cudaGetSymbolAddress((void**)&xh,   g_xh);
    cudaGetSymbolAddress((void**)&xl,   g_xl);
    cudaGetSymbolAddress((void**)&wq16, g_wq16);
    cudaGetSymbolAddress((void**)&wk16, g_wk16);
    cudaGetSymbolAddress((void**)&wv16, g_wv16);
    cudaGetSymbolAddress((void**)&wo16, g_wo16);
    cudaGetSymbolAddress((void**)&qh,   g_qh);
    cudaGetSymbolAddress((void**)&ql,   g_ql);
    cudaGetSymbolAddress((void**)&k16,  g_k16);
    cudaGetSymbolAddress((void**)&v16,  g_v16);
    cudaGetSymbolAddress((void**)&ch,   g_ch);

    cudaFuncSetAttribute(gemm_qk_f16x2_kernel,
                         cudaFuncAttributeMaxDynamicSharedMemorySize, GEMM_SMEM2);
    cudaFuncSetAttribute(gemm_mma_f16x1_kernel,
                         cudaFuncAttributeMaxDynamicSharedMemorySize, GEMM_SMEM1);
    cudaFuncSetAttribute(attn_mma_kernel,
                         cudaFuncAttributeMaxDynamicSharedMemorySize, AT_SMEM);

    const int nx4 = MROWS * D_MODEL / 4;
    const int nw4 = D_MODEL * D_MODEL / 4;
    dim3 qkgrid(D_MODEL / 128, MROWS / 128, 2);   // fused Q+K
    dim3 ggrid(D_MODEL / 128, MROWS / 128);
    const float qscale = 0.08838834764831845f;    // 1/sqrt(128)

    cvt_x_kernel<<<(nx4 + 255) / 256, 256>>>(x, xh, xl, nx4);
    cvt_w4_kernel<<<(4 * nw4 + 255) / 256, 256>>>(Wq, Wk, Wv, Wo,
                                                  wq16, wk16, wv16, wo16, nw4);

    gemm_qk_f16x2_kernel<<<qkgrid, 256, GEMM_SMEM2>>>(xh, xl, wq16, wk16,
                                                      qh, ql, k16, qscale);
    gemm_mma_f16x1_kernel<<<ggrid, 256, GEMM_SMEM1>>>(xh, wv16, nullptr, v16);

    attn_mma_kernel<<<dim3(S_LEN / 64, NHEADS, BATCH), 256, AT_SMEM>>>();

    gemm_mma_f16x1_kernel<<<ggrid, 256, GEMM_SMEM1>>>(ch, wo16, out, nullptr);
}

// round 16
// speedup vs baseline: 6.6204x; 1.2343x over previous
#include <cuda_runtime.h>
#include <cuda_fp16.h>
#include <cstdint>

// ---------------------------------------------------------------------------
// MultiHeadSelfAttention  B=2, S=2048, D=2048, H=16, Hd=128, fp32 in/out
//   Q,K GEMMs: fp16 "x2" (x pair * W fp16) fused in one launch (grid.z=2),
//              outputs single fp16 (Q pre-scaled).
//   V,Wo GEMMs: pure fp16 1-pass.
//   Attention: all-single fp16 flash attention (Q,K,V,P single), 2 CTAs/SM.
//   Calibrated rel_err ~6.6e-4 < 1e-3.
// ---------------------------------------------------------------------------

#define S_LEN   2048
#define D_MODEL 2048
#define BATCH   2
#define NHEADS  16
#define HDIM    128
#define MROWS   (BATCH * S_LEN)   // 4096

// ------------------------- scratch (static, allocation-free) ---------------
__device__ __half g_xh[(size_t)MROWS * D_MODEL];     // x fp16 hi
__device__ __half g_xl[(size_t)MROWS * D_MODEL];     // x fp16 lo
__device__ __half g_wq16[(size_t)D_MODEL * D_MODEL];
__device__ __half g_wk16[(size_t)D_MODEL * D_MODEL];
__device__ __half g_wv16[(size_t)D_MODEL * D_MODEL];
__device__ __half g_wo16[(size_t)D_MODEL * D_MODEL];
__device__ __half g_q16[(size_t)MROWS * D_MODEL];    // Q single (pre-scaled)
__device__ __half g_k16[(size_t)MROWS * D_MODEL];    // K single
__device__ __half g_v16[(size_t)MROWS * D_MODEL];    // V single
__device__ __half g_ch[(size_t)MROWS * D_MODEL];     // ctx single

// ------------------------- helpers -----------------------------------------
__device__ __forceinline__ uint32_t smem_u32(const void* p) {
    uint32_t a;
    asm("{ .reg .u64 t; cvta.to.shared.u64 t, %1; cvt.u32.u64 %0, t; }"
        : "=r"(a) : "l"(p));
    return a;
}
#define SMEM_SWIZZLE_128B(off) ((off) ^ (((off) >> 3) & 0x70))

__device__ __forceinline__ void ldsm4(uint32_t* r, uint32_t addr) {
    asm volatile("ldmatrix.sync.aligned.m8n8.x4.shared.b16 {%0,%1,%2,%3}, [%4];"
                 : "=r"(r[0]), "=r"(r[1]), "=r"(r[2]), "=r"(r[3]) : "r"(addr));
}
__device__ __forceinline__ void ldsm4t(uint32_t* r, uint32_t addr) {
    asm volatile("ldmatrix.sync.aligned.m8n8.x4.trans.shared.b16 {%0,%1,%2,%3}, [%4];"
                 : "=r"(r[0]), "=r"(r[1]), "=r"(r[2]), "=r"(r[3]) : "r"(addr));
}
__device__ __forceinline__ void mma16816h(float* d, const uint32_t* a, const uint32_t* b) {
    asm volatile(
        "mma.sync.aligned.m16n8k16.row.col.f32.f16.f16.f32 "
        "{%0,%1,%2,%3}, {%4,%5,%6,%7}, {%8,%9}, {%0,%1,%2,%3};"
        : "+f"(d[0]), "+f"(d[1]), "+f"(d[2]), "+f"(d[3])
        : "r"(a[0]), "r"(a[1]), "r"(a[2]), "r"(a[3]), "r"(b[0]), "r"(b[1]));
}
__device__ __forceinline__ void cp_async16(uint32_t sdst, const void* gsrc) {
    asm volatile("cp.async.cg.shared.global [%0], [%1], 16;" :: "r"(sdst), "l"(gsrc));
}
__device__ __forceinline__ uint32_t pack_h2(float a, float b) {
    __half2 v(__float2half(a), __float2half(b));
    return *(uint32_t*)&v;
}

// ---------------------------------------------------------------------------
// Conversions
// ---------------------------------------------------------------------------
__global__ __launch_bounds__(256) void cvt_x_kernel(
    const float* __restrict__ in, __half* __restrict__ hh,
    __half* __restrict__ hl, int n4)
{
    int i = blockIdx.x * blockDim.x + threadIdx.x;
    if (i >= n4) return;
    float4 v = ((const float4*)in)[i];
    float x[4] = {v.x, v.y, v.z, v.w};
    float h[4], l[4];
#pragma unroll
    for (int j = 0; j < 4; j++) {
        h[j] = __half2float(__float2half(x[j]));
        l[j] = x[j] - h[j];
    }
    ((uint32_t*)hh)[2 * i]     = pack_h2(h[0], h[1]);
    ((uint32_t*)hh)[2 * i + 1] = pack_h2(h[2], h[3]);
    ((uint32_t*)hl)[2 * i]     = pack_h2(l[0], l[1]);
    ((uint32_t*)hl)[2 * i + 1] = pack_h2(l[2], l[3]);
}

__global__ __launch_bounds__(256) void cvt_w4_kernel(
    const float* __restrict__ a0, const float* __restrict__ a1,
    const float* __restrict__ a2, const float* __restrict__ a3,
    __half* __restrict__ o0, __half* __restrict__ o1,
    __half* __restrict__ o2, __half* __restrict__ o3, int n4)
{
    int idx = blockIdx.x * blockDim.x + threadIdx.x;
    int w = idx / n4;
    int i = idx - w * n4;
    if (w >= 4) return;
    const float* src = (w == 0) ? a0 : (w == 1) ? a1 : (w == 2) ? a2 : a3;
    __half* dst      = (w == 0) ? o0 : (w == 1) ? o1 : (w == 2) ? o2 : o3;
    float4 v = ((const float4*)src)[i];
    ((uint32_t*)dst)[2 * i]     = pack_h2(v.x, v.y);
    ((uint32_t*)dst)[2 * i + 1] = pack_h2(v.z, v.w);
}

// ---------------------------------------------------------------------------
// Common GEMM geometry
// ---------------------------------------------------------------------------
#define GK        64
#define TILE_B    (128 * GK * 2)         // 16384
#define NCHUNK    (D_MODEL / GK)         // 32

// ---------------------------------------------------------------------------
// Fused Q+K fp16x2 GEMM (grid.z selects weight/output); single fp16 outputs.
// ---------------------------------------------------------------------------
#define STAGE_B2   (3 * TILE_B)          // 49152
#define NSTAGE2    2
#define GEMM_SMEM2 (NSTAGE2 * STAGE_B2)  // 98304

__global__ __launch_bounds__(256, 2) void gemm_qk_f16x2_kernel(
    const __half* __restrict__ Ah, const __half* __restrict__ Al,
    const __half* __restrict__ Bq, const __half* __restrict__ Bk,
    __half* __restrict__ Q16, __half* __restrict__ K16, float qscale)
{
    extern __shared__ char smem[];
    const uint32_t smem_base = smem_u32(smem);
    const int tid  = threadIdx.x;
    const int wid  = tid >> 5;
    const int lane = tid & 31;
    const int wm   = wid & 3;
    const int wn   = wid >> 2;
    const int row0 = blockIdx.y * 128;
    const int col0 = blockIdx.x * 128;
    const int isK  = blockIdx.z;
    const __half* B   = isK ? Bk : Bq;
    __half* Out       = isK ? K16 : Q16;
    const float scale = isK ? 1.0f : qscale;

    int cr[4], cs[4];
    uint32_t csw[4];
#pragma unroll
    for (int i = 0; i < 4; i++) {
        int idx = tid + i * 256;
        cr[i]  = idx >> 3;
        cs[i]  = idx & 7;
        csw[i] = SMEM_SWIZZLE_128B((uint32_t)(cr[i] * 128 + cs[i] * 16));
    }

    auto copy_stage = [&](int st, int kc) {
        const uint32_t sb = smem_base + st * STAGE_B2;
#pragma unroll
        for (int i = 0; i < 4; i++) {
            const size_t aoff = (size_t)(row0 + cr[i]) * D_MODEL + kc * GK + cs[i] * 8;
            const size_t boff = (size_t)(col0 + cr[i]) * D_MODEL + kc * GK + cs[i] * 8;
            cp_async16(sb + 0 * TILE_B + csw[i], Ah + aoff);
            cp_async16(sb + 1 * TILE_B + csw[i], Al + aoff);
            cp_async16(sb + 2 * TILE_B + csw[i], B + boff);
        }
    };

    float acc[2][8][4];
#pragma unroll
    for (int mf = 0; mf < 2; mf++)
#pragma unroll
        for (int nf = 0; nf < 8; nf++)
#pragma unroll
            for (int r = 0; r < 4; r++) acc[mf][nf][r] = 0.f;

    const int quad = lane >> 3;
    const int r16  = (lane & 7) | ((quad & 1) << 3);
    const int cbq  = (quad >> 1) << 4;

    copy_stage(0, 0);
    asm volatile("cp.async.commit_group;");

    for (int kc = 0; kc < NCHUNK; kc++) {
        if (kc + 1 < NCHUNK) {
            copy_stage((kc + 1) & 1, kc + 1);
            asm volatile("cp.async.commit_group;");
            asm volatile("cp.async.wait_group 1;");
        } else {
            asm volatile("cp.async.wait_group 0;");
        }
        __syncthreads();

        const uint32_t sb  = smem_base + (kc & 1) * STAGE_B2;
        const uint32_t sAh = sb + 0 * TILE_B;
        const uint32_t sAl = sb + 1 * TILE_B;
        const uint32_t sB  = sb + 2 * TILE_B;

#pragma unroll
        for (int ks = 0; ks < 4; ks++) {
            uint32_t ah[2][4], al[2][4], bb[8][2];
#pragma unroll
            for (int mf = 0; mf < 2; mf++) {
                const int row = wm * 32 + mf * 16 + r16;
                const uint32_t off =
                    SMEM_SWIZZLE_128B((uint32_t)(row * 128 + cbq + ks * 32));
                ldsm4(ah[mf], sAh + off);
                ldsm4(al[mf], sAl + off);
            }
#pragma unroll
            for (int p = 0; p < 4; p++) {
                const int row = wn * 64 + p * 16 + r16;
                const uint32_t off =
                    SMEM_SWIZZLE_128B((uint32_t)(row * 128 + cbq + ks * 32));
                uint32_t q[4];
                ldsm4(q, sB + off);
                bb[2 * p][0] = q[0]; bb[2 * p][1] = q[2];
                bb[2 * p + 1][0] = q[1]; bb[2 * p + 1][1] = q[3];
            }
#pragma unroll
            for (int mf = 0; mf < 2; mf++)
#pragma unroll
                for (int nf = 0; nf < 8; nf++) {
                    mma16816h(acc[mf][nf], ah[mf], bb[nf]);
                    mma16816h(acc[mf][nf], al[mf], bb[nf]);
                }
        }
        __syncthreads();
    }

#pragma unroll
    for (int mf = 0; mf < 2; mf++) {
        const int row = row0 + wm * 32 + mf * 16 + (lane >> 2);
#pragma unroll
        for (int nf = 0; nf < 8; nf++) {
            const int col = col0 + wn * 64 + nf * 8 + (lane & 3) * 2;
            *(uint32_t*)(Out + (size_t)row * D_MODEL + col) =
                pack_h2(acc[mf][nf][0] * scale, acc[mf][nf][1] * scale);
            *(uint32_t*)(Out + (size_t)(row + 8) * D_MODEL + col) =
                pack_h2(acc[mf][nf][2] * scale, acc[mf][nf][3] * scale);
        }
    }
}

// ---------------------------------------------------------------------------
// fp16 1-pass GEMM-NT (V, Wo): 2 tiles/stage, 3 stages (96KB), 2 CTAs/SM.
// ---------------------------------------------------------------------------
#define STAGE_B1   (2 * TILE_B)          // 32768
#define NSTAGE1    3
#define GEMM_SMEM1 (NSTAGE1 * STAGE_B1)  // 98304

__global__ __launch_bounds__(256, 2) void gemm_mma_f16x1_kernel(
    const __half* __restrict__ A, const __half* __restrict__ B,
    float* __restrict__ Cf, __half* __restrict__ Hh)
{
    extern __shared__ char smem[];
    const uint32_t smem_base = smem_u32(smem);
    const int tid  = threadIdx.x;
    const int wid  = tid >> 5;
    const int lane = tid & 31;
    const int wm   = wid & 3;
    const int wn   = wid >> 2;
    const int row0 = blockIdx.y * 128;
    const int col0 = blockIdx.x * 128;

    int cr[4], cs[4];
    uint32_t csw[4];
#pragma unroll
    for (int i = 0; i < 4; i++) {
        int idx = tid + i * 256;
        cr[i]  = idx >> 3;
        cs[i]  = idx & 7;
        csw[i] = SMEM_SWIZZLE_128B((uint32_t)(cr[i] * 128 + cs[i] * 16));
    }

    auto copy_stage = [&](int st, int kc) {
        const uint32_t sb = smem_base + st * STAGE_B1;
#pragma unroll
        for (int i = 0; i < 4; i++) {
            const size_t aoff = (size_t)(row0 + cr[i]) * D_MODEL + kc * GK + cs[i] * 8;
            const size_t boff = (size_t)(col0 + cr[i]) * D_MODEL + kc * GK + cs[i] * 8;
            cp_async16(sb + 0 * TILE_B + csw[i], A + aoff);
            cp_async16(sb + 1 * TILE_B + csw[i], B + boff);
        }
    };

    float acc[2][8][4];
#pragma unroll
    for (int mf = 0; mf < 2; mf++)
#pragma unroll
        for (int nf = 0; nf < 8; nf++)
#pragma unroll
            for (int r = 0; r < 4; r++) acc[mf][nf][r] = 0.f;

    const int quad = lane >> 3;
    const int r16  = (lane & 7) | ((quad & 1) << 3);
    const int cbq  = (quad >> 1) << 4;

    copy_stage(0, 0);
    asm volatile("cp.async.commit_group;");
    copy_stage(1, 1);
    asm volatile("cp.async.commit_group;");

    for (int kc = 0; kc < NCHUNK; kc++) {
        if (kc + 2 < NCHUNK) copy_stage((kc + 2) % NSTAGE1, kc + 2);
        asm volatile("cp.async.commit_group;");
        asm volatile("cp.async.wait_group 2;");
        __syncthreads();

        const uint32_t sb = smem_base + (kc % NSTAGE1) * STAGE_B1;
        const uint32_t sA = sb + 0 * TILE_B;
        const uint32_t sB = sb + 1 * TILE_B;

#pragma unroll
        for (int ks = 0; ks < 4; ks++) {
            uint32_t aa[2][4], bb[8][2];
#pragma unroll
            for (int mf = 0; mf < 2; mf++) {
                const int row = wm * 32 + mf * 16 + r16;
                const uint32_t off =
                    SMEM_SWIZZLE_128B((uint32_t)(row * 128 + cbq + ks * 32));
                ldsm4(aa[mf], sA + off);
            }
#pragma unroll
            for (int p = 0; p < 4; p++) {
                const int row = wn * 64 + p * 16 + r16;
                const uint32_t off =
                    SMEM_SWIZZLE_128B((uint32_t)(row * 128 + cbq + ks * 32));
                uint32_t q[4];
                ldsm4(q, sB + off);
                bb[2 * p][0] = q[0]; bb[2 * p][1] = q[2];
                bb[2 * p + 1][0] = q[1]; bb[2 * p + 1][1] = q[3];
            }
#pragma unroll
            for (int mf = 0; mf < 2; mf++)
#pragma unroll
                for (int nf = 0; nf < 8; nf++)
                    mma16816h(acc[mf][nf], aa[mf], bb[nf]);
        }
        __syncthreads();
    }

#pragma unroll
    for (int mf = 0; mf < 2; mf++) {
        const int row = row0 + wm * 32 + mf * 16 + (lane >> 2);
#pragma unroll
        for (int nf = 0; nf < 8; nf++) {
            const int col = col0 + wn * 64 + nf * 8 + (lane & 3) * 2;
            if (Cf) {
                float* p0 = Cf + (size_t)row * D_MODEL + col;
                float* p1 = Cf + (size_t)(row + 8) * D_MODEL + col;
                *(float2*)p0 = make_float2(acc[mf][nf][0], acc[mf][nf][1]);
                *(float2*)p1 = make_float2(acc[mf][nf][2], acc[mf][nf][3]);
            } else {
                *(uint32_t*)(Hh + (size_t)row * D_MODEL + col) =
                    pack_h2(acc[mf][nf][0], acc[mf][nf][1]);
                *(uint32_t*)(Hh + (size_t)(row + 8) * D_MODEL + col) =
                    pack_h2(acc[mf][nf][2], acc[mf][nf][3]);
            }
        }
    }
}

// ---------------------------------------------------------------------------
// Flash attention, all-single fp16 (Q,K,V,P single).  108KB smem, 2 CTAs/SM.
// ---------------------------------------------------------------------------
#define AT_Q    0                // 16384
#define AT_KST  16384            // 2 x 16384
#define AT_VST  49152            // 2 x 16384
#define AT_SS   81920            // 64 x 68 f32 = 17408
#define AT_P    99328            // 64 x 64 fp16 SW128 = 8192
#define AT_AL   107520
#define AT_LR   107776
#define AT_SMEM 108032
#define NKV     (S_LEN / 64)

__device__ __forceinline__ void at_copy_tile(uint32_t dst, const __half* src,
                                             int tid) {
#pragma unroll
    for (int i = 0; i < 4; i++) {
        int idx = tid + i * 256;
        int c   = idx >> 9;
        int r   = (idx >> 3) & 63;
        int sg  = idx & 7;
        uint32_t so = dst + c * 8192 +
                      SMEM_SWIZZLE_128B((uint32_t)(r * 128 + sg * 16));
        cp_async16(so, src + (size_t)r * D_MODEL + c * 64 + sg * 8);
    }
}

__global__ __launch_bounds__(256, 2) void attn_mma_kernel()
{
    extern __shared__ char smbuf[];
    const uint32_t sb = smem_u32(smbuf);
    const int tid  = threadIdx.x;
    const int wid  = tid >> 5;
    const int lane = tid & 31;
    const int b    = blockIdx.z;
    const int h    = blockIdx.y;
    const int q0   = blockIdx.x * 64;

    const int r16 = (lane & 7) | (((lane >> 3) & 1) << 3);
    const int cbq = ((lane >> 4) & 1) << 4;
    const int wm  = wid & 1;
    const int wn  = wid >> 1;

    const size_t hoff = (size_t)h * HDIM;
    const __half* Qg = g_q16 + (size_t)(b * S_LEN + q0) * D_MODEL + hoff;
    const __half* Kg = g_k16 + (size_t)(b * S_LEN) * D_MODEL + hoff;
    const __half* Vg = g_v16 + (size_t)(b * S_LEN) * D_MODEL + hoff;

    float* Ssp   = (float*)(smbuf + AT_SS);
    float* alphp = (float*)(smbuf + AT_AL);
    float* lrowp = (float*)(smbuf + AT_LR);

    at_copy_tile(sb + AT_Q,   Qg, tid);
    at_copy_tile(sb + AT_KST, Kg, tid);
    at_copy_tile(sb + AT_VST, Vg, tid);
    asm volatile("cp.async.commit_group;");

    float m_i = -1e30f, l_i = 0.f;
    float o_acc[2][4][4];
#pragma unroll
    for (int mf = 0; mf < 2; mf++)
#pragma unroll
        for (int nf = 0; nf < 4; nf++)
#pragma unroll
            for (int r = 0; r < 4; r++) o_acc[mf][nf][r] = 0.f;

    const int srow = tid >> 2;
    const int scol = (tid & 3) * 16;

    for (int it = 0; it < NKV; it++) {
        const int st = it & 1;
        asm volatile("cp.async.wait_group 0;");
        __syncthreads();

        // ---- S = Q16 K16^T ----
        float sacc[2][2][4];
#pragma unroll
        for (int mf = 0; mf < 2; mf++)
#pragma unroll
            for (int nf = 0; nf < 2; nf++)
#pragma unroll
                for (int r = 0; r < 4; r++) sacc[mf][nf][r] = 0.f;

        const uint32_t kb = sb + AT_KST + st * 16384;
#pragma unroll
        for (int ks = 0; ks < 8; ks++) {
            const int chunk = ks >> 2;
            const int kbyte = (ks & 3) * 32 + cbq;
            uint32_t aq[2][4];
#pragma unroll
            for (int mf = 0; mf < 2; mf++) {
                const uint32_t off = chunk * 8192 +
                    SMEM_SWIZZLE_128B((uint32_t)((wm * 32 + mf * 16 + r16) * 128 + kbyte));
                ldsm4(aq[mf], sb + AT_Q + off);
            }
            const uint32_t offb = chunk * 8192 +
                SMEM_SWIZZLE_128B((uint32_t)((wn * 16 + r16) * 128 + kbyte));
            uint32_t q[4];
            ldsm4(q, kb + offb);
            uint32_t bb[2][2] = {{q[0], q[2]}, {q[1], q[3]}};
#pragma unroll
            for (int mf = 0; mf < 2; mf++)
#pragma unroll
                for (int nf = 0; nf < 2; nf++)
                    mma16816h(sacc[mf][nf], aq[mf], bb[nf]);
        }

#pragma unroll
        for (int mf = 0; mf < 2; mf++) {
            const int row = wm * 32 + mf * 16 + (lane >> 2);
#pragma unroll
            for (int nf = 0; nf < 2; nf++) {
                const int col = wn * 16 + nf * 8 + (lane & 3) * 2;
                *(float2*)(Ssp + row * 68 + col) =
                    make_float2(sacc[mf][nf][0], sacc[mf][nf][1]);
                *(float2*)(Ssp + (row + 8) * 68 + col) =
                    make_float2(sacc[mf][nf][2], sacc[mf][nf][3]);
            }
        }
        __syncthreads();

        if (it + 1 < NKV) {
            const int ns = (it + 1) & 1;
            const size_t roff = (size_t)((it + 1) * 64) * D_MODEL;
            at_copy_tile(sb + AT_KST + ns * 16384, Kg + roff, tid);
            at_copy_tile(sb + AT_VST + ns * 16384, Vg + roff, tid);
            asm volatile("cp.async.commit_group;");
        }

        // ---- online softmax (P stored single fp16) ----
        {
            float sv[16];
#pragma unroll
            for (int u = 0; u < 4; u++)
                *(float4*)(sv + u * 4) = *(float4*)(Ssp + srow * 68 + scol + u * 4);
            float mx = sv[0];
#pragma unroll
            for (int u = 1; u < 16; u++) mx = fmaxf(mx, sv[u]);
            mx = fmaxf(mx, __shfl_xor_sync(0xffffffffu, mx, 1));
            mx = fmaxf(mx, __shfl_xor_sync(0xffffffffu, mx, 2));
            const float mnew  = fmaxf(m_i, mx);
            const float alpha = __expf(m_i - mnew);
            m_i = mnew;
            float sum = 0.f;
            float p[16];
#pragma unroll
            for (int u = 0; u < 16; u++) {
                p[u] = __expf(sv[u] - mnew);
                sum += p[u];
            }
            sum += __shfl_xor_sync(0xffffffffu, sum, 1);
            sum += __shfl_xor_sync(0xffffffffu, sum, 2);
            l_i = l_i * alpha + sum;
#pragma unroll
            for (int u2 = 0; u2 < 8; u2++) {
                const uint32_t off =
                    SMEM_SWIZZLE_128B((uint32_t)(srow * 128 + (scol + u2 * 2) * 2));
                *(uint32_t*)(smbuf + AT_P + off) = pack_h2(p[u2 * 2], p[u2 * 2 + 1]);
            }
            if ((tid & 3) == 0) alphp[srow] = alpha;
        }
        __syncthreads();

        // ---- rescale O ----
#pragma unroll
        for (int mf = 0; mf < 2; mf++) {
            const float a0 = alphp[wm * 32 + mf * 16 + (lane >> 2)];
            const float a1 = alphp[wm * 32 + mf * 16 + (lane >> 2) + 8];
#pragma unroll
            for (int nf = 0; nf < 4; nf++) {
                o_acc[mf][nf][0] *= a0; o_acc[mf][nf][1] *= a0;
                o_acc[mf][nf][2] *= a1; o_acc[mf][nf][3] *= a1;
            }
        }

        // ---- O += P16 V16 ----
        const uint32_t vb = sb + AT_VST + st * 16384;
        const int g  = lane >> 3;
        const int kg = (g & 1) << 3;
        const int ng = (g >> 1) << 3;
#pragma unroll
        for (int kpv = 0; kpv < 4; kpv++) {
            uint32_t ap[2][4];
#pragma unroll
            for (int mf = 0; mf < 2; mf++) {
                const uint32_t off =
                    SMEM_SWIZZLE_128B((uint32_t)((wm * 32 + mf * 16 + r16) * 128 +
                                                 kpv * 32 + cbq));
                ldsm4(ap[mf], smbuf == nullptr ? 0 : sb + AT_P + off);
            }
            uint32_t bv[4][2];
#pragma unroll
            for (int pr = 0; pr < 2; pr++) {
                const int kr = kpv * 16 + kg + (lane & 7);
                const int nc = wn * 32 + pr * 16 + ng;
                const uint32_t off = (uint32_t)(nc >> 6) * 8192 +
                    SMEM_SWIZZLE_128B((uint32_t)(kr * 128 + (nc & 63) * 2));
                uint32_t t4[4];
                ldsm4t(t4, vb + off);
                bv[2 * pr][0] = t4[0]; bv[2 * pr][1] = t4[1];
                bv[2 * pr + 1][0] = t4[2]; bv[2 * pr + 1][1] = t4[3];
            }
#pragma unroll
            for (int mf = 0; mf < 2; mf++)
#pragma unroll
                for (int nf = 0; nf < 4; nf++)
                    mma16816h(o_acc[mf][nf], ap[mf], bv[nf]);
        }
    }

    // ---- epilogue: ctx single fp16 ----
    if ((tid & 3) == 0) lrowp[srow] = l_i;
    __syncthreads();
    if (tid < 64) lrowp[tid] = 1.0f / lrowp[tid];
    __syncthreads();

    __half* Chg = g_ch + (size_t)(b * S_LEN + q0) * D_MODEL + hoff;
#pragma unroll
    for (int mf = 0; mf < 2; mf++) {
        const int ra  = wm * 32 + mf * 16 + (lane >> 2);
        const float i0 = lrowp[ra];
        const float i1 = lrowp[ra + 8];
#pragma unroll
        for (int nf = 0; nf < 4; nf++) {
            const int col = wn * 32 + nf * 8 + (lane & 3) * 2;
            *(uint32_t*)(Chg + (size_t)ra * D_MODEL + col) =
                pack_h2(o_acc[mf][nf][0] * i0, o_acc[mf][nf][1] * i0);
            *(uint32_t*)(Chg + (size_t)(ra + 8) * D_MODEL + col) =
                pack_h2(o_acc[mf][nf][2] * i1, o_acc[mf][nf][3] * i1);
        }
    }
}

// ---------------------------------------------------------------------------
extern "C" void kernel_launch(void* const* d_in, const int* in_sizes, int n_in,
                              void* d_out, int out_size)
{
    const float* x  = (const float*)d_in[0];
    const float* Wq = (const float*)d_in[1];
    const float* Wk = (const float*)d_in[2];
    const float* Wv = (const float*)d_in[3];
    const float* Wo = (const float*)d_in[4];
    float* out = (float*)d_out;

    __half *xh, *xl, *wq16, *wk16, *wv16, *wo16, *q16, *k16, *v16, *ch;
    cudaGetSymbolAddress((void**)&xh,   g_xh);
    cudaGetSymbolAddress((void**)&xl,   g_xl);
    cudaGetSymbolAddress((void**)&wq16, g_wq16);
    cudaGetSymbolAddress((void**)&wk16, g_wk16);
    cudaGetSymbolAddress((void**)&wv16, g_wv16);
    cudaGetSymbolAddress((void**)&wo16, g_wo16);
    cudaGetSymbolAddress((void**)&q16,  g_q16);
    cudaGetSymbolAddress((void**)&k16,  g_k16);
    cudaGetSymbolAddress((void**)&v16,  g_v16);
    cudaGetSymbolAddress((void**)&ch,   g_ch);

    cudaFuncSetAttribute(gemm_qk_f16x2_kernel,
                         cudaFuncAttributeMaxDynamicSharedMemorySize, GEMM_SMEM2);
    cudaFuncSetAttribute(gemm_mma_f16x1_kernel,
                         cudaFuncAttributeMaxDynamicSharedMemorySize, GEMM_SMEM1);
    cudaFuncSetAttribute(attn_mma_kernel,
                         cudaFuncAttributeMaxDynamicSharedMemorySize, AT_SMEM);

    const int nx4 = MROWS * D_MODEL / 4;
    const int nw4 = D_MODEL * D_MODEL / 4;
    dim3 qkgrid(D_MODEL / 128, MROWS / 128, 2);
    dim3 ggrid(D_MODEL / 128, MROWS / 128);
    const float qscale = 0.08838834764831845f;   // 1/sqrt(128)

    cvt_x_kernel<<<(nx4 + 255) / 256, 256>>>(x, xh, xl, nx4);
    cvt_w4_kernel<<<(4 * nw4 + 255) / 256, 256>>>(Wq, Wk, Wv, Wo,
                                                  wq16, wk16, wv16, wo16, nw4);

    gemm_qk_f16x2_kernel<<<qkgrid, 256, GEMM_SMEM2>>>(xh, xl, wq16, wk16,
                                                      q16, k16, qscale);
    gemm_mma_f16x1_kernel<<<ggrid, 256, GEMM_SMEM1>>>(xh, wv16, nullptr, v16);

    attn_mma_kernel<<<dim3(S_LEN / 64, NHEADS, BATCH), 256, AT_SMEM>>>();

    gemm_mma_f16x1_kernel<<<ggrid, 256, GEMM_SMEM1>>>(ch, wo16, out, nullptr);
}

// round 17
// speedup vs baseline: 8.3558x; 1.2621x over previous
#include <cuda_runtime.h>
#include <cuda_fp16.h>
#include <cstdint>

// ---------------------------------------------------------------------------
// MultiHeadSelfAttention  B=2, S=2048, D=2048, H=16, Hd=128, fp32 in/out
//   ALL GEMMs pure fp16 1-pass; Q,K,V fused in one launch (grid.z=3).
//   Attention: all-single fp16 flash attention, 2 CTAs/SM.
//   Calibrated rel_err ~7.1e-4 < 1e-3 (error model 5-for-5 across rounds).
// ---------------------------------------------------------------------------

#define S_LEN   2048
#define D_MODEL 2048
#define BATCH   2
#define NHEADS  16
#define HDIM    128
#define MROWS   (BATCH * S_LEN)   // 4096

// ------------------------- scratch (static, allocation-free) ---------------
__device__ __half g_x16[(size_t)MROWS * D_MODEL];    // x single fp16
__device__ __half g_wq16[(size_t)D_MODEL * D_MODEL];
__device__ __half g_wk16[(size_t)D_MODEL * D_MODEL];
__device__ __half g_wv16[(size_t)D_MODEL * D_MODEL];
__device__ __half g_wo16[(size_t)D_MODEL * D_MODEL];
__device__ __half g_q16[(size_t)MROWS * D_MODEL];    // Q single (pre-scaled)
__device__ __half g_k16[(size_t)MROWS * D_MODEL];    // K single
__device__ __half g_v16[(size_t)MROWS * D_MODEL];    // V single
__device__ __half g_ch[(size_t)MROWS * D_MODEL];     // ctx single

// ------------------------- helpers -----------------------------------------
__device__ __forceinline__ uint32_t smem_u32(const void* p) {
    uint32_t a;
    asm("{ .reg .u64 t; cvta.to.shared.u64 t, %1; cvt.u32.u64 %0, t; }"
        : "=r"(a) : "l"(p));
    return a;
}
#define SMEM_SWIZZLE_128B(off) ((off) ^ (((off) >> 3) & 0x70))

__device__ __forceinline__ void ldsm4(uint32_t* r, uint32_t addr) {
    asm volatile("ldmatrix.sync.aligned.m8n8.x4.shared.b16 {%0,%1,%2,%3}, [%4];"
                 : "=r"(r[0]), "=r"(r[1]), "=r"(r[2]), "=r"(r[3]) : "r"(addr));
}
__device__ __forceinline__ void ldsm4t(uint32_t* r, uint32_t addr) {
    asm volatile("ldmatrix.sync.aligned.m8n8.x4.trans.shared.b16 {%0,%1,%2,%3}, [%4];"
                 : "=r"(r[0]), "=r"(r[1]), "=r"(r[2]), "=r"(r[3]) : "r"(addr));
}
__device__ __forceinline__ void mma16816h(float* d, const uint32_t* a, const uint32_t* b) {
    asm volatile(
        "mma.sync.aligned.m16n8k16.row.col.f32.f16.f16.f32 "
        "{%0,%1,%2,%3}, {%4,%5,%6,%7}, {%8,%9}, {%0,%1,%2,%3};"
        : "+f"(d[0]), "+f"(d[1]), "+f"(d[2]), "+f"(d[3])
        : "r"(a[0]), "r"(a[1]), "r"(a[2]), "r"(a[3]), "r"(b[0]), "r"(b[1]));
}
__device__ __forceinline__ void cp_async16(uint32_t sdst, const void* gsrc) {
    asm volatile("cp.async.cg.shared.global [%0], [%1], 16;" :: "r"(sdst), "l"(gsrc));
}
__device__ __forceinline__ uint32_t pack_h2(float a, float b) {
    __half2 v(__float2half(a), __float2half(b));
    return *(uint32_t*)&v;
}

// ---------------------------------------------------------------------------
// Conversions: x and all 4 weights -> single fp16 (5 tensors, one style)
// ---------------------------------------------------------------------------
__global__ __launch_bounds__(256) void cvt_h16_kernel(
    const float* __restrict__ in, __half* __restrict__ out, int n4)
{
    int i = blockIdx.x * blockDim.x + threadIdx.x;
    if (i >= n4) return;
    float4 v = ((const float4*)in)[i];
    ((uint32_t*)out)[2 * i]     = pack_h2(v.x, v.y);
    ((uint32_t*)out)[2 * i + 1] = pack_h2(v.z, v.w);
}

__global__ __launch_bounds__(256) void cvt_w4_kernel(
    const float* __restrict__ a0, const float* __restrict__ a1,
    const float* __restrict__ a2, const float* __restrict__ a3,
    __half* __restrict__ o0, __half* __restrict__ o1,
    __half* __restrict__ o2, __half* __restrict__ o3, int n4)
{
    int idx = blockIdx.x * blockDim.x + threadIdx.x;
    int w = idx / n4;
    int i = idx - w * n4;
    if (w >= 4) return;
    const float* src = (w == 0) ? a0 : (w == 1) ? a1 : (w == 2) ? a2 : a3;
    __half* dst      = (w == 0) ? o0 : (w == 1) ? o1 : (w == 2) ? o2 : o3;
    float4 v = ((const float4*)src)[i];
    ((uint32_t*)dst)[2 * i]     = pack_h2(v.x, v.y);
    ((uint32_t*)dst)[2 * i + 1] = pack_h2(v.z, v.w);
}

// ---------------------------------------------------------------------------
// Common GEMM geometry
// ---------------------------------------------------------------------------
#define GK        64
#define TILE_B    (128 * GK * 2)         // 16384
#define NCHUNK    (D_MODEL / GK)         // 32
#define STAGE_B1   (2 * TILE_B)          // 32768
#define NSTAGE1    3
#define GEMM_SMEM1 (NSTAGE1 * STAGE_B1)  // 98304

// ---------------------------------------------------------------------------
// Fused Q+K+V fp16 1-pass GEMM (grid.z = 0/1/2 selects weight + output).
// 2 tiles/stage, 3 stages, launch_bounds(256,2) -> 2 CTAs/SM.
// ---------------------------------------------------------------------------
__global__ __launch_bounds__(256, 2) void gemm_qkv_f16_kernel(
    const __half* __restrict__ A,
    const __half* __restrict__ Bq, const __half* __restrict__ Bk,
    const __half* __restrict__ Bv,
    __half* __restrict__ Q16, __half* __restrict__ K16,
    __half* __restrict__ V16, float qscale)
{
    extern __shared__ char smem[];
    const uint32_t smem_base = smem_u32(smem);
    const int tid  = threadIdx.x;
    const int wid  = tid >> 5;
    const int lane = tid & 31;
    const int wm   = wid & 3;
    const int wn   = wid >> 2;
    const int row0 = blockIdx.y * 128;
    const int col0 = blockIdx.x * 128;
    const int z    = blockIdx.z;
    const __half* B   = (z == 0) ? Bq : (z == 1) ? Bk : Bv;
    __half* Out       = (z == 0) ? Q16 : (z == 1) ? K16 : V16;
    const float scale = (z == 0) ? qscale : 1.0f;

    int cr[4], cs[4];
    uint32_t csw[4];
#pragma unroll
    for (int i = 0; i < 4; i++) {
        int idx = tid + i * 256;
        cr[i]  = idx >> 3;
        cs[i]  = idx & 7;
        csw[i] = SMEM_SWIZZLE_128B((uint32_t)(cr[i] * 128 + cs[i] * 16));
    }

    auto copy_stage = [&](int st, int kc) {
        const uint32_t sb = smem_base + st * STAGE_B1;
#pragma unroll
        for (int i = 0; i < 4; i++) {
            const size_t aoff = (size_t)(row0 + cr[i]) * D_MODEL + kc * GK + cs[i] * 8;
            const size_t boff = (size_t)(col0 + cr[i]) * D_MODEL + kc * GK + cs[i] * 8;
            cp_async16(sb + 0 * TILE_B + csw[i], A + aoff);
            cp_async16(sb + 1 * TILE_B + csw[i], B + boff);
        }
    };

    float acc[2][8][4];
#pragma unroll
    for (int mf = 0; mf < 2; mf++)
#pragma unroll
        for (int nf = 0; nf < 8; nf++)
#pragma unroll
            for (int r = 0; r < 4; r++) acc[mf][nf][r] = 0.f;

    const int quad = lane >> 3;
    const int r16  = (lane & 7) | ((quad & 1) << 3);
    const int cbq  = (quad >> 1) << 4;

    copy_stage(0, 0);
    asm volatile("cp.async.commit_group;");
    copy_stage(1, 1);
    asm volatile("cp.async.commit_group;");

    for (int kc = 0; kc < NCHUNK; kc++) {
        if (kc + 2 < NCHUNK) copy_stage((kc + 2) % NSTAGE1, kc + 2);
        asm volatile("cp.async.commit_group;");
        asm volatile("cp.async.wait_group 2;");
        __syncthreads();

        const uint32_t sb = smem_base + (kc % NSTAGE1) * STAGE_B1;
        const uint32_t sA = sb + 0 * TILE_B;
        const uint32_t sB = sb + 1 * TILE_B;

#pragma unroll
        for (int ks = 0; ks < 4; ks++) {
            uint32_t aa[2][4], bb[8][2];
#pragma unroll
            for (int mf = 0; mf < 2; mf++) {
                const int row = wm * 32 + mf * 16 + r16;
                const uint32_t off =
                    SMEM_SWIZZLE_128B((uint32_t)(row * 128 + cbq + ks * 32));
                ldsm4(aa[mf], sA + off);
            }
#pragma unroll
            for (int p = 0; p < 4; p++) {
                const int row = wn * 64 + p * 16 + r16;
                const uint32_t off =
                    SMEM_SWIZZLE_128B((uint32_t)(row * 128 + cbq + ks * 32));
                uint32_t q[4];
                ldsm4(q, sB + off);
                bb[2 * p][0] = q[0]; bb[2 * p][1] = q[2];
                bb[2 * p + 1][0] = q[1]; bb[2 * p + 1][1] = q[3];
            }
#pragma unroll
            for (int mf = 0; mf < 2; mf++)
#pragma unroll
                for (int nf = 0; nf < 8; nf++)
                    mma16816h(acc[mf][nf], aa[mf], bb[nf]);
        }
        __syncthreads();
    }

#pragma unroll
    for (int mf = 0; mf < 2; mf++) {
        const int row = row0 + wm * 32 + mf * 16 + (lane >> 2);
#pragma unroll
        for (int nf = 0; nf < 8; nf++) {
            const int col = col0 + wn * 64 + nf * 8 + (lane & 3) * 2;
            *(uint32_t*)(Out + (size_t)row * D_MODEL + col) =
                pack_h2(acc[mf][nf][0] * scale, acc[mf][nf][1] * scale);
            *(uint32_t*)(Out + (size_t)(row + 8) * D_MODEL + col) =
                pack_h2(acc[mf][nf][2] * scale, acc[mf][nf][3] * scale);
        }
    }
}

// ---------------------------------------------------------------------------
// fp16 1-pass GEMM-NT (Wo): fp32 output.
// ---------------------------------------------------------------------------
__global__ __launch_bounds__(256, 2) void gemm_mma_f16x1_kernel(
    const __half* __restrict__ A, const __half* __restrict__ B,
    float* __restrict__ Cf)
{
    extern __shared__ char smem[];
    const uint32_t smem_base = smem_u32(smem);
    const int tid  = threadIdx.x;
    const int wid  = tid >> 5;
    const int lane = tid & 31;
    const int wm   = wid & 3;
    const int wn   = wid >> 2;
    const int row0 = blockIdx.y * 128;
    const int col0 = blockIdx.x * 128;

    int cr[4], cs[4];
    uint32_t csw[4];
#pragma unroll
    for (int i = 0; i < 4; i++) {
        int idx = tid + i * 256;
        cr[i]  = idx >> 3;
        cs[i]  = idx & 7;
        csw[i] = SMEM_SWIZZLE_128B((uint32_t)(cr[i] * 128 + cs[i] * 16));
    }

    auto copy_stage = [&](int st, int kc) {
        const uint32_t sb = smem_base + st * STAGE_B1;
#pragma unroll
        for (int i = 0; i < 4; i++) {
            const size_t aoff = (size_t)(row0 + cr[i]) * D_MODEL + kc * GK + cs[i] * 8;
            const size_t boff = (size_t)(col0 + cr[i]) * D_MODEL + kc * GK + cs[i] * 8;
            cp_async16(sb + 0 * TILE_B + csw[i], A + aoff);
            cp_async16(sb + 1 * TILE_B + csw[i], B + boff);
        }
    };

    float acc[2][8][4];
#pragma unroll
    for (int mf = 0; mf < 2; mf++)
#pragma unroll
        for (int nf = 0; nf < 8; nf++)
#pragma unroll
            for (int r = 0; r < 4; r++) acc[mf][nf][r] = 0.f;

    const int quad = lane >> 3;
    const int r16  = (lane & 7) | ((quad & 1) << 3);
    const int cbq  = (quad >> 1) << 4;

    copy_stage(0, 0);
    asm volatile("cp.async.commit_group;");
    copy_stage(1, 1);
    asm volatile("cp.async.commit_group;");

    for (int kc = 0; kc < NCHUNK; kc++) {
        if (kc + 2 < NCHUNK) copy_stage((kc + 2) % NSTAGE1, kc + 2);
        asm volatile("cp.async.commit_group;");
        asm volatile("cp.async.wait_group 2;");
        __syncthreads();

        const uint32_t sb = smem_base + (kc % NSTAGE1) * STAGE_B1;
        const uint32_t sA = sb + 0 * TILE_B;
        const uint32_t sB = sb + 1 * TILE_B;

#pragma unroll
        for (int ks = 0; ks < 4; ks++) {
            uint32_t aa[2][4], bb[8][2];
#pragma unroll
            for (int mf = 0; mf < 2; mf++) {
                const int row = wm * 32 + mf * 16 + r16;
                const uint32_t off =
                    SMEM_SWIZZLE_128B((uint32_t)(row * 128 + cbq + ks * 32));
                ldsm4(aa[mf], sA + off);
            }
#pragma unroll
            for (int p = 0; p < 4; p++) {
                const int row = wn * 64 + p * 16 + r16;
                const uint32_t off =
                    SMEM_SWIZZLE_128B((uint32_t)(row * 128 + cbq + ks * 32));
                uint32_t q[4];
                ldsm4(q, sB + off);
                bb[2 * p][0] = q[0]; bb[2 * p][1] = q[2];
                bb[2 * p + 1][0] = q[1]; bb[2 * p + 1][1] = q[3];
            }
#pragma unroll
            for (int mf = 0; mf < 2; mf++)
#pragma unroll
                for (int nf = 0; nf < 8; nf++)
                    mma16816h(acc[mf][nf], aa[mf], bb[nf]);
        }
        __syncthreads();
    }

#pragma unroll
    for (int mf = 0; mf < 2; mf++) {
        const int row = row0 + wm * 32 + mf * 16 + (lane >> 2);
#pragma unroll
        for (int nf = 0; nf < 8; nf++) {
            const int col = col0 + wn * 64 + nf * 8 + (lane & 3) * 2;
            float* p0 = Cf + (size_t)row * D_MODEL + col;
            float* p1 = Cf + (size_t)(row + 8) * D_MODEL + col;
            *(float2*)p0 = make_float2(acc[mf][nf][0], acc[mf][nf][1]);
            *(float2*)p1 = make_float2(acc[mf][nf][2], acc[mf][nf][3]);
        }
    }
}

// ---------------------------------------------------------------------------
// Flash attention, all-single fp16 (unchanged from R16 passing kernel).
// ---------------------------------------------------------------------------
#define AT_Q    0                // 16384
#define AT_KST  16384            // 2 x 16384
#define AT_VST  49152            // 2 x 16384
#define AT_SS   81920            // 64 x 68 f32 = 17408
#define AT_P    99328            // 64 x 64 fp16 SW128 = 8192
#define AT_AL   107520
#define AT_LR   107776
#define AT_SMEM 108032
#define NKV     (S_LEN / 64)

__device__ __forceinline__ void at_copy_tile(uint32_t dst, const __half* src,
                                             int tid) {
#pragma unroll
    for (int i = 0; i < 4; i++) {
        int idx = tid + i * 256;
        int c   = idx >> 9;
        int r   = (idx >> 3) & 63;
        int sg  = idx & 7;
        uint32_t so = dst + c * 8192 +
                      SMEM_SWIZZLE_128B((uint32_t)(r * 128 + sg * 16));
        cp_async16(so, src + (size_t)r * D_MODEL + c * 64 + sg * 8);
    }
}

__global__ __launch_bounds__(256, 2) void attn_mma_kernel()
{
    extern __shared__ char smbuf[];
    const uint32_t sb = smem_u32(smbuf);
    const int tid  = threadIdx.x;
    const int wid  = tid >> 5;
    const int lane = tid & 31;
    const int b    = blockIdx.z;
    const int h    = blockIdx.y;
    const int q0   = blockIdx.x * 64;

    const int r16 = (lane & 7) | (((lane >> 3) & 1) << 3);
    const int cbq = ((lane >> 4) & 1) << 4;
    const int wm  = wid & 1;
    const int wn  = wid >> 1;

    const size_t hoff = (size_t)h * HDIM;
    const __half* Qg = g_q16 + (size_t)(b * S_LEN + q0) * D_MODEL + hoff;
    const __half* Kg = g_k16 + (size_t)(b * S_LEN) * D_MODEL + hoff;
    const __half* Vg = g_v16 + (size_t)(b * S_LEN) * D_MODEL + hoff;

    float* Ssp   = (float*)(smbuf + AT_SS);
    float* alphp = (float*)(smbuf + AT_AL);
    float* lrowp = (float*)(smbuf + AT_LR);

    at_copy_tile(sb + AT_Q,   Qg, tid);
    at_copy_tile(sb + AT_KST, Kg, tid);
    at_copy_tile(sb + AT_VST, Vg, tid);
    asm volatile("cp.async.commit_group;");

    float m_i = -1e30f, l_i = 0.f;
    float o_acc[2][4][4];
#pragma unroll
    for (int mf = 0; mf < 2; mf++)
#pragma unroll
        for (int nf = 0; nf < 4; nf++)
#pragma unroll
            for (int r = 0; r < 4; r++) o_acc[mf][nf][r] = 0.f;

    const int srow = tid >> 2;
    const int scol = (tid & 3) * 16;

    for (int it = 0; it < NKV; it++) {
        const int st = it & 1;
        asm volatile("cp.async.wait_group 0;");
        __syncthreads();

        float sacc[2][2][4];
#pragma unroll
        for (int mf = 0; mf < 2; mf++)
#pragma unroll
            for (int nf = 0; nf < 2; nf++)
#pragma unroll
                for (int r = 0; r < 4; r++) sacc[mf][nf][r] = 0.f;

        const uint32_t kb = sb + AT_KST + st * 16384;
#pragma unroll
        for (int ks = 0; ks < 8; ks++) {
            const int chunk = ks >> 2;
            const int kbyte = (ks & 3) * 32 + cbq;
            uint32_t aq[2][4];
#pragma unroll
            for (int mf = 0; mf < 2; mf++) {
                const uint32_t off = chunk * 8192 +
                    SMEM_SWIZZLE_128B((uint32_t)((wm * 32 + mf * 16 + r16) * 128 + kbyte));
                ldsm4(aq[mf], sb + AT_Q + off);
            }
            const uint32_t offb = chunk * 8192 +
                SMEM_SWIZZLE_128B((uint32_t)((wn * 16 + r16) * 128 + kbyte));
            uint32_t q[4];
            ldsm4(q, kb + offb);
            uint32_t bb[2][2] = {{q[0], q[2]}, {q[1], q[3]}};
#pragma unroll
            for (int mf = 0; mf < 2; mf++)
#pragma unroll
                for (int nf = 0; nf < 2; nf++)
                    mma16816h(sacc[mf][nf], aq[mf], bb[nf]);
        }

#pragma unroll
        for (int mf = 0; mf < 2; mf++) {
            const int row = wm * 32 + mf * 16 + (lane >> 2);
#pragma unroll
            for (int nf = 0; nf < 2; nf++) {
                const int col = wn * 16 + nf * 8 + (lane & 3) * 2;
                *(float2*)(Ssp + row * 68 + col) =
                    make_float2(sacc[mf][nf][0], sacc[mf][nf][1]);
                *(float2*)(Ssp + (row + 8) * 68 + col) =
                    make_float2(sacc[mf][nf][2], sacc[mf][nf][3]);
            }
        }
        __syncthreads();

        if (it + 1 < NKV) {
            const int ns = (it + 1) & 1;
            const size_t roff = (size_t)((it + 1) * 64) * D_MODEL;
            at_copy_tile(sb + AT_KST + ns * 16384, Kg + roff, tid);
            at_copy_tile(sb + AT_VST + ns * 16384, Vg + roff, tid);
            asm volatile("cp.async.commit_group;");
        }

        {
            float sv[16];
#pragma unroll
            for (int u = 0; u < 4; u++)
                *(float4*)(sv + u * 4) = *(float4*)(Ssp + srow * 68 + scol + u * 4);
            float mx = sv[0];
#pragma unroll
            for (int u = 1; u < 16; u++) mx = fmaxf(mx, sv[u]);
            mx = fmaxf(mx, __shfl_xor_sync(0xffffffffu, mx, 1));
            mx = fmaxf(mx, __shfl_xor_sync(0xffffffffu, mx, 2));
            const float mnew  = fmaxf(m_i, mx);
            const float alpha = __expf(m_i - mnew);
            m_i = mnew;
            float sum = 0.f;
            float p[16];
#pragma unroll
            for (int u = 0; u < 16; u++) {
                p[u] = __expf(sv[u] - mnew);
                sum += p[u];
            }
            sum += __shfl_xor_sync(0xffffffffu, sum, 1);
            sum += __shfl_xor_sync(0xffffffffu, sum, 2);
            l_i = l_i * alpha + sum;
#pragma unroll
            for (int u2 = 0; u2 < 8; u2++) {
                const uint32_t off =
                    SMEM_SWIZZLE_128B((uint32_t)(srow * 128 + (scol + u2 * 2) * 2));
                *(uint32_t*)(smbuf + AT_P + off) = pack_h2(p[u2 * 2], p[u2 * 2 + 1]);
            }
            if ((tid & 3) == 0) alphp[srow] = alpha;
        }
        __syncthreads();

#pragma unroll
        for (int mf = 0; mf < 2; mf++) {
            const float a0 = alphp[wm * 32 + mf * 16 + (lane >> 2)];
            const float a1 = alphp[wm * 32 + mf * 16 + (lane >> 2) + 8];
#pragma unroll
            for (int nf = 0; nf < 4; nf++) {
                o_acc[mf][nf][0] *= a0; o_acc[mf][nf][1] *= a0;
                o_acc[mf][nf][2] *= a1; o_acc[mf][nf][3] *= a1;
            }
        }

        const uint32_t vb = sb + AT_VST + st * 16384;
        const int g  = lane >> 3;
        const int kg = (g & 1) << 3;
        const int ng = (g >> 1) << 3;
#pragma unroll
        for (int kpv = 0; kpv < 4; kpv++) {
            uint32_t ap[2][4];
#pragma unroll
            for (int mf = 0; mf < 2; mf++) {
                const uint32_t off =
                    SMEM_SWIZZLE_128B((uint32_t)((wm * 32 + mf * 16 + r16) * 128 +
                                                 kpv * 32 + cbq));
                ldsm4(ap[mf], sb + AT_P + off);
            }
            uint32_t bv[4][2];
#pragma unroll
            for (int pr = 0; pr < 2; pr++) {
                const int kr = kpv * 16 + kg + (lane & 7);
                const int nc = wn * 32 + pr * 16 + ng;
                const uint32_t off = (uint32_t)(nc >> 6) * 8192 +
                    SMEM_SWIZZLE_128B((uint32_t)(kr * 128 + (nc & 63) * 2));
                uint32_t t4[4];
                ldsm4t(t4, vb + off);
                bv[2 * pr][0] = t4[0]; bv[2 * pr][1] = t4[1];
                bv[2 * pr + 1][0] = t4[2]; bv[2 * pr + 1][1] = t4[3];
            }
#pragma unroll
            for (int mf = 0; mf < 2; mf++)
#pragma unroll
                for (int nf = 0; nf < 4; nf++)
                    mma16816h(o_acc[mf][nf], ap[mf], bv[nf]);
        }
    }

    if ((tid & 3) == 0) lrowp[srow] = l_i;
    __syncthreads();
    if (tid < 64) lrowp[tid] = 1.0f / lrowp[tid];
    __syncthreads();

    __half* Chg = g_ch + (size_t)(b * S_LEN + q0) * D_MODEL + hoff;
#pragma unroll
    for (int mf = 0; mf < 2; mf++) {
        const int ra  = wm * 32 + mf * 16 + (lane >> 2);
        const float i0 = lrowp[ra];
        const float i1 = lrowp[ra + 8];
#pragma unroll
        for (int nf = 0; nf < 4; nf++) {
            const int col = wn * 32 + nf * 8 + (lane & 3) * 2;
            *(uint32_t*)(Chg + (size_t)ra * D_MODEL + col) =
                pack_h2(o_acc[mf][nf][0] * i0, o_acc[mf][nf][1] * i0);
            *(uint32_t*)(Chg + (size_t)(ra + 8) * D_MODEL + col) =
                pack_h2(o_acc[mf][nf][2] * i1, o_acc[mf][nf][3] * i1);
        }
    }
}

// ---------------------------------------------------------------------------
extern "C" void kernel_launch(void* const* d_in, const int* in_sizes, int n_in,
                              void* d_out, int out_size)
{
    const float* x  = (const float*)d_in[0];
    const float* Wq = (const float*)d_in[1];
    const float* Wk = (const float*)d_in[2];
    const float* Wv = (const float*)d_in[3];
    const float* Wo = (const float*)d_in[4];
    float* out = (float*)d_out;

    __half *x16, *wq16, *wk16, *wv16, *wo16, *q16, *k16, *v16, *ch;
    cudaGetSymbolAddress((void**)&x16,  g_x16);
    cudaGetSymbolAddress((void**)&wq16, g_wq16);
    cudaGetSymbolAddress((void**)&wk16, g_wk16);
    cudaGetSymbolAddress((void**)&wv16, g_wv16);
    cudaGetSymbolAddress((void**)&wo16, g_wo16);
    cudaGetSymbolAddress((void**)&q16,  g_q16);
    cudaGetSymbolAddress((void**)&k16,  g_k16);
    cudaGetSymbolAddress((void**)&v16,  g_v16);
    cudaGetSymbolAddress((void**)&ch,   g_ch);

    cudaFuncSetAttribute(gemm_qkv_f16_kernel,
                         cudaFuncAttributeMaxDynamicSharedMemorySize, GEMM_SMEM1);
    cudaFuncSetAttribute(gemm_mma_f16x1_kernel,
                         cudaFuncAttributeMaxDynamicSharedMemorySize, GEMM_SMEM1);
    cudaFuncSetAttribute(attn_mma_kernel,
                         cudaFuncAttributeMaxDynamicSharedMemorySize, AT_SMEM);

    const int nx4 = MROWS * D_MODEL / 4;
    const int nw4 = D_MODEL * D_MODEL / 4;
    dim3 qkvgrid(D_MODEL / 128, MROWS / 128, 3);   // fused Q+K+V
    dim3 ggrid(D_MODEL / 128, MROWS / 128);
    const float qscale = 0.08838834764831845f;     // 1/sqrt(128)

    cvt_h16_kernel<<<(nx4 + 255) / 256, 256>>>(x, x16, nx4);
    cvt_w4_kernel<<<(4 * nw4 + 255) / 256, 256>>>(Wq, Wk, Wv, Wo,
                                                  wq16, wk16, wv16, wo16, nw4);

    gemm_qkv_f16_kernel<<<qkvgrid, 256, GEMM_SMEM1>>>(x16, wq16, wk16, wv16,
                                                      q16, k16, v16, qscale);

    attn_mma_kernel<<<dim3(S_LEN / 64, NHEADS, BATCH), 256, AT_SMEM>>>();

    gemm_mma_f16x1_kernel<<<ggrid, 256, GEMM_SMEM1>>>(ch, wo16, out);
}